// round 13
// baseline (speedup 1.0000x reference)
#include <cuda_runtime.h>
#include <cuda_bf16.h>
#include <math.h>
#include <stdint.h>

// ---------------- problem constants ----------------
#define BB    2
#define SS    1024
#define TOK   2048          // B*S
#define DIM   1024
#define QKVD  3072
#define NHEAD 16
#define HDIM  64
#define NEXP  8
#define FDIM  4096
#define NSLOT 4096          // TOK * top_k

// ---------------- device scratch (no allocs allowed) ----------------
__device__ __align__(128) float g_proj[(size_t)TOK * DIM];
__device__ __align__(128) float g_x1  [(size_t)TOK * DIM];
__device__ __align__(128) float g_moe2[(size_t)NSLOT * DIM];

// hi/lo bf16 operand planes
__device__ __align__(128) __nv_bfloat16 g_qkvH [(size_t)TOK * QKVD];
__device__ __align__(128) __nv_bfloat16 g_qkvL [(size_t)TOK * QKVD];
__device__ __align__(128) __nv_bfloat16 g_srcH [(size_t)TOK * DIM];
__device__ __align__(128) __nv_bfloat16 g_srcL [(size_t)TOK * DIM];
__device__ __align__(128) __nv_bfloat16 g_attnH[(size_t)TOK * DIM];
__device__ __align__(128) __nv_bfloat16 g_attnL[(size_t)TOK * DIM];
__device__ __align__(128) __nv_bfloat16 g_x1H  [(size_t)TOK * DIM];
__device__ __align__(128) __nv_bfloat16 g_x1L  [(size_t)TOK * DIM];
__device__ __align__(128) __nv_bfloat16 g_hH   [(size_t)NSLOT * FDIM];
__device__ __align__(128) __nv_bfloat16 g_hL   [(size_t)NSLOT * FDIM];
__device__ __align__(128) __nv_bfloat16 g_ipwH [(size_t)QKVD * DIM];
__device__ __align__(128) __nv_bfloat16 g_ipwL [(size_t)QKVD * DIM];
__device__ __align__(128) __nv_bfloat16 g_outwH[(size_t)DIM * DIM];
__device__ __align__(128) __nv_bfloat16 g_outwL[(size_t)DIM * DIM];
__device__ __align__(128) __nv_bfloat16 g_w1H  [(size_t)NEXP * FDIM * DIM];
__device__ __align__(128) __nv_bfloat16 g_w1L  [(size_t)NEXP * FDIM * DIM];
__device__ __align__(128) __nv_bfloat16 g_w2H  [(size_t)NEXP * DIM * FDIM];
__device__ __align__(128) __nv_bfloat16 g_w2L  [(size_t)NEXP * DIM * FDIM];

__device__ int   g_tidx[NSLOT];
__device__ float g_tprob[NSLOT];
__device__ float g_usage[NEXP];
__device__ int   g_count[NEXP];
__device__ int   g_off[NEXP];
__device__ int   g_fill[NEXP];
__device__ int   g_list[NSLOT];

__device__ __forceinline__ float gelu_f(float x) {
    return 0.5f * x * (1.0f + erff(x * 0.70710678118654752f));
}

// ---------------- PTX helpers (all compute_103-legal) ----------------
__device__ __forceinline__ uint32_t smem_u32(const void* p) {
    uint32_t a;
    asm("{ .reg .u64 t; cvta.to.shared.u64 t, %1; cvt.u32.u64 %0, t; }"
        : "=r"(a) : "l"(p));
    return a;
}

#define CP16(dst, src) \
    asm volatile("cp.async.cg.shared.global [%0], [%1], 16;" \
                 :: "r"(dst), "l"(src) : "memory")
#define CPCOMMIT()  asm volatile("cp.async.commit_group;" ::: "memory")
#define CPWAIT0()   asm volatile("cp.async.wait_group 0;" ::: "memory")
#define CPWAIT2()   asm volatile("cp.async.wait_group 2;" ::: "memory")

#define LDSM4(R, addr) \
    asm volatile("ldmatrix.sync.aligned.m8n8.x4.shared.b16 {%0,%1,%2,%3}, [%4];" \
        : "=r"((R)[0]), "=r"((R)[1]), "=r"((R)[2]), "=r"((R)[3]) : "r"(addr))
#define LDSM4T(R, addr) \
    asm volatile("ldmatrix.sync.aligned.m8n8.x4.trans.shared.b16 {%0,%1,%2,%3}, [%4];" \
        : "=r"((R)[0]), "=r"((R)[1]), "=r"((R)[2]), "=r"((R)[3]) : "r"(addr))

__device__ __forceinline__ void mma16816(float* c, const uint32_t* a,
                                         uint32_t b0, uint32_t b1) {
    asm volatile(
        "mma.sync.aligned.m16n8k16.row.col.f32.bf16.bf16.f32 "
        "{%0,%1,%2,%3}, {%4,%5,%6,%7}, {%8,%9}, {%0,%1,%2,%3};"
        : "+f"(c[0]), "+f"(c[1]), "+f"(c[2]), "+f"(c[3])
        : "r"(a[0]), "r"(a[1]), "r"(a[2]), "r"(a[3]), "r"(b0), "r"(b1));
}

__device__ __forceinline__ uint32_t packbf(float a, float b) {
    __nv_bfloat162 t;
    t.x = __float2bfloat16_rn(a);
    t.y = __float2bfloat16_rn(b);
    return *(uint32_t*)&t;
}

// ---------------- init (re-zero per replay) ----------------
__global__ void k_init() {
    int i = threadIdx.x;
    if (i < NEXP) { g_usage[i] = 0.f; g_count[i] = 0; g_fill[i] = 0; }
}

// ---------------- fp32 -> (hi, lo) bf16 planes ----------------
__global__ void __launch_bounds__(256) k_conv(
    const float* __restrict__ x, __nv_bfloat16* __restrict__ hi,
    __nv_bfloat16* __restrict__ lo, long n4)
{
    long i = (long)blockIdx.x * blockDim.x + threadIdx.x;
    if (i >= n4) return;
    float4 v = ((const float4*)x)[i];
    __nv_bfloat16 h0 = __float2bfloat16_rn(v.x);
    __nv_bfloat16 h1 = __float2bfloat16_rn(v.y);
    __nv_bfloat16 h2 = __float2bfloat16_rn(v.z);
    __nv_bfloat16 h3 = __float2bfloat16_rn(v.w);
    __nv_bfloat162 H0; H0.x = h0; H0.y = h1;
    __nv_bfloat162 H1; H1.x = h2; H1.y = h3;
    __nv_bfloat162 L0, L1;
    L0.x = __float2bfloat16_rn(v.x - __bfloat162float(h0));
    L0.y = __float2bfloat16_rn(v.y - __bfloat162float(h1));
    L1.x = __float2bfloat16_rn(v.z - __bfloat162float(h2));
    L1.y = __float2bfloat16_rn(v.w - __bfloat162float(h3));
    ((__nv_bfloat162*)hi)[2 * i]     = H0;
    ((__nv_bfloat162*)hi)[2 * i + 1] = H1;
    ((__nv_bfloat162*)lo)[2 * i]     = L0;
    ((__nv_bfloat162*)lo)[2 * i + 1] = L1;
}

// =====================================================================
// bf16-split NT GEMM via mma.sync: C[m,n] = sum_k A[m,k]*B[n,k]
//   tile 128x128, K-chunk 16, 8 warps (2m x 4n), hi/lo planes,
//   4-stage cp.async pipeline (3 chunks in flight), ONE sync per chunk.
//   Loop: wait_group(2) [drains chunk c] -> sync -> stage(c+3) -> compute(c).
//   TSB=48 (multiple of 16: cp.async/ldmatrix alignment; odd multiple of
//   16 -> the 8 row addrs per ldmatrix hit distinct 16B banks, conflict-free).
//   SMEM: 4 x 24576 + 512 = 98.8KB -> 2 CTAs/SM.
// MODE 0: C fp32 = acc + bias
// MODE 1: A rows gathered via g_list (token=slot>>1); gelu(acc+bias) ->
//         hi/lo bf16 planes at row g_off[e]+m
// MODE 2: A rows = g_off[e]+m; (acc+bias)*prob -> fp32 scatter to row slot
// MODE 3: plain A rows; (acc+bias) [cols<DIM scaled 1/8] -> hi/lo planes
// =====================================================================
#define TSB   48            // smem row stride bytes (32 data + 16 pad)
#define PL    6144          // one plane: 128 rows * 48B
#define BUFB  24576         // 4 planes (Ahi, Alo, Bhi, Blo)
#define NBUF  4
#define SM_BIAS  (NBUF * BUFB)          // 98304
#define SM_TOTAL (SM_BIAS + 512)

template<int MODE>
__global__ void __launch_bounds__(256)
mma_gemm(const __nv_bfloat16* __restrict__ Ah, const __nv_bfloat16* __restrict__ Al,
         const __nv_bfloat16* __restrict__ Bh, const __nv_bfloat16* __restrict__ Bl,
         const float* __restrict__ bias,
         float* __restrict__ Cf,
         __nv_bfloat16* __restrict__ ChH, __nv_bfloat16* __restrict__ ChL,
         int M, int N, int K, long strideBe, int strideBiasE)
{
    extern __shared__ char smem[];
    const uint32_t sb = smem_u32(smem);

    int tid  = threadIdx.x;
    int wid  = tid >> 5, lane = tid & 31;
    int mBase = blockIdx.y * 128;
    int nBase = blockIdx.x * 128;

    int count = M, off = 0;
    const int* lst = 0;
    if (MODE == 1 || MODE == 2) {
        int e = blockIdx.z;
        count = g_count[e];
        if (mBase >= count) return;
        off  = g_off[e];
        Bh  += (long)e * strideBe;
        Bl  += (long)e * strideBe;
        bias += (long)e * strideBiasE;
        lst  = g_list + off;
    }

    if (tid < 128) *(float*)(smem + SM_BIAS + tid * 4) = bias[nBase + tid];

    // ---- cp.async source setup: thread -> (row r, 16B half hf of 32B row-chunk)
    int r  = tid >> 1;
    int hf = tid & 1;
    long aRow;
    {
        int mIdxL = mBase + r;
        if (MODE == 0 || MODE == 3) aRow = mIdxL;
        else if (MODE == 1) aRow = (long)(lst[min(mIdxL, count - 1)] >> 1);
        else                aRow = (long)off + min(mIdxL, count - 1);
    }
    const char* aH = (const char*)(Ah + aRow * (long)K) + hf * 16;
    const char* aL = (const char*)(Al + aRow * (long)K) + hf * 16;
    const char* bH = (const char*)(Bh + (long)(nBase + r) * K) + hf * 16;
    const char* bL = (const char*)(Bl + (long)(nBase + r) * K) + hf * 16;
    uint32_t d0 = sb + (uint32_t)(r * TSB + hf * 16);

    const int NC = K >> 4;   // 16-K chunks

    auto stage_chunk = [&](int cc) {
        long ob = (long)cc * 32;     // 16 bf16 = 32 bytes per row per chunk
        uint32_t db = d0 + (uint32_t)((cc & (NBUF - 1)) * BUFB);
        CP16(db,          aH + ob);
        CP16(db + PL,     aL + ob);
        CP16(db + 2 * PL, bH + ob);
        CP16(db + 3 * PL, bL + ob);
        CPCOMMIT();
    };

    // prologue: stage chunks 0,1,2 (3 groups outstanding)
    stage_chunk(0);
    stage_chunk(1);
    stage_chunk(2);

    // warp compute setup
    int wm = wid >> 2;           // 0..1  (m half)
    int wn = wid & 3;            // 0..3  (n quarter)
    uint32_t laneoff = (uint32_t)((lane & 15) * TSB + (lane >> 4) * 16);
    uint32_t aBaseOff = (uint32_t)(wm * 64 * TSB) + laneoff;
    uint32_t bBaseOff = (uint32_t)(2 * PL + wn * 32 * TSB) + laneoff;

    float acc[4][4][4];
    #pragma unroll
    for (int i = 0; i < 4; i++)
        #pragma unroll
        for (int j = 0; j < 4; j++)
            #pragma unroll
            for (int q = 0; q < 4; q++) acc[i][j][q] = 0.f;

    // mainloop: exactly one commit per iteration keeps 3 groups outstanding,
    // so wait_group(2) always completes precisely chunk c.
    for (int c = 0; c < NC; c++) {
        CPWAIT2();
        __syncthreads();
        if (c + 3 < NC) stage_chunk(c + 3); else CPCOMMIT();

        uint32_t base = sb + (uint32_t)((c & (NBUF - 1)) * BUFB);
        uint32_t ah[4][4], al[4][4], bh[2][4], bl[2][4];
        #pragma unroll
        for (int mi = 0; mi < 4; mi++) {
            uint32_t ad = base + aBaseOff + mi * (16 * TSB);
            LDSM4(ah[mi], ad);
            LDSM4(al[mi], ad + PL);
        }
        #pragma unroll
        for (int np = 0; np < 2; np++) {
            uint32_t bd = base + bBaseOff + np * (16 * TSB);
            LDSM4(bh[np], bd);
            LDSM4(bl[np], bd + PL);
        }
        #pragma unroll
        for (int mi = 0; mi < 4; mi++)
            #pragma unroll
            for (int nj = 0; nj < 4; nj++) {
                int np = nj >> 1, s = nj & 1;
                mma16816(acc[mi][nj], ah[mi], bh[np][s], bh[np][s + 2]);
            }
        #pragma unroll
        for (int mi = 0; mi < 4; mi++)
            #pragma unroll
            for (int nj = 0; nj < 4; nj++) {
                int np = nj >> 1, s = nj & 1;
                mma16816(acc[mi][nj], ah[mi], bl[np][s], bl[np][s + 2]);
            }
        #pragma unroll
        for (int mi = 0; mi < 4; mi++)
            #pragma unroll
            for (int nj = 0; nj < 4; nj++) {
                int np = nj >> 1, s = nj & 1;
                mma16816(acc[mi][nj], al[mi], bh[np][s], bh[np][s + 2]);
            }
    }

    // ---- epilogue (regs only; bias smem ordered by first loop sync)
    int g  = lane >> 2;
    int tg = lane & 3;
    const float* sbias = (const float*)(smem + SM_BIAS);
    float qs = 1.f;
    if (MODE == 3) qs = (nBase < DIM) ? 0.125f : 1.f;   // pre-scale Q by 1/sqrt(HD)

    #pragma unroll
    for (int mi = 0; mi < 4; mi++) {
        #pragma unroll
        for (int hrow = 0; hrow < 2; hrow++) {
            int rm = wm * 64 + mi * 16 + g + hrow * 8;  // row in tile
            int m  = mBase + rm;
            if ((MODE == 1 || MODE == 2) && m >= count) continue;
            long cRow; float scl = 1.f;
            if (MODE == 0 || MODE == 3) cRow = m;
            else if (MODE == 1)         cRow = (long)off + m;
            else { int slot = lst[m]; cRow = slot; scl = g_tprob[slot]; }
            #pragma unroll
            for (int nj = 0; nj < 4; nj++) {
                int col = wn * 32 + nj * 8 + tg * 2;
                float vx = acc[mi][nj][hrow * 2]     + sbias[col];
                float vy = acc[mi][nj][hrow * 2 + 1] + sbias[col + 1];
                if (MODE == 1) { vx = gelu_f(vx); vy = gelu_f(vy); }
                if (MODE == 3) { vx *= qs; vy *= qs; }
                if (MODE == 1 || MODE == 3) {
                    __nv_bfloat16 hx = __float2bfloat16_rn(vx);
                    __nv_bfloat16 hy = __float2bfloat16_rn(vy);
                    __nv_bfloat162 H; H.x = hx; H.y = hy;
                    __nv_bfloat162 L;
                    L.x = __float2bfloat16_rn(vx - __bfloat162float(hx));
                    L.y = __float2bfloat16_rn(vy - __bfloat162float(hy));
                    long idx = cRow * (long)N + nBase + col;
                    *(__nv_bfloat162*)(ChH + idx) = H;
                    *(__nv_bfloat162*)(ChL + idx) = L;
                } else {
                    float2 v; v.x = vx * scl; v.y = vy * scl;
                    *(float2*)(Cf + cRow * (long)N + nBase + col) = v;
                }
            }
        }
    }
}

// =====================================================================
// FA2-style mma attention: 128 q-rows/CTA, 8 warps x m16, K-tile 64.
// Single __syncthreads per K-tile (wait -> sync -> prefetch -> compute).
// =====================================================================
#define AT_STRIDE 144                    // 64 bf16 cols + 16B pad
#define AT_KVB    18432                  // Kh(9216) + Vh(9216) per buffer
#define AT_KH(b)  ((b) * AT_KVB)
#define AT_VH(b)  ((b) * AT_KVB + 9216)
#define AT_QH     36864
#define AT_QL     55296
#define AT_SMEM   73728

__global__ void __launch_bounds__(256) attn_mma(
    const __nv_bfloat16* __restrict__ qkvH,
    const __nv_bfloat16* __restrict__ qkvL,
    __nv_bfloat16* __restrict__ outH, __nv_bfloat16* __restrict__ outL)
{
    extern __shared__ char smem[];
    const uint32_t sb = smem_u32(smem);
    int tid = threadIdx.x, wid = tid >> 5, lane = tid & 31;
    int bh = blockIdx.y;
    int b  = bh >> 4, h = bh & 15;
    int q0 = blockIdx.x * 128;

    const char* Hb = (const char*)qkvH;
    const char* Lb = (const char*)qkvL;
    const long ROWB = (long)QKVD * 2;            // bytes per token row
    const long tokB = (long)b * SS;

    auto stage_kv = [&](int tile) {
        #pragma unroll
        for (int u = 0; u < 2; u++) {
            int id = tid + u * 256;
            int row = id >> 3, ch = id & 7;
            long ko = (tokB + tile * 64 + row) * ROWB + (long)(DIM     + h * 64) * 2 + ch * 16;
            long vo = (tokB + tile * 64 + row) * ROWB + (long)(2 * DIM + h * 64) * 2 + ch * 16;
            CP16(sb + AT_KH(tile & 1) + row * AT_STRIDE + ch * 16, Hb + ko);
            CP16(sb + AT_VH(tile & 1) + row * AT_STRIDE + ch * 16, Hb + vo);
        }
        CPCOMMIT();
    };

    // ---- stage Q (both planes) + K/V tile 0
    #pragma unroll
    for (int u = 0; u < 4; u++) {
        int id = tid + u * 256;                  // 0..1023
        int row = id >> 3, ch = id & 7;
        long so = (tokB + q0 + row) * ROWB + (long)(h * 64) * 2 + ch * 16;
        CP16(sb + AT_QH + row * AT_STRIDE + ch * 16, Hb + so);
        CP16(sb + AT_QL + row * AT_STRIDE + ch * 16, Lb + so);
    }
    stage_kv(0);
    CPWAIT0();
    __syncthreads();

    // ---- load Q fragments once (warp owns rows wid*16 .. +15)
    uint32_t qh[4][4], ql[4][4];
    {
        uint32_t rb = (uint32_t)((wid * 16 + (lane & 15)) * AT_STRIDE + (lane >> 4) * 16);
        #pragma unroll
        for (int ks = 0; ks < 4; ks++) {
            LDSM4(qh[ks], sb + AT_QH + rb + ks * 32);
            LDSM4(ql[ks], sb + AT_QL + rb + ks * 32);
        }
    }

    float m0 = -1e30f, m1 = -1e30f, l0 = 0.f, l1 = 0.f;
    float O[8][4];
    #pragma unroll
    for (int j = 0; j < 8; j++)
        #pragma unroll
        for (int q = 0; q < 4; q++) O[j][q] = 0.f;

    const int NT = SS / 64;   // 16 K-tiles
    for (int c = 0; c < NT; c++) {
        if (c) { CPWAIT0(); __syncthreads(); }
        if (c + 1 < NT) stage_kv(c + 1);

        // ---- scores S[m16][kk64] = Q . K^T
        float s[8][4];
        #pragma unroll
        for (int j = 0; j < 8; j++)
            #pragma unroll
            for (int q = 0; q < 4; q++) s[j][q] = 0.f;

        uint32_t kb = sb + AT_KH(c & 1) + (uint32_t)((lane & 15) * AT_STRIDE + (lane >> 4) * 16);
        #pragma unroll
        for (int ks = 0; ks < 4; ks++) {        // d chunks of 16
            uint32_t kf[4][4];
            #pragma unroll
            for (int np = 0; np < 4; np++)
                LDSM4(kf[np], kb + np * (16 * AT_STRIDE) + ks * 32);
            #pragma unroll
            for (int np = 0; np < 4; np++) {
                mma16816(s[2 * np],     qh[ks], kf[np][0], kf[np][2]);
                mma16816(s[2 * np + 1], qh[ks], kf[np][1], kf[np][3]);
            }
            #pragma unroll
            for (int np = 0; np < 4; np++) {
                mma16816(s[2 * np],     ql[ks], kf[np][0], kf[np][2]);
                mma16816(s[2 * np + 1], ql[ks], kf[np][1], kf[np][3]);
            }
        }

        // ---- online softmax (2 rows/thread; quad = lanes sharing a row)
        float rm0 = -1e30f, rm1 = -1e30f;
        #pragma unroll
        for (int j = 0; j < 8; j++) {
            rm0 = fmaxf(rm0, fmaxf(s[j][0], s[j][1]));
            rm1 = fmaxf(rm1, fmaxf(s[j][2], s[j][3]));
        }
        rm0 = fmaxf(rm0, __shfl_xor_sync(0xffffffffu, rm0, 1));
        rm0 = fmaxf(rm0, __shfl_xor_sync(0xffffffffu, rm0, 2));
        rm1 = fmaxf(rm1, __shfl_xor_sync(0xffffffffu, rm1, 1));
        rm1 = fmaxf(rm1, __shfl_xor_sync(0xffffffffu, rm1, 2));
        float mn0 = fmaxf(m0, rm0), mn1 = fmaxf(m1, rm1);
        float a0 = __expf(m0 - mn0), a1 = __expf(m1 - mn1);
        m0 = mn0; m1 = mn1;
        float rs0 = 0.f, rs1 = 0.f;
        #pragma unroll
        for (int j = 0; j < 8; j++) {
            s[j][0] = __expf(s[j][0] - mn0);
            s[j][1] = __expf(s[j][1] - mn0);
            s[j][2] = __expf(s[j][2] - mn1);
            s[j][3] = __expf(s[j][3] - mn1);
            rs0 += s[j][0] + s[j][1];
            rs1 += s[j][2] + s[j][3];
        }
        rs0 += __shfl_xor_sync(0xffffffffu, rs0, 1);
        rs0 += __shfl_xor_sync(0xffffffffu, rs0, 2);
        rs1 += __shfl_xor_sync(0xffffffffu, rs1, 1);
        rs1 += __shfl_xor_sync(0xffffffffu, rs1, 2);
        l0 = l0 * a0 + rs0;
        l1 = l1 * a1 + rs1;
        #pragma unroll
        for (int j = 0; j < 8; j++) {
            O[j][0] *= a0; O[j][1] *= a0;
            O[j][2] *= a1; O[j][3] *= a1;
        }

        // ---- pack P hi/lo as A-fragments directly from score frags
        uint32_t ph[4][4], pl[4][4];
        #pragma unroll
        for (int ks = 0; ks < 4; ks++) {
            int j0 = 2 * ks, j1 = 2 * ks + 1;
            #pragma unroll
            for (int half = 0; half < 2; half++) {
                int jj = half ? j1 : j0;
                float x = s[jj][0], y = s[jj][1], z = s[jj][2], w = s[jj][3];
                __nv_bfloat16 hx = __float2bfloat16_rn(x);
                __nv_bfloat16 hy = __float2bfloat16_rn(y);
                __nv_bfloat16 hz = __float2bfloat16_rn(z);
                __nv_bfloat16 hw = __float2bfloat16_rn(w);
                __nv_bfloat162 P0; P0.x = hx; P0.y = hy;
                __nv_bfloat162 P1; P1.x = hz; P1.y = hw;
                ph[ks][2 * half]     = *(uint32_t*)&P0;
                ph[ks][2 * half + 1] = *(uint32_t*)&P1;
                pl[ks][2 * half]     = packbf(x - __bfloat162float(hx),
                                              y - __bfloat162float(hy));
                pl[ks][2 * half + 1] = packbf(z - __bfloat162float(hz),
                                              w - __bfloat162float(hw));
            }
        }

        // ---- O += P . V  (V via ldmatrix.trans)
        uint32_t vb = sb + AT_VH(c & 1) + (uint32_t)((lane & 15) * AT_STRIDE + (lane >> 4) * 16);
        #pragma unroll
        for (int ks = 0; ks < 4; ks++) {        // kk chunks of 16
            uint32_t vf[4][4];
            #pragma unroll
            for (int np = 0; np < 4; np++)
                LDSM4T(vf[np], vb + ks * (16 * AT_STRIDE) + np * 32);
            #pragma unroll
            for (int np = 0; np < 4; np++) {
                mma16816(O[2 * np],     ph[ks], vf[np][0], vf[np][1]);
                mma16816(O[2 * np + 1], ph[ks], vf[np][2], vf[np][3]);
            }
            #pragma unroll
            for (int np = 0; np < 4; np++) {
                mma16816(O[2 * np],     pl[ks], vf[np][0], vf[np][1]);
                mma16816(O[2 * np + 1], pl[ks], vf[np][2], vf[np][3]);
            }
        }
    }

    // ---- epilogue: O/l -> hi/lo planes at [tok][h*64 + d]
    float inv0 = 1.f / l0, inv1 = 1.f / l1;
    int g  = lane >> 2;
    int t2 = (lane & 3) * 2;
    long tok0 = (long)b * SS + q0 + wid * 16 + g;
    long tok1 = tok0 + 8;
    #pragma unroll
    for (int nj = 0; nj < 8; nj++) {
        int col = h * 64 + nj * 8 + t2;
        float v0 = O[nj][0] * inv0, v1 = O[nj][1] * inv0;
        float v2 = O[nj][2] * inv1, v3 = O[nj][3] * inv1;
        __nv_bfloat16 h0 = __float2bfloat16_rn(v0);
        __nv_bfloat16 h1 = __float2bfloat16_rn(v1);
        __nv_bfloat16 h2 = __float2bfloat16_rn(v2);
        __nv_bfloat16 h3 = __float2bfloat16_rn(v3);
        __nv_bfloat162 H0; H0.x = h0; H0.y = h1;
        __nv_bfloat162 H1; H1.x = h2; H1.y = h3;
        *(__nv_bfloat162*)(outH + tok0 * DIM + col) = H0;
        *(__nv_bfloat162*)(outH + tok1 * DIM + col) = H1;
        __nv_bfloat162 L0, L1;
        L0.x = __float2bfloat16_rn(v0 - __bfloat162float(h0));
        L0.y = __float2bfloat16_rn(v1 - __bfloat162float(h1));
        L1.x = __float2bfloat16_rn(v2 - __bfloat162float(h2));
        L1.y = __float2bfloat16_rn(v3 - __bfloat162float(h3));
        *(__nv_bfloat162*)(outL + tok0 * DIM + col) = L0;
        *(__nv_bfloat162*)(outL + tok1 * DIM + col) = L1;
    }
}

// ---------------- residual + LayerNorm; also emits x1 hi/lo planes ----------
__global__ void __launch_bounds__(256) ln_res_kernel(
    const float* __restrict__ a, const float* __restrict__ b,
    const float* __restrict__ g, const float* __restrict__ bt,
    float* __restrict__ out,
    __nv_bfloat16* __restrict__ outH, __nv_bfloat16* __restrict__ outL)
{
    long t  = blockIdx.x;
    int tid = threadIdx.x;
    float4 va = ((const float4*)(a + t * DIM))[tid];
    float4 vb = ((const float4*)(b + t * DIM))[tid];
    float v[4] = { va.x + vb.x, va.y + vb.y, va.z + vb.z, va.w + vb.w };
    float s1 = v[0] + v[1] + v[2] + v[3];
    float s2 = v[0]*v[0] + v[1]*v[1] + v[2]*v[2] + v[3]*v[3];
    #pragma unroll
    for (int o2 = 16; o2 >= 1; o2 >>= 1) {
        s1 += __shfl_xor_sync(0xffffffffu, s1, o2);
        s2 += __shfl_xor_sync(0xffffffffu, s2, o2);
    }
    __shared__ float r1[8], r2[8], mv[2];
    if ((tid & 31) == 0) { r1[tid >> 5] = s1; r2[tid >> 5] = s2; }
    __syncthreads();
    if (tid == 0) {
        float A = 0.f, Bq = 0.f;
        #pragma unroll
        for (int w = 0; w < 8; w++) { A += r1[w]; Bq += r2[w]; }
        float mean = A * (1.f / DIM);
        float var  = Bq * (1.f / DIM) - mean * mean;
        mv[0] = mean; mv[1] = rsqrtf(var + 1e-5f);
    }
    __syncthreads();
    float mean = mv[0], rstd = mv[1];
    float4 gg  = ((const float4*)g)[tid];
    float4 bbv = ((const float4*)bt)[tid];
    float4 ov;
    ov.x = (v[0] - mean) * rstd * gg.x + bbv.x;
    ov.y = (v[1] - mean) * rstd * gg.y + bbv.y;
    ov.z = (v[2] - mean) * rstd * gg.z + bbv.z;
    ov.w = (v[3] - mean) * rstd * gg.w + bbv.w;
    ((float4*)(out + t * DIM))[tid] = ov;

    __nv_bfloat16 h0 = __float2bfloat16_rn(ov.x), h1 = __float2bfloat16_rn(ov.y);
    __nv_bfloat16 h2 = __float2bfloat16_rn(ov.z), h3 = __float2bfloat16_rn(ov.w);
    __nv_bfloat162 H0; H0.x = h0; H0.y = h1;
    __nv_bfloat162 H1; H1.x = h2; H1.y = h3;
    __nv_bfloat162 L0, L1;
    L0.x = __float2bfloat16_rn(ov.x - __bfloat162float(h0));
    L0.y = __float2bfloat16_rn(ov.y - __bfloat162float(h1));
    L1.x = __float2bfloat16_rn(ov.z - __bfloat162float(h2));
    L1.y = __float2bfloat16_rn(ov.w - __bfloat162float(h3));
    ((__nv_bfloat162*)(outH + t * DIM))[2 * tid]     = H0;
    ((__nv_bfloat162*)(outH + t * DIM))[2 * tid + 1] = H1;
    ((__nv_bfloat162*)(outL + t * DIM))[2 * tid]     = L0;
    ((__nv_bfloat162*)(outL + t * DIM))[2 * tid + 1] = L1;
}

// ---------------- combine MoE slots + residual + LN2 -> d_out ----------------
__global__ void __launch_bounds__(256) ln2_kernel(
    const float* __restrict__ x1, const float* __restrict__ moe2,
    const float* __restrict__ g, const float* __restrict__ bt,
    float* __restrict__ out)
{
    long t  = blockIdx.x;
    int tid = threadIdx.x;
    float4 va = ((const float4*)(x1   + t * DIM))[tid];
    float4 vb = ((const float4*)(moe2 + (2 * t)     * DIM))[tid];
    float4 vc = ((const float4*)(moe2 + (2 * t + 1) * DIM))[tid];
    float v[4] = { va.x + vb.x + vc.x, va.y + vb.y + vc.y,
                   va.z + vb.z + vc.z, va.w + vb.w + vc.w };
    float s1 = v[0] + v[1] + v[2] + v[3];
    float s2 = v[0]*v[0] + v[1]*v[1] + v[2]*v[2] + v[3]*v[3];
    #pragma unroll
    for (int o2 = 16; o2 >= 1; o2 >>= 1) {
        s1 += __shfl_xor_sync(0xffffffffu, s1, o2);
        s2 += __shfl_xor_sync(0xffffffffu, s2, o2);
    }
    __shared__ float r1[8], r2[8], mv[2];
    if ((tid & 31) == 0) { r1[tid >> 5] = s1; r2[tid >> 5] = s2; }
    __syncthreads();
    if (tid == 0) {
        float A = 0.f, Bq = 0.f;
        #pragma unroll
        for (int w = 0; w < 8; w++) { A += r1[w]; Bq += r2[w]; }
        float mean = A * (1.f / DIM);
        float var  = Bq * (1.f / DIM) - mean * mean;
        mv[0] = mean; mv[1] = rsqrtf(var + 1e-5f);
    }
    __syncthreads();
    float mean = mv[0], rstd = mv[1];
    float4 gg  = ((const float4*)g)[tid];
    float4 bbv = ((const float4*)bt)[tid];
    float4 ov;
    ov.x = (v[0] - mean) * rstd * gg.x + bbv.x;
    ov.y = (v[1] - mean) * rstd * gg.y + bbv.y;
    ov.z = (v[2] - mean) * rstd * gg.z + bbv.z;
    ov.w = (v[3] - mean) * rstd * gg.w + bbv.w;
    ((float4*)(out + t * DIM))[tid] = ov;
}

// ---------------- gate: logits, softmax usage, top-2 -------------------------
__global__ void __launch_bounds__(256) gate_kernel(
    const float* __restrict__ x, const float* __restrict__ gw,
    const float* __restrict__ gb)
{
    int t = blockIdx.x;
    int w = threadIdx.x >> 5, lane = threadIdx.x & 31;
    const float* xr = x + (long)t * DIM;
    const float* wr = gw + w * DIM;
    float s = 0.f;
    for (int d = lane; d < DIM; d += 32) s += xr[d] * wr[d];
    #pragma unroll
    for (int o2 = 16; o2 >= 1; o2 >>= 1) s += __shfl_xor_sync(0xffffffffu, s, o2);
    __shared__ float lg[NEXP];
    if (lane == 0) lg[w] = s + gb[w];
    __syncthreads();
    if (threadIdx.x == 0) {
        float mx = lg[0];
        #pragma unroll
        for (int e = 1; e < NEXP; e++) mx = fmaxf(mx, lg[e]);
        float ex[NEXP], sum = 0.f;
        #pragma unroll
        for (int e = 0; e < NEXP; e++) { ex[e] = expf(lg[e] - mx); sum += ex[e]; }
        float inv = 1.f / sum;
        #pragma unroll
        for (int e = 0; e < NEXP; e++) atomicAdd(&g_usage[e], ex[e] * inv);
        int e0 = 0;
        #pragma unroll
        for (int e = 1; e < NEXP; e++) if (lg[e] > lg[e0]) e0 = e;
        int e1 = -1;
        #pragma unroll
        for (int e = 0; e < NEXP; e++)
            if (e != e0 && (e1 < 0 || lg[e] > lg[e1])) e1 = e;
        float z  = expf(lg[e1] - lg[e0]);
        float p0 = 1.f / (1.f + z);
        g_tidx[2 * t]     = e0;  g_tidx[2 * t + 1]  = e1;
        g_tprob[2 * t]    = p0;  g_tprob[2 * t + 1] = z * p0;
        atomicAdd(&g_count[e0], 1);
        atomicAdd(&g_count[e1], 1);
    }
}

__global__ void k_offsets() {
    if (threadIdx.x == 0) {
        int a = 0;
        for (int e = 0; e < NEXP; e++) { g_off[e] = a; a += g_count[e]; }
    }
}

__global__ void k_fill() {
    int t = blockIdx.x * blockDim.x + threadIdx.x;
    if (t < TOK) {
        #pragma unroll
        for (int k = 0; k < 2; k++) {
            int e   = g_tidx[2 * t + k];
            int pos = atomicAdd(&g_fill[e], 1);
            g_list[g_off[e] + pos] = 2 * t + k;
        }
    }
}

__global__ void k_aux(float* out) {
    float s = 0.f;
    #pragma unroll
    for (int e = 0; e < NEXP; e++) {
        float u = g_usage[e] * (1.f / TOK);
        s += u * u;
    }
    out[(size_t)TOK * DIM] = (float)NEXP * s;
}

// ---------------- launch ----------------
extern "C" void kernel_launch(void* const* d_in, const int* in_sizes, int n_in,
                              void* d_out, int out_size)
{
    (void)in_sizes; (void)n_in;
    const float* src  = (const float*)d_in[0];
    const float* ipw  = (const float*)d_in[1];
    const float* ipb  = (const float*)d_in[2];
    const float* outw = (const float*)d_in[3];
    const float* outb = (const float*)d_in[4];
    const float* gw   = (const float*)d_in[5];
    const float* gb   = (const float*)d_in[6];
    const float* w1   = (const float*)d_in[7];
    const float* b1   = (const float*)d_in[8];
    const float* w2   = (const float*)d_in[9];
    const float* b2   = (const float*)d_in[10];
    const float* ln1g = (const float*)d_in[11];
    const float* ln1b = (const float*)d_in[12];
    const float* ln2g = (const float*)d_in[13];
    const float* ln2b = (const float*)d_in[14];
    float* out = (float*)d_out;

    float *p_proj, *p_x1, *p_moe2;
    cudaGetSymbolAddress((void**)&p_proj, g_proj);
    cudaGetSymbolAddress((void**)&p_x1,   g_x1);
    cudaGetSymbolAddress((void**)&p_moe2, g_moe2);
    __nv_bfloat16 *qkvH, *qkvL, *srcH, *srcL, *attnH, *attnL, *x1H, *x1L, *hH, *hL;
    __nv_bfloat16 *ipwH, *ipwL, *outwH, *outwL, *w1H, *w1L, *w2H, *w2L;
    cudaGetSymbolAddress((void**)&qkvH,  g_qkvH);
    cudaGetSymbolAddress((void**)&qkvL,  g_qkvL);
    cudaGetSymbolAddress((void**)&srcH,  g_srcH);
    cudaGetSymbolAddress((void**)&srcL,  g_srcL);
    cudaGetSymbolAddress((void**)&attnH, g_attnH);
    cudaGetSymbolAddress((void**)&attnL, g_attnL);
    cudaGetSymbolAddress((void**)&x1H,   g_x1H);
    cudaGetSymbolAddress((void**)&x1L,   g_x1L);
    cudaGetSymbolAddress((void**)&hH,    g_hH);
    cudaGetSymbolAddress((void**)&hL,    g_hL);
    cudaGetSymbolAddress((void**)&ipwH,  g_ipwH);
    cudaGetSymbolAddress((void**)&ipwL,  g_ipwL);
    cudaGetSymbolAddress((void**)&outwH, g_outwH);
    cudaGetSymbolAddress((void**)&outwL, g_outwL);
    cudaGetSymbolAddress((void**)&w1H,   g_w1H);
    cudaGetSymbolAddress((void**)&w1L,   g_w1L);
    cudaGetSymbolAddress((void**)&w2H,   g_w2H);
    cudaGetSymbolAddress((void**)&w2L,   g_w2L);

    cudaFuncSetAttribute(attn_mma,
                         cudaFuncAttributeMaxDynamicSharedMemorySize, AT_SMEM);
    cudaFuncSetAttribute(mma_gemm<0>,
                         cudaFuncAttributeMaxDynamicSharedMemorySize, SM_TOTAL);
    cudaFuncSetAttribute(mma_gemm<1>,
                         cudaFuncAttributeMaxDynamicSharedMemorySize, SM_TOTAL);
    cudaFuncSetAttribute(mma_gemm<2>,
                         cudaFuncAttributeMaxDynamicSharedMemorySize, SM_TOTAL);
    cudaFuncSetAttribute(mma_gemm<3>,
                         cudaFuncAttributeMaxDynamicSharedMemorySize, SM_TOTAL);

    // 1) per-replay init
    k_init<<<1, 32>>>();
    // 2-5) operand plane conversions needed before QKV / MoE
    {
        long n;
        n = (long)TOK * DIM / 4;
        k_conv<<<(int)((n + 255) / 256), 256>>>(src, srcH, srcL, n);
        n = (long)QKVD * DIM / 4;
        k_conv<<<(int)((n + 255) / 256), 256>>>(ipw, ipwH, ipwL, n);
        n = (long)NEXP * FDIM * DIM / 4;
        k_conv<<<(int)((n + 255) / 256), 256>>>(w1, w1H, w1L, n);
        n = (long)NEXP * DIM * FDIM / 4;
        k_conv<<<(int)((n + 255) / 256), 256>>>(w2, w2H, w2L, n);
    }

    // 6) QKV projection -> hi/lo planes, Q columns pre-scaled by 1/8
    mma_gemm<3><<<dim3(QKVD / 128, TOK / 128, 1), 256, SM_TOTAL>>>(
        srcH, srcL, ipwH, ipwL, ipb, 0, qkvH, qkvL, TOK, QKVD, DIM, 0, 0);

    // 7) tensor-core flash attention -> attn hi/lo planes
    attn_mma<<<dim3(SS / 128, BB * NHEAD), 256, AT_SMEM>>>(qkvH, qkvL, attnH, attnL);

    // 8) out-proj weight planes (only needed from here on)
    {
        long n = (long)DIM * DIM / 4;
        k_conv<<<(int)((n + 255) / 256), 256>>>(outw, outwH, outwL, n);
    }

    // 9) output projection (fp32 out for LN)
    mma_gemm<0><<<dim3(DIM / 128, TOK / 128, 1), 256, SM_TOTAL>>>(
        attnH, attnL, outwH, outwL, outb, p_proj, 0, 0, TOK, DIM, DIM, 0, 0);

    // 10) x1 = LN(src + attn_out); also emit x1 planes
    ln_res_kernel<<<TOK, 256>>>(p_proj, src, ln1g, ln1b, p_x1, x1H, x1L);

    // 11) gating
    gate_kernel<<<TOK, 256>>>(p_x1, gw, gb);
    k_offsets<<<1, 32>>>();
    k_fill<<<TOK / 256, 256>>>();

    // 12) expert GEMM1: h = gelu(x1 @ w1[e]^T + b1[e]) -> hi/lo planes
    mma_gemm<1><<<dim3(FDIM / 128, TOK / 128, NEXP), 256, SM_TOTAL>>>(
        x1H, x1L, w1H, w1L, b1, 0, hH, hL,
        TOK, FDIM, DIM, (long)FDIM * DIM, FDIM);

    // 13) expert GEMM2: eo = (h @ w2[e]^T + b2[e]) * prob -> fp32 scatter
    mma_gemm<2><<<dim3(DIM / 128, TOK / 128, NEXP), 256, SM_TOTAL>>>(
        hH, hL, w2H, w2L, b2, p_moe2, 0, 0,
        TOK, DIM, FDIM, (long)DIM * FDIM, DIM);

    // 14) out = LN(x1 + moe_out)
    ln2_kernel<<<TOK, 256>>>(p_x1, p_moe2, ln2g, ln2b, out);

    // 15) aux loss
    if (out_size > TOK * DIM) k_aux<<<1, 1>>>(out);
}

// round 14
// speedup vs baseline: 1.0544x; 1.0544x over previous
#include <cuda_runtime.h>
#include <cuda_bf16.h>
#include <math.h>
#include <stdint.h>

// ---------------- problem constants ----------------
#define BB    2
#define SS    1024
#define TOK   2048          // B*S
#define DIM   1024
#define QKVD  3072
#define NHEAD 16
#define HDIM  64
#define NEXP  8
#define FDIM  4096
#define NSLOT 4096          // TOK * top_k

// ---------------- device scratch (no allocs allowed) ----------------
__device__ __align__(128) float g_proj[(size_t)TOK * DIM];
__device__ __align__(128) float g_x1  [(size_t)TOK * DIM];
__device__ __align__(128) float g_moe2[(size_t)NSLOT * DIM];

// hi/lo bf16 operand planes
__device__ __align__(128) __nv_bfloat16 g_qkvH [(size_t)TOK * QKVD];
__device__ __align__(128) __nv_bfloat16 g_qkvL [(size_t)TOK * QKVD];
__device__ __align__(128) __nv_bfloat16 g_srcH [(size_t)TOK * DIM];
__device__ __align__(128) __nv_bfloat16 g_srcL [(size_t)TOK * DIM];
__device__ __align__(128) __nv_bfloat16 g_attnH[(size_t)TOK * DIM];
__device__ __align__(128) __nv_bfloat16 g_attnL[(size_t)TOK * DIM];
__device__ __align__(128) __nv_bfloat16 g_x1H  [(size_t)TOK * DIM];
__device__ __align__(128) __nv_bfloat16 g_x1L  [(size_t)TOK * DIM];
__device__ __align__(128) __nv_bfloat16 g_hH   [(size_t)NSLOT * FDIM];
__device__ __align__(128) __nv_bfloat16 g_hL   [(size_t)NSLOT * FDIM];
__device__ __align__(128) __nv_bfloat16 g_ipwH [(size_t)QKVD * DIM];
__device__ __align__(128) __nv_bfloat16 g_ipwL [(size_t)QKVD * DIM];
__device__ __align__(128) __nv_bfloat16 g_outwH[(size_t)DIM * DIM];
__device__ __align__(128) __nv_bfloat16 g_outwL[(size_t)DIM * DIM];
__device__ __align__(128) __nv_bfloat16 g_w1H  [(size_t)NEXP * FDIM * DIM];
__device__ __align__(128) __nv_bfloat16 g_w1L  [(size_t)NEXP * FDIM * DIM];
__device__ __align__(128) __nv_bfloat16 g_w2H  [(size_t)NEXP * DIM * FDIM];
__device__ __align__(128) __nv_bfloat16 g_w2L  [(size_t)NEXP * DIM * FDIM];

__device__ int   g_tidx[NSLOT];
__device__ float g_tprob[NSLOT];
__device__ float g_usage[NEXP];
__device__ int   g_count[NEXP];
__device__ int   g_off[NEXP];
__device__ int   g_fill[NEXP];
__device__ int   g_list[NSLOT];

__device__ __forceinline__ float gelu_f(float x) {
    return 0.5f * x * (1.0f + erff(x * 0.70710678118654752f));
}

// ---------------- PTX helpers (all compute_103-legal) ----------------
__device__ __forceinline__ uint32_t smem_u32(const void* p) {
    uint32_t a;
    asm("{ .reg .u64 t; cvta.to.shared.u64 t, %1; cvt.u32.u64 %0, t; }"
        : "=r"(a) : "l"(p));
    return a;
}

#define CP16(dst, src) \
    asm volatile("cp.async.cg.shared.global [%0], [%1], 16;" \
                 :: "r"(dst), "l"(src) : "memory")
#define CPCOMMIT()  asm volatile("cp.async.commit_group;" ::: "memory")
#define CPWAIT0()   asm volatile("cp.async.wait_group 0;" ::: "memory")

#define LDSM4(R, addr) \
    asm volatile("ldmatrix.sync.aligned.m8n8.x4.shared.b16 {%0,%1,%2,%3}, [%4];" \
        : "=r"((R)[0]), "=r"((R)[1]), "=r"((R)[2]), "=r"((R)[3]) : "r"(addr))
#define LDSM4T(R, addr) \
    asm volatile("ldmatrix.sync.aligned.m8n8.x4.trans.shared.b16 {%0,%1,%2,%3}, [%4];" \
        : "=r"((R)[0]), "=r"((R)[1]), "=r"((R)[2]), "=r"((R)[3]) : "r"(addr))

__device__ __forceinline__ void mma16816(float* c, const uint32_t* a,
                                         uint32_t b0, uint32_t b1) {
    asm volatile(
        "mma.sync.aligned.m16n8k16.row.col.f32.bf16.bf16.f32 "
        "{%0,%1,%2,%3}, {%4,%5,%6,%7}, {%8,%9}, {%0,%1,%2,%3};"
        : "+f"(c[0]), "+f"(c[1]), "+f"(c[2]), "+f"(c[3])
        : "r"(a[0]), "r"(a[1]), "r"(a[2]), "r"(a[3]), "r"(b0), "r"(b1));
}

__device__ __forceinline__ uint32_t packbf(float a, float b) {
    __nv_bfloat162 t;
    t.x = __float2bfloat16_rn(a);
    t.y = __float2bfloat16_rn(b);
    return *(uint32_t*)&t;
}

// ---------------- init (re-zero per replay) ----------------
__global__ void k_init() {
    int i = threadIdx.x;
    if (i < NEXP) { g_usage[i] = 0.f; g_count[i] = 0; g_fill[i] = 0; }
}

// ---------------- fp32 -> (hi, lo) bf16 planes ----------------
__global__ void __launch_bounds__(256) k_conv(
    const float* __restrict__ x, __nv_bfloat16* __restrict__ hi,
    __nv_bfloat16* __restrict__ lo, long n4)
{
    long i = (long)blockIdx.x * blockDim.x + threadIdx.x;
    if (i >= n4) return;
    float4 v = ((const float4*)x)[i];
    __nv_bfloat16 h0 = __float2bfloat16_rn(v.x);
    __nv_bfloat16 h1 = __float2bfloat16_rn(v.y);
    __nv_bfloat16 h2 = __float2bfloat16_rn(v.z);
    __nv_bfloat16 h3 = __float2bfloat16_rn(v.w);
    __nv_bfloat162 H0; H0.x = h0; H0.y = h1;
    __nv_bfloat162 H1; H1.x = h2; H1.y = h3;
    __nv_bfloat162 L0, L1;
    L0.x = __float2bfloat16_rn(v.x - __bfloat162float(h0));
    L0.y = __float2bfloat16_rn(v.y - __bfloat162float(h1));
    L1.x = __float2bfloat16_rn(v.z - __bfloat162float(h2));
    L1.y = __float2bfloat16_rn(v.w - __bfloat162float(h3));
    ((__nv_bfloat162*)hi)[2 * i]     = H0;
    ((__nv_bfloat162*)hi)[2 * i + 1] = H1;
    ((__nv_bfloat162*)lo)[2 * i]     = L0;
    ((__nv_bfloat162*)lo)[2 * i + 1] = L1;
}

// =====================================================================
// bf16-split NT GEMM via mma.sync (R9 champion config):
//   tile 128x128x32, 8 warps (2m x 4n), hi/lo planes,
//   2-stage cp.async double buffer, ONE __syncthreads per K-chunk
//   (wait -> sync -> prefetch(c+1) -> compute(c); the single barrier
//    both publishes chunk c and protects buf[(c+1)&1] WAR)
// MODE 0: C fp32 = acc + bias
// MODE 1: A rows gathered via g_list (token=slot>>1); gelu(acc+bias) ->
//         hi/lo bf16 planes at row g_off[e]+m
// MODE 2: A rows = g_off[e]+m; (acc+bias)*prob -> fp32 scatter to row slot
// MODE 3: plain A rows; (acc+bias) [cols<DIM scaled 1/8] -> hi/lo planes
// =====================================================================
#define TSB   80            // smem row stride bytes (64 data + 16 pad)
#define PL    10240         // one plane: 128 rows * 80B
#define BUFB  40960         // 4 planes (Ahi, Alo, Bhi, Blo)
#define SM_BIAS  81920      // after 2 buffers (82KB keeps 2 CTAs/SM)
#define SM_TOTAL (SM_BIAS + 512)

template<int MODE>
__global__ void __launch_bounds__(256)
mma_gemm(const __nv_bfloat16* __restrict__ Ah, const __nv_bfloat16* __restrict__ Al,
         const __nv_bfloat16* __restrict__ Bh, const __nv_bfloat16* __restrict__ Bl,
         const float* __restrict__ bias,
         float* __restrict__ Cf,
         __nv_bfloat16* __restrict__ ChH, __nv_bfloat16* __restrict__ ChL,
         int M, int N, int K, long strideBe, int strideBiasE)
{
    extern __shared__ char smem[];
    const uint32_t sb = smem_u32(smem);

    int tid  = threadIdx.x;
    int wid  = tid >> 5, lane = tid & 31;
    int mBase = blockIdx.y * 128;
    int nBase = blockIdx.x * 128;

    int count = M, off = 0;
    const int* lst = 0;
    if (MODE == 1 || MODE == 2) {
        int e = blockIdx.z;
        count = g_count[e];
        if (mBase >= count) return;
        off  = g_off[e];
        Bh  += (long)e * strideBe;
        Bl  += (long)e * strideBe;
        bias += (long)e * strideBiasE;
        lst  = g_list + off;
    }

    if (tid < 128) *(float*)(smem + SM_BIAS + tid * 4) = bias[nBase + tid];

    // ---- cp.async source setup: thread -> (row r, 32B half hf)
    int r  = tid >> 1;
    int hf = tid & 1;
    long aRow;
    {
        int mIdxL = mBase + r;
        if (MODE == 0 || MODE == 3) aRow = mIdxL;
        else if (MODE == 1) aRow = (long)(lst[min(mIdxL, count - 1)] >> 1);
        else                aRow = (long)off + min(mIdxL, count - 1);
    }
    const char* aH = (const char*)(Ah + aRow * (long)K) + hf * 32;
    const char* aL = (const char*)(Al + aRow * (long)K) + hf * 32;
    const char* bH = (const char*)(Bh + (long)(nBase + r) * K) + hf * 32;
    const char* bL = (const char*)(Bl + (long)(nBase + r) * K) + hf * 32;
    uint32_t d0 = sb + (uint32_t)(r * TSB + hf * 32);

    const int NC = K >> 5;   // 32-K chunks

    auto stage_chunk = [&](int cc) {
        long ob = (long)cc * 64;     // 32 bf16 = 64 bytes
        uint32_t db = d0 + (uint32_t)((cc & 1) * BUFB);
        CP16(db,              aH + ob);  CP16(db + 16,              aH + ob + 16);
        CP16(db + PL,         aL + ob);  CP16(db + PL + 16,         aL + ob + 16);
        CP16(db + 2 * PL,     bH + ob);  CP16(db + 2 * PL + 16,     bH + ob + 16);
        CP16(db + 3 * PL,     bL + ob);  CP16(db + 3 * PL + 16,     bL + ob + 16);
        CPCOMMIT();
    };

    // prologue: stage chunk 0
    stage_chunk(0);

    // warp compute setup
    int wm = wid >> 2;           // 0..1  (m half)
    int wn = wid & 3;            // 0..3  (n quarter)
    uint32_t laneoff = (uint32_t)((lane & 15) * TSB + (lane >> 4) * 16);
    uint32_t aBaseOff = (uint32_t)(wm * 64 * TSB) + laneoff;
    uint32_t bBaseOff = (uint32_t)(2 * PL + wn * 32 * TSB) + laneoff;

    float acc[4][4][4];
    #pragma unroll
    for (int i = 0; i < 4; i++)
        #pragma unroll
        for (int j = 0; j < 4; j++)
            #pragma unroll
            for (int q = 0; q < 4; q++) acc[i][j][q] = 0.f;

    // mainloop: wait(chunk c) -> sync -> prefetch(c+1) -> compute(c)
    for (int c = 0; c < NC; c++) {
        CPWAIT0();
        __syncthreads();
        if (c + 1 < NC) stage_chunk(c + 1);

        uint32_t base = sb + (uint32_t)((c & 1) * BUFB);
        #pragma unroll
        for (int ks = 0; ks < 2; ks++) {
            uint32_t ah[4][4], al[4][4], bh[2][4], bl[2][4];
            #pragma unroll
            for (int mi = 0; mi < 4; mi++) {
                uint32_t ad = base + aBaseOff + mi * (16 * TSB) + ks * 32;
                LDSM4(ah[mi], ad);
                LDSM4(al[mi], ad + PL);
            }
            #pragma unroll
            for (int np = 0; np < 2; np++) {
                uint32_t bd = base + bBaseOff + np * (16 * TSB) + ks * 32;
                LDSM4(bh[np], bd);
                LDSM4(bl[np], bd + PL);
            }
            #pragma unroll
            for (int mi = 0; mi < 4; mi++)
                #pragma unroll
                for (int nj = 0; nj < 4; nj++) {
                    int np = nj >> 1, s = nj & 1;
                    mma16816(acc[mi][nj], ah[mi], bh[np][s], bh[np][s + 2]);
                }
            #pragma unroll
            for (int mi = 0; mi < 4; mi++)
                #pragma unroll
                for (int nj = 0; nj < 4; nj++) {
                    int np = nj >> 1, s = nj & 1;
                    mma16816(acc[mi][nj], ah[mi], bl[np][s], bl[np][s + 2]);
                }
            #pragma unroll
            for (int mi = 0; mi < 4; mi++)
                #pragma unroll
                for (int nj = 0; nj < 4; nj++) {
                    int np = nj >> 1, s = nj & 1;
                    mma16816(acc[mi][nj], al[mi], bh[np][s], bh[np][s + 2]);
                }
        }
    }

    // ---- epilogue (regs only; bias smem ordered by first loop sync)
    int g  = lane >> 2;
    int tg = lane & 3;
    const float* sbias = (const float*)(smem + SM_BIAS);
    float qs = 1.f;
    if (MODE == 3) qs = (nBase < DIM) ? 0.125f : 1.f;   // pre-scale Q by 1/sqrt(HD)

    #pragma unroll
    for (int mi = 0; mi < 4; mi++) {
        #pragma unroll
        for (int hrow = 0; hrow < 2; hrow++) {
            int rm = wm * 64 + mi * 16 + g + hrow * 8;  // row in tile
            int m  = mBase + rm;
            if ((MODE == 1 || MODE == 2) && m >= count) continue;
            long cRow; float scl = 1.f;
            if (MODE == 0 || MODE == 3) cRow = m;
            else if (MODE == 1)         cRow = (long)off + m;
            else { int slot = lst[m]; cRow = slot; scl = g_tprob[slot]; }
            #pragma unroll
            for (int nj = 0; nj < 4; nj++) {
                int col = wn * 32 + nj * 8 + tg * 2;
                float vx = acc[mi][nj][hrow * 2]     + sbias[col];
                float vy = acc[mi][nj][hrow * 2 + 1] + sbias[col + 1];
                if (MODE == 1) { vx = gelu_f(vx); vy = gelu_f(vy); }
                if (MODE == 3) { vx *= qs; vy *= qs; }
                if (MODE == 1 || MODE == 3) {
                    __nv_bfloat16 hx = __float2bfloat16_rn(vx);
                    __nv_bfloat16 hy = __float2bfloat16_rn(vy);
                    __nv_bfloat162 H; H.x = hx; H.y = hy;
                    __nv_bfloat162 L;
                    L.x = __float2bfloat16_rn(vx - __bfloat162float(hx));
                    L.y = __float2bfloat16_rn(vy - __bfloat162float(hy));
                    long idx = cRow * (long)N + nBase + col;
                    *(__nv_bfloat162*)(ChH + idx) = H;
                    *(__nv_bfloat162*)(ChL + idx) = L;
                } else {
                    float2 v; v.x = vx * scl; v.y = vy * scl;
                    *(float2*)(Cf + cRow * (long)N + nBase + col) = v;
                }
            }
        }
    }
}

// =====================================================================
// FA2-style mma attention: 128 q-rows/CTA, 8 warps x m16, K-tile 64.
// Single __syncthreads per K-tile (wait -> sync -> prefetch -> compute).
// =====================================================================
#define AT_STRIDE 144                    // 64 bf16 cols + 16B pad
#define AT_KVB    18432                  // Kh(9216) + Vh(9216) per buffer
#define AT_KH(b)  ((b) * AT_KVB)
#define AT_VH(b)  ((b) * AT_KVB + 9216)
#define AT_QH     36864
#define AT_QL     55296
#define AT_SMEM   73728

__global__ void __launch_bounds__(256) attn_mma(
    const __nv_bfloat16* __restrict__ qkvH,
    const __nv_bfloat16* __restrict__ qkvL,
    __nv_bfloat16* __restrict__ outH, __nv_bfloat16* __restrict__ outL)
{
    extern __shared__ char smem[];
    const uint32_t sb = smem_u32(smem);
    int tid = threadIdx.x, wid = tid >> 5, lane = tid & 31;
    int bh = blockIdx.y;
    int b  = bh >> 4, h = bh & 15;
    int q0 = blockIdx.x * 128;

    const char* Hb = (const char*)qkvH;
    const char* Lb = (const char*)qkvL;
    const long ROWB = (long)QKVD * 2;            // bytes per token row
    const long tokB = (long)b * SS;

    auto stage_kv = [&](int tile) {
        #pragma unroll
        for (int u = 0; u < 2; u++) {
            int id = tid + u * 256;
            int row = id >> 3, ch = id & 7;
            long ko = (tokB + tile * 64 + row) * ROWB + (long)(DIM     + h * 64) * 2 + ch * 16;
            long vo = (tokB + tile * 64 + row) * ROWB + (long)(2 * DIM + h * 64) * 2 + ch * 16;
            CP16(sb + AT_KH(tile & 1) + row * AT_STRIDE + ch * 16, Hb + ko);
            CP16(sb + AT_VH(tile & 1) + row * AT_STRIDE + ch * 16, Hb + vo);
        }
        CPCOMMIT();
    };

    // ---- stage Q (both planes) + K/V tile 0
    #pragma unroll
    for (int u = 0; u < 4; u++) {
        int id = tid + u * 256;                  // 0..1023
        int row = id >> 3, ch = id & 7;
        long so = (tokB + q0 + row) * ROWB + (long)(h * 64) * 2 + ch * 16;
        CP16(sb + AT_QH + row * AT_STRIDE + ch * 16, Hb + so);
        CP16(sb + AT_QL + row * AT_STRIDE + ch * 16, Lb + so);
    }
    stage_kv(0);
    CPWAIT0();
    __syncthreads();

    // ---- load Q fragments once (warp owns rows wid*16 .. +15)
    uint32_t qh[4][4], ql[4][4];
    {
        uint32_t rb = (uint32_t)((wid * 16 + (lane & 15)) * AT_STRIDE + (lane >> 4) * 16);
        #pragma unroll
        for (int ks = 0; ks < 4; ks++) {
            LDSM4(qh[ks], sb + AT_QH + rb + ks * 32);
            LDSM4(ql[ks], sb + AT_QL + rb + ks * 32);
        }
    }

    float m0 = -1e30f, m1 = -1e30f, l0 = 0.f, l1 = 0.f;
    float O[8][4];
    #pragma unroll
    for (int j = 0; j < 8; j++)
        #pragma unroll
        for (int q = 0; q < 4; q++) O[j][q] = 0.f;

    const int NT = SS / 64;   // 16 K-tiles
    for (int c = 0; c < NT; c++) {
        if (c) { CPWAIT0(); __syncthreads(); }
        if (c + 1 < NT) stage_kv(c + 1);

        // ---- scores S[m16][kk64] = Q . K^T
        float s[8][4];
        #pragma unroll
        for (int j = 0; j < 8; j++)
            #pragma unroll
            for (int q = 0; q < 4; q++) s[j][q] = 0.f;

        uint32_t kb = sb + AT_KH(c & 1) + (uint32_t)((lane & 15) * AT_STRIDE + (lane >> 4) * 16);
        #pragma unroll
        for (int ks = 0; ks < 4; ks++) {        // d chunks of 16
            uint32_t kf[4][4];
            #pragma unroll
            for (int np = 0; np < 4; np++)
                LDSM4(kf[np], kb + np * (16 * AT_STRIDE) + ks * 32);
            #pragma unroll
            for (int np = 0; np < 4; np++) {
                mma16816(s[2 * np],     qh[ks], kf[np][0], kf[np][2]);
                mma16816(s[2 * np + 1], qh[ks], kf[np][1], kf[np][3]);
            }
            #pragma unroll
            for (int np = 0; np < 4; np++) {
                mma16816(s[2 * np],     ql[ks], kf[np][0], kf[np][2]);
                mma16816(s[2 * np + 1], ql[ks], kf[np][1], kf[np][3]);
            }
        }

        // ---- online softmax (2 rows/thread; quad = lanes sharing a row)
        float rm0 = -1e30f, rm1 = -1e30f;
        #pragma unroll
        for (int j = 0; j < 8; j++) {
            rm0 = fmaxf(rm0, fmaxf(s[j][0], s[j][1]));
            rm1 = fmaxf(rm1, fmaxf(s[j][2], s[j][3]));
        }
        rm0 = fmaxf(rm0, __shfl_xor_sync(0xffffffffu, rm0, 1));
        rm0 = fmaxf(rm0, __shfl_xor_sync(0xffffffffu, rm0, 2));
        rm1 = fmaxf(rm1, __shfl_xor_sync(0xffffffffu, rm1, 1));
        rm1 = fmaxf(rm1, __shfl_xor_sync(0xffffffffu, rm1, 2));
        float mn0 = fmaxf(m0, rm0), mn1 = fmaxf(m1, rm1);
        float a0 = __expf(m0 - mn0), a1 = __expf(m1 - mn1);
        m0 = mn0; m1 = mn1;
        float rs0 = 0.f, rs1 = 0.f;
        #pragma unroll
        for (int j = 0; j < 8; j++) {
            s[j][0] = __expf(s[j][0] - mn0);
            s[j][1] = __expf(s[j][1] - mn0);
            s[j][2] = __expf(s[j][2] - mn1);
            s[j][3] = __expf(s[j][3] - mn1);
            rs0 += s[j][0] + s[j][1];
            rs1 += s[j][2] + s[j][3];
        }
        rs0 += __shfl_xor_sync(0xffffffffu, rs0, 1);
        rs0 += __shfl_xor_sync(0xffffffffu, rs0, 2);
        rs1 += __shfl_xor_sync(0xffffffffu, rs1, 1);
        rs1 += __shfl_xor_sync(0xffffffffu, rs1, 2);
        l0 = l0 * a0 + rs0;
        l1 = l1 * a1 + rs1;
        #pragma unroll
        for (int j = 0; j < 8; j++) {
            O[j][0] *= a0; O[j][1] *= a0;
            O[j][2] *= a1; O[j][3] *= a1;
        }

        // ---- pack P hi/lo as A-fragments directly from score frags
        uint32_t ph[4][4], pl[4][4];
        #pragma unroll
        for (int ks = 0; ks < 4; ks++) {
            int j0 = 2 * ks, j1 = 2 * ks + 1;
            #pragma unroll
            for (int half = 0; half < 2; half++) {
                int jj = half ? j1 : j0;
                float x = s[jj][0], y = s[jj][1], z = s[jj][2], w = s[jj][3];
                __nv_bfloat16 hx = __float2bfloat16_rn(x);
                __nv_bfloat16 hy = __float2bfloat16_rn(y);
                __nv_bfloat16 hz = __float2bfloat16_rn(z);
                __nv_bfloat16 hw = __float2bfloat16_rn(w);
                __nv_bfloat162 P0; P0.x = hx; P0.y = hy;
                __nv_bfloat162 P1; P1.x = hz; P1.y = hw;
                ph[ks][2 * half]     = *(uint32_t*)&P0;
                ph[ks][2 * half + 1] = *(uint32_t*)&P1;
                pl[ks][2 * half]     = packbf(x - __bfloat162float(hx),
                                              y - __bfloat162float(hy));
                pl[ks][2 * half + 1] = packbf(z - __bfloat162float(hz),
                                              w - __bfloat162float(hw));
            }
        }

        // ---- O += P . V  (V via ldmatrix.trans)
        uint32_t vb = sb + AT_VH(c & 1) + (uint32_t)((lane & 15) * AT_STRIDE + (lane >> 4) * 16);
        #pragma unroll
        for (int ks = 0; ks < 4; ks++) {        // kk chunks of 16
            uint32_t vf[4][4];
            #pragma unroll
            for (int np = 0; np < 4; np++)
                LDSM4T(vf[np], vb + ks * (16 * AT_STRIDE) + np * 32);
            #pragma unroll
            for (int np = 0; np < 4; np++) {
                mma16816(O[2 * np],     ph[ks], vf[np][0], vf[np][1]);
                mma16816(O[2 * np + 1], ph[ks], vf[np][2], vf[np][3]);
            }
            #pragma unroll
            for (int np = 0; np < 4; np++) {
                mma16816(O[2 * np],     pl[ks], vf[np][0], vf[np][1]);
                mma16816(O[2 * np + 1], pl[ks], vf[np][2], vf[np][3]);
            }
        }
    }

    // ---- epilogue: O/l -> hi/lo planes at [tok][h*64 + d]
    float inv0 = 1.f / l0, inv1 = 1.f / l1;
    int g  = lane >> 2;
    int t2 = (lane & 3) * 2;
    long tok0 = (long)b * SS + q0 + wid * 16 + g;
    long tok1 = tok0 + 8;
    #pragma unroll
    for (int nj = 0; nj < 8; nj++) {
        int col = h * 64 + nj * 8 + t2;
        float v0 = O[nj][0] * inv0, v1 = O[nj][1] * inv0;
        float v2 = O[nj][2] * inv1, v3 = O[nj][3] * inv1;
        __nv_bfloat16 h0 = __float2bfloat16_rn(v0);
        __nv_bfloat16 h1 = __float2bfloat16_rn(v1);
        __nv_bfloat16 h2 = __float2bfloat16_rn(v2);
        __nv_bfloat16 h3 = __float2bfloat16_rn(v3);
        __nv_bfloat162 H0; H0.x = h0; H0.y = h1;
        __nv_bfloat162 H1; H1.x = h2; H1.y = h3;
        *(__nv_bfloat162*)(outH + tok0 * DIM + col) = H0;
        *(__nv_bfloat162*)(outH + tok1 * DIM + col) = H1;
        __nv_bfloat162 L0, L1;
        L0.x = __float2bfloat16_rn(v0 - __bfloat162float(h0));
        L0.y = __float2bfloat16_rn(v1 - __bfloat162float(h1));
        L1.x = __float2bfloat16_rn(v2 - __bfloat162float(h2));
        L1.y = __float2bfloat16_rn(v3 - __bfloat162float(h3));
        *(__nv_bfloat162*)(outL + tok0 * DIM + col) = L0;
        *(__nv_bfloat162*)(outL + tok1 * DIM + col) = L1;
    }
}

// ---------------- residual + LayerNorm; also emits x1 hi/lo planes ----------
__global__ void __launch_bounds__(256) ln_res_kernel(
    const float* __restrict__ a, const float* __restrict__ b,
    const float* __restrict__ g, const float* __restrict__ bt,
    float* __restrict__ out,
    __nv_bfloat16* __restrict__ outH, __nv_bfloat16* __restrict__ outL)
{
    long t  = blockIdx.x;
    int tid = threadIdx.x;
    float4 va = ((const float4*)(a + t * DIM))[tid];
    float4 vb = ((const float4*)(b + t * DIM))[tid];
    float v[4] = { va.x + vb.x, va.y + vb.y, va.z + vb.z, va.w + vb.w };
    float s1 = v[0] + v[1] + v[2] + v[3];
    float s2 = v[0]*v[0] + v[1]*v[1] + v[2]*v[2] + v[3]*v[3];
    #pragma unroll
    for (int o2 = 16; o2 >= 1; o2 >>= 1) {
        s1 += __shfl_xor_sync(0xffffffffu, s1, o2);
        s2 += __shfl_xor_sync(0xffffffffu, s2, o2);
    }
    __shared__ float r1[8], r2[8], mv[2];
    if ((tid & 31) == 0) { r1[tid >> 5] = s1; r2[tid >> 5] = s2; }
    __syncthreads();
    if (tid == 0) {
        float A = 0.f, Bq = 0.f;
        #pragma unroll
        for (int w = 0; w < 8; w++) { A += r1[w]; Bq += r2[w]; }
        float mean = A * (1.f / DIM);
        float var  = Bq * (1.f / DIM) - mean * mean;
        mv[0] = mean; mv[1] = rsqrtf(var + 1e-5f);
    }
    __syncthreads();
    float mean = mv[0], rstd = mv[1];
    float4 gg  = ((const float4*)g)[tid];
    float4 bbv = ((const float4*)bt)[tid];
    float4 ov;
    ov.x = (v[0] - mean) * rstd * gg.x + bbv.x;
    ov.y = (v[1] - mean) * rstd * gg.y + bbv.y;
    ov.z = (v[2] - mean) * rstd * gg.z + bbv.z;
    ov.w = (v[3] - mean) * rstd * gg.w + bbv.w;
    ((float4*)(out + t * DIM))[tid] = ov;

    __nv_bfloat16 h0 = __float2bfloat16_rn(ov.x), h1 = __float2bfloat16_rn(ov.y);
    __nv_bfloat16 h2 = __float2bfloat16_rn(ov.z), h3 = __float2bfloat16_rn(ov.w);
    __nv_bfloat162 H0; H0.x = h0; H0.y = h1;
    __nv_bfloat162 H1; H1.x = h2; H1.y = h3;
    __nv_bfloat162 L0, L1;
    L0.x = __float2bfloat16_rn(ov.x - __bfloat162float(h0));
    L0.y = __float2bfloat16_rn(ov.y - __bfloat162float(h1));
    L1.x = __float2bfloat16_rn(ov.z - __bfloat162float(h2));
    L1.y = __float2bfloat16_rn(ov.w - __bfloat162float(h3));
    ((__nv_bfloat162*)(outH + t * DIM))[2 * tid]     = H0;
    ((__nv_bfloat162*)(outH + t * DIM))[2 * tid + 1] = H1;
    ((__nv_bfloat162*)(outL + t * DIM))[2 * tid]     = L0;
    ((__nv_bfloat162*)(outL + t * DIM))[2 * tid + 1] = L1;
}

// ---------------- combine MoE slots + residual + LN2 -> d_out ----------------
__global__ void __launch_bounds__(256) ln2_kernel(
    const float* __restrict__ x1, const float* __restrict__ moe2,
    const float* __restrict__ g, const float* __restrict__ bt,
    float* __restrict__ out)
{
    long t  = blockIdx.x;
    int tid = threadIdx.x;
    float4 va = ((const float4*)(x1   + t * DIM))[tid];
    float4 vb = ((const float4*)(moe2 + (2 * t)     * DIM))[tid];
    float4 vc = ((const float4*)(moe2 + (2 * t + 1) * DIM))[tid];
    float v[4] = { va.x + vb.x + vc.x, va.y + vb.y + vc.y,
                   va.z + vb.z + vc.z, va.w + vb.w + vc.w };
    float s1 = v[0] + v[1] + v[2] + v[3];
    float s2 = v[0]*v[0] + v[1]*v[1] + v[2]*v[2] + v[3]*v[3];
    #pragma unroll
    for (int o2 = 16; o2 >= 1; o2 >>= 1) {
        s1 += __shfl_xor_sync(0xffffffffu, s1, o2);
        s2 += __shfl_xor_sync(0xffffffffu, s2, o2);
    }
    __shared__ float r1[8], r2[8], mv[2];
    if ((tid & 31) == 0) { r1[tid >> 5] = s1; r2[tid >> 5] = s2; }
    __syncthreads();
    if (tid == 0) {
        float A = 0.f, Bq = 0.f;
        #pragma unroll
        for (int w = 0; w < 8; w++) { A += r1[w]; Bq += r2[w]; }
        float mean = A * (1.f / DIM);
        float var  = Bq * (1.f / DIM) - mean * mean;
        mv[0] = mean; mv[1] = rsqrtf(var + 1e-5f);
    }
    __syncthreads();
    float mean = mv[0], rstd = mv[1];
    float4 gg  = ((const float4*)g)[tid];
    float4 bbv = ((const float4*)bt)[tid];
    float4 ov;
    ov.x = (v[0] - mean) * rstd * gg.x + bbv.x;
    ov.y = (v[1] - mean) * rstd * gg.y + bbv.y;
    ov.z = (v[2] - mean) * rstd * gg.z + bbv.z;
    ov.w = (v[3] - mean) * rstd * gg.w + bbv.w;
    ((float4*)(out + t * DIM))[tid] = ov;
}

// ---------------- gate: logits, softmax usage, top-2 -------------------------
__global__ void __launch_bounds__(256) gate_kernel(
    const float* __restrict__ x, const float* __restrict__ gw,
    const float* __restrict__ gb)
{
    int t = blockIdx.x;
    int w = threadIdx.x >> 5, lane = threadIdx.x & 31;
    const float* xr = x + (long)t * DIM;
    const float* wr = gw + w * DIM;
    float s = 0.f;
    for (int d = lane; d < DIM; d += 32) s += xr[d] * wr[d];
    #pragma unroll
    for (int o2 = 16; o2 >= 1; o2 >>= 1) s += __shfl_xor_sync(0xffffffffu, s, o2);
    __shared__ float lg[NEXP];
    if (lane == 0) lg[w] = s + gb[w];
    __syncthreads();
    if (threadIdx.x == 0) {
        float mx = lg[0];
        #pragma unroll
        for (int e = 1; e < NEXP; e++) mx = fmaxf(mx, lg[e]);
        float ex[NEXP], sum = 0.f;
        #pragma unroll
        for (int e = 0; e < NEXP; e++) { ex[e] = expf(lg[e] - mx); sum += ex[e]; }
        float inv = 1.f / sum;
        #pragma unroll
        for (int e = 0; e < NEXP; e++) atomicAdd(&g_usage[e], ex[e] * inv);
        int e0 = 0;
        #pragma unroll
        for (int e = 1; e < NEXP; e++) if (lg[e] > lg[e0]) e0 = e;
        int e1 = -1;
        #pragma unroll
        for (int e = 0; e < NEXP; e++)
            if (e != e0 && (e1 < 0 || lg[e] > lg[e1])) e1 = e;
        float z  = expf(lg[e1] - lg[e0]);
        float p0 = 1.f / (1.f + z);
        g_tidx[2 * t]     = e0;  g_tidx[2 * t + 1]  = e1;
        g_tprob[2 * t]    = p0;  g_tprob[2 * t + 1] = z * p0;
        atomicAdd(&g_count[e0], 1);
        atomicAdd(&g_count[e1], 1);
    }
}

__global__ void k_offsets() {
    if (threadIdx.x == 0) {
        int a = 0;
        for (int e = 0; e < NEXP; e++) { g_off[e] = a; a += g_count[e]; }
    }
}

__global__ void k_fill() {
    int t = blockIdx.x * blockDim.x + threadIdx.x;
    if (t < TOK) {
        #pragma unroll
        for (int k = 0; k < 2; k++) {
            int e   = g_tidx[2 * t + k];
            int pos = atomicAdd(&g_fill[e], 1);
            g_list[g_off[e] + pos] = 2 * t + k;
        }
    }
}

__global__ void k_aux(float* out) {
    float s = 0.f;
    #pragma unroll
    for (int e = 0; e < NEXP; e++) {
        float u = g_usage[e] * (1.f / TOK);
        s += u * u;
    }
    out[(size_t)TOK * DIM] = (float)NEXP * s;
}

// ---------------- launch ----------------
extern "C" void kernel_launch(void* const* d_in, const int* in_sizes, int n_in,
                              void* d_out, int out_size)
{
    (void)in_sizes; (void)n_in;
    const float* src  = (const float*)d_in[0];
    const float* ipw  = (const float*)d_in[1];
    const float* ipb  = (const float*)d_in[2];
    const float* outw = (const float*)d_in[3];
    const float* outb = (const float*)d_in[4];
    const float* gw   = (const float*)d_in[5];
    const float* gb   = (const float*)d_in[6];
    const float* w1   = (const float*)d_in[7];
    const float* b1   = (const float*)d_in[8];
    const float* w2   = (const float*)d_in[9];
    const float* b2   = (const float*)d_in[10];
    const float* ln1g = (const float*)d_in[11];
    const float* ln1b = (const float*)d_in[12];
    const float* ln2g = (const float*)d_in[13];
    const float* ln2b = (const float*)d_in[14];
    float* out = (float*)d_out;

    float *p_proj, *p_x1, *p_moe2;
    cudaGetSymbolAddress((void**)&p_proj, g_proj);
    cudaGetSymbolAddress((void**)&p_x1,   g_x1);
    cudaGetSymbolAddress((void**)&p_moe2, g_moe2);
    __nv_bfloat16 *qkvH, *qkvL, *srcH, *srcL, *attnH, *attnL, *x1H, *x1L, *hH, *hL;
    __nv_bfloat16 *ipwH, *ipwL, *outwH, *outwL, *w1H, *w1L, *w2H, *w2L;
    cudaGetSymbolAddress((void**)&qkvH,  g_qkvH);
    cudaGetSymbolAddress((void**)&qkvL,  g_qkvL);
    cudaGetSymbolAddress((void**)&srcH,  g_srcH);
    cudaGetSymbolAddress((void**)&srcL,  g_srcL);
    cudaGetSymbolAddress((void**)&attnH, g_attnH);
    cudaGetSymbolAddress((void**)&attnL, g_attnL);
    cudaGetSymbolAddress((void**)&x1H,   g_x1H);
    cudaGetSymbolAddress((void**)&x1L,   g_x1L);
    cudaGetSymbolAddress((void**)&hH,    g_hH);
    cudaGetSymbolAddress((void**)&hL,    g_hL);
    cudaGetSymbolAddress((void**)&ipwH,  g_ipwH);
    cudaGetSymbolAddress((void**)&ipwL,  g_ipwL);
    cudaGetSymbolAddress((void**)&outwH, g_outwH);
    cudaGetSymbolAddress((void**)&outwL, g_outwL);
    cudaGetSymbolAddress((void**)&w1H,   g_w1H);
    cudaGetSymbolAddress((void**)&w1L,   g_w1L);
    cudaGetSymbolAddress((void**)&w2H,   g_w2H);
    cudaGetSymbolAddress((void**)&w2L,   g_w2L);

    cudaFuncSetAttribute(attn_mma,
                         cudaFuncAttributeMaxDynamicSharedMemorySize, AT_SMEM);
    cudaFuncSetAttribute(mma_gemm<0>,
                         cudaFuncAttributeMaxDynamicSharedMemorySize, SM_TOTAL);
    cudaFuncSetAttribute(mma_gemm<1>,
                         cudaFuncAttributeMaxDynamicSharedMemorySize, SM_TOTAL);
    cudaFuncSetAttribute(mma_gemm<2>,
                         cudaFuncAttributeMaxDynamicSharedMemorySize, SM_TOTAL);
    cudaFuncSetAttribute(mma_gemm<3>,
                         cudaFuncAttributeMaxDynamicSharedMemorySize, SM_TOTAL);

    // Launch order: QKV GEMM is launch #5 and attention #6 so the ncu
    // capture window (which has been landing on launch ~5) hits a tensor
    // kernel instead of a conversion kernel.
    // 1) per-replay init
    k_init<<<1, 32>>>();
    // 2-4) conversions needed before QKV + expert GEMM1
    {
        long n;
        n = (long)TOK * DIM / 4;
        k_conv<<<(int)((n + 255) / 256), 256>>>(src, srcH, srcL, n);
        n = (long)QKVD * DIM / 4;
        k_conv<<<(int)((n + 255) / 256), 256>>>(ipw, ipwH, ipwL, n);
        n = (long)NEXP * FDIM * DIM / 4;
        k_conv<<<(int)((n + 255) / 256), 256>>>(w1, w1H, w1L, n);
    }

    // 5) QKV projection -> hi/lo planes, Q columns pre-scaled by 1/8
    mma_gemm<3><<<dim3(QKVD / 128, TOK / 128, 1), 256, SM_TOTAL>>>(
        srcH, srcL, ipwH, ipwL, ipb, 0, qkvH, qkvL, TOK, QKVD, DIM, 0, 0);

    // 6) tensor-core flash attention -> attn hi/lo planes
    attn_mma<<<dim3(SS / 128, BB * NHEAD), 256, AT_SMEM>>>(qkvH, qkvL, attnH, attnL);

    // 7-8) remaining weight conversions (first consumers are steps 10/14)
    {
        long n = (long)DIM * DIM / 4;
        k_conv<<<(int)((n + 255) / 256), 256>>>(outw, outwH, outwL, n);
        n = (long)NEXP * DIM * FDIM / 4;
        k_conv<<<(int)((n + 255) / 256), 256>>>(w2, w2H, w2L, n);
    }

    // 9) output projection (fp32 out for LN)
    mma_gemm<0><<<dim3(DIM / 128, TOK / 128, 1), 256, SM_TOTAL>>>(
        attnH, attnL, outwH, outwL, outb, p_proj, 0, 0, TOK, DIM, DIM, 0, 0);

    // 10) x1 = LN(src + attn_out); also emit x1 planes
    ln_res_kernel<<<TOK, 256>>>(p_proj, src, ln1g, ln1b, p_x1, x1H, x1L);

    // 11) gating
    gate_kernel<<<TOK, 256>>>(p_x1, gw, gb);
    k_offsets<<<1, 32>>>();
    k_fill<<<TOK / 256, 256>>>();

    // 12) expert GEMM1: h = gelu(x1 @ w1[e]^T + b1[e]) -> hi/lo planes
    mma_gemm<1><<<dim3(FDIM / 128, TOK / 128, NEXP), 256, SM_TOTAL>>>(
        x1H, x1L, w1H, w1L, b1, 0, hH, hL,
        TOK, FDIM, DIM, (long)FDIM * DIM, FDIM);

    // 13) expert GEMM2: eo = (h @ w2[e]^T + b2[e]) * prob -> fp32 scatter
    mma_gemm<2><<<dim3(DIM / 128, TOK / 128, NEXP), 256, SM_TOTAL>>>(
        hH, hL, w2H, w2L, b2, p_moe2, 0, 0,
        TOK, DIM, FDIM, (long)DIM * FDIM, DIM);

    // 14) out = LN(x1 + moe_out)
    ln2_kernel<<<TOK, 256>>>(p_x1, p_moe2, ln2g, ln2b, out);

    // 15) aux loss
    if (out_size > TOK * DIM) k_aux<<<1, 1>>>(out);
}

// round 15
// speedup vs baseline: 1.1675x; 1.1073x over previous
#include <cuda_runtime.h>
#include <cuda_bf16.h>
#include <math.h>
#include <stdint.h>

// ---------------- problem constants ----------------
#define BB    2
#define SS    1024
#define TOK   2048          // B*S
#define DIM   1024
#define QKVD  3072
#define NHEAD 16
#define HDIM  64
#define NEXP  8
#define FDIM  4096
#define NSLOT 4096          // TOK * top_k

// ---------------- device scratch (no allocs allowed) ----------------
__device__ __align__(128) float g_proj[(size_t)TOK * DIM];
__device__ __align__(128) float g_x1  [(size_t)TOK * DIM];
__device__ __align__(128) float g_moe2[(size_t)NSLOT * DIM];

// hi/lo bf16 operand planes
__device__ __align__(128) __nv_bfloat16 g_qkvH [(size_t)TOK * QKVD];
__device__ __align__(128) __nv_bfloat16 g_qkvL [(size_t)TOK * QKVD];
__device__ __align__(128) __nv_bfloat16 g_srcH [(size_t)TOK * DIM];
__device__ __align__(128) __nv_bfloat16 g_srcL [(size_t)TOK * DIM];
__device__ __align__(128) __nv_bfloat16 g_attnH[(size_t)TOK * DIM];
__device__ __align__(128) __nv_bfloat16 g_attnL[(size_t)TOK * DIM];
__device__ __align__(128) __nv_bfloat16 g_x1H  [(size_t)TOK * DIM];
__device__ __align__(128) __nv_bfloat16 g_x1L  [(size_t)TOK * DIM];
__device__ __align__(128) __nv_bfloat16 g_hH   [(size_t)NSLOT * FDIM];
__device__ __align__(128) __nv_bfloat16 g_hL   [(size_t)NSLOT * FDIM];
__device__ __align__(128) __nv_bfloat16 g_ipwH [(size_t)QKVD * DIM];
__device__ __align__(128) __nv_bfloat16 g_ipwL [(size_t)QKVD * DIM];
__device__ __align__(128) __nv_bfloat16 g_outwH[(size_t)DIM * DIM];
__device__ __align__(128) __nv_bfloat16 g_outwL[(size_t)DIM * DIM];
__device__ __align__(128) __nv_bfloat16 g_w1H  [(size_t)NEXP * FDIM * DIM];
__device__ __align__(128) __nv_bfloat16 g_w1L  [(size_t)NEXP * FDIM * DIM];
__device__ __align__(128) __nv_bfloat16 g_w2H  [(size_t)NEXP * DIM * FDIM];
__device__ __align__(128) __nv_bfloat16 g_w2L  [(size_t)NEXP * DIM * FDIM];

__device__ int   g_tidx[NSLOT];
__device__ float g_tprob[NSLOT];
__device__ float g_usage[NEXP];
__device__ int   g_count[NEXP];
__device__ int   g_off[NEXP];
__device__ int   g_fill[NEXP];
__device__ int   g_list[NSLOT];

__device__ __forceinline__ float gelu_f(float x) {
    return 0.5f * x * (1.0f + erff(x * 0.70710678118654752f));
}

// ---------------- PTX helpers (all compute_103-legal) ----------------
__device__ __forceinline__ uint32_t smem_u32(const void* p) {
    uint32_t a;
    asm("{ .reg .u64 t; cvta.to.shared.u64 t, %1; cvt.u32.u64 %0, t; }"
        : "=r"(a) : "l"(p));
    return a;
}

#define CP16(dst, src) \
    asm volatile("cp.async.cg.shared.global [%0], [%1], 16;" \
                 :: "r"(dst), "l"(src) : "memory")
#define CPCOMMIT()  asm volatile("cp.async.commit_group;" ::: "memory")
#define CPWAIT0()   asm volatile("cp.async.wait_group 0;" ::: "memory")

#define LDSM4(R, addr) \
    asm volatile("ldmatrix.sync.aligned.m8n8.x4.shared.b16 {%0,%1,%2,%3}, [%4];" \
        : "=r"((R)[0]), "=r"((R)[1]), "=r"((R)[2]), "=r"((R)[3]) : "r"(addr))
#define LDSM4T(R, addr) \
    asm volatile("ldmatrix.sync.aligned.m8n8.x4.trans.shared.b16 {%0,%1,%2,%3}, [%4];" \
        : "=r"((R)[0]), "=r"((R)[1]), "=r"((R)[2]), "=r"((R)[3]) : "r"(addr))

__device__ __forceinline__ void mma16816(float* c, const uint32_t* a,
                                         uint32_t b0, uint32_t b1) {
    asm volatile(
        "mma.sync.aligned.m16n8k16.row.col.f32.bf16.bf16.f32 "
        "{%0,%1,%2,%3}, {%4,%5,%6,%7}, {%8,%9}, {%0,%1,%2,%3};"
        : "+f"(c[0]), "+f"(c[1]), "+f"(c[2]), "+f"(c[3])
        : "r"(a[0]), "r"(a[1]), "r"(a[2]), "r"(a[3]), "r"(b0), "r"(b1));
}

__device__ __forceinline__ uint32_t packbf(float a, float b) {
    __nv_bfloat162 t;
    t.x = __float2bfloat16_rn(a);
    t.y = __float2bfloat16_rn(b);
    return *(uint32_t*)&t;
}

// ---------------- init (re-zero per replay) ----------------
__global__ void k_init() {
    int i = threadIdx.x;
    if (i < NEXP) { g_usage[i] = 0.f; g_count[i] = 0; g_fill[i] = 0; }
}

// ---------------- fp32 -> (hi, lo) bf16 planes ----------------
__global__ void __launch_bounds__(256) k_conv(
    const float* __restrict__ x, __nv_bfloat16* __restrict__ hi,
    __nv_bfloat16* __restrict__ lo, long n4)
{
    long i = (long)blockIdx.x * blockDim.x + threadIdx.x;
    if (i >= n4) return;
    float4 v = ((const float4*)x)[i];
    __nv_bfloat16 h0 = __float2bfloat16_rn(v.x);
    __nv_bfloat16 h1 = __float2bfloat16_rn(v.y);
    __nv_bfloat16 h2 = __float2bfloat16_rn(v.z);
    __nv_bfloat16 h3 = __float2bfloat16_rn(v.w);
    __nv_bfloat162 H0; H0.x = h0; H0.y = h1;
    __nv_bfloat162 H1; H1.x = h2; H1.y = h3;
    __nv_bfloat162 L0, L1;
    L0.x = __float2bfloat16_rn(v.x - __bfloat162float(h0));
    L0.y = __float2bfloat16_rn(v.y - __bfloat162float(h1));
    L1.x = __float2bfloat16_rn(v.z - __bfloat162float(h2));
    L1.y = __float2bfloat16_rn(v.w - __bfloat162float(h3));
    ((__nv_bfloat162*)hi)[2 * i]     = H0;
    ((__nv_bfloat162*)hi)[2 * i + 1] = H1;
    ((__nv_bfloat162*)lo)[2 * i]     = L0;
    ((__nv_bfloat162*)lo)[2 * i + 1] = L1;
}

// =====================================================================
// bf16-split NT GEMM via mma.sync (R9 champion pipeline):
//   tile 128x128x32, 8 warps (2m x 4n), hi/lo planes,
//   2-stage cp.async double buffer, ONE __syncthreads per K-chunk.
// Split-3 (hi*hi + hi*lo + lo*hi) for MODE 0/2/3.
// MODE 1 uses split-2 (drops A-lo correction; A = x1, whose quantization
//   error attenuates ~50x end-to-end per the R7 attention measurement):
//   skips Alo staging + ldmatrix + the third MMA pass (-33% MMAs, -25% load).
// MODE 0: C fp32 = acc + bias
// MODE 1: A rows gathered via g_list (token=slot>>1); gelu(acc+bias) ->
//         hi/lo bf16 planes at row g_off[e]+m
// MODE 2: A rows = g_off[e]+m; (acc+bias)*prob -> fp32 scatter to row slot
// MODE 3: plain A rows; (acc+bias) [cols<DIM scaled 1/8] -> hi/lo planes
// =====================================================================
#define TSB   80            // smem row stride bytes (64 data + 16 pad)
#define PL    10240         // one plane: 128 rows * 80B
#define BUFB  40960         // 4 planes (Ahi, Alo, Bhi, Blo)
#define SM_BIAS  81920      // after 2 buffers (82KB keeps 2 CTAs/SM)
#define SM_TOTAL (SM_BIAS + 512)

template<int MODE>
__global__ void __launch_bounds__(256)
mma_gemm(const __nv_bfloat16* __restrict__ Ah, const __nv_bfloat16* __restrict__ Al,
         const __nv_bfloat16* __restrict__ Bh, const __nv_bfloat16* __restrict__ Bl,
         const float* __restrict__ bias,
         float* __restrict__ Cf,
         __nv_bfloat16* __restrict__ ChH, __nv_bfloat16* __restrict__ ChL,
         int M, int N, int K, long strideBe, int strideBiasE)
{
    extern __shared__ char smem[];
    const uint32_t sb = smem_u32(smem);

    int tid  = threadIdx.x;
    int wid  = tid >> 5, lane = tid & 31;
    int mBase = blockIdx.y * 128;
    int nBase = blockIdx.x * 128;

    int count = M, off = 0;
    const int* lst = 0;
    if (MODE == 1 || MODE == 2) {
        int e = blockIdx.z;
        count = g_count[e];
        if (mBase >= count) return;
        off  = g_off[e];
        Bh  += (long)e * strideBe;
        Bl  += (long)e * strideBe;
        bias += (long)e * strideBiasE;
        lst  = g_list + off;
    }

    if (tid < 128) *(float*)(smem + SM_BIAS + tid * 4) = bias[nBase + tid];

    // ---- cp.async source setup: thread -> (row r, 32B half hf)
    int r  = tid >> 1;
    int hf = tid & 1;
    long aRow;
    {
        int mIdxL = mBase + r;
        if (MODE == 0 || MODE == 3) aRow = mIdxL;
        else if (MODE == 1) aRow = (long)(lst[min(mIdxL, count - 1)] >> 1);
        else                aRow = (long)off + min(mIdxL, count - 1);
    }
    const char* aH = (const char*)(Ah + aRow * (long)K) + hf * 32;
    const char* aL = (const char*)(Al + aRow * (long)K) + hf * 32;
    const char* bH = (const char*)(Bh + (long)(nBase + r) * K) + hf * 32;
    const char* bL = (const char*)(Bl + (long)(nBase + r) * K) + hf * 32;
    uint32_t d0 = sb + (uint32_t)(r * TSB + hf * 32);

    const int NC = K >> 5;   // 32-K chunks

    auto stage_chunk = [&](int cc) {
        long ob = (long)cc * 64;     // 32 bf16 = 64 bytes
        uint32_t db = d0 + (uint32_t)((cc & 1) * BUFB);
        CP16(db,              aH + ob);  CP16(db + 16,              aH + ob + 16);
        if (MODE != 1) {
            CP16(db + PL,     aL + ob);  CP16(db + PL + 16,         aL + ob + 16);
        }
        CP16(db + 2 * PL,     bH + ob);  CP16(db + 2 * PL + 16,     bH + ob + 16);
        CP16(db + 3 * PL,     bL + ob);  CP16(db + 3 * PL + 16,     bL + ob + 16);
        CPCOMMIT();
    };

    // prologue: stage chunk 0
    stage_chunk(0);

    // warp compute setup
    int wm = wid >> 2;           // 0..1  (m half)
    int wn = wid & 3;            // 0..3  (n quarter)
    uint32_t laneoff = (uint32_t)((lane & 15) * TSB + (lane >> 4) * 16);
    uint32_t aBaseOff = (uint32_t)(wm * 64 * TSB) + laneoff;
    uint32_t bBaseOff = (uint32_t)(2 * PL + wn * 32 * TSB) + laneoff;

    float acc[4][4][4];
    #pragma unroll
    for (int i = 0; i < 4; i++)
        #pragma unroll
        for (int j = 0; j < 4; j++)
            #pragma unroll
            for (int q = 0; q < 4; q++) acc[i][j][q] = 0.f;

    // mainloop: wait(chunk c) -> sync -> prefetch(c+1) -> compute(c)
    for (int c = 0; c < NC; c++) {
        CPWAIT0();
        __syncthreads();
        if (c + 1 < NC) stage_chunk(c + 1);

        uint32_t base = sb + (uint32_t)((c & 1) * BUFB);
        #pragma unroll
        for (int ks = 0; ks < 2; ks++) {
            uint32_t ah[4][4], al[4][4], bh[2][4], bl[2][4];
            #pragma unroll
            for (int mi = 0; mi < 4; mi++) {
                uint32_t ad = base + aBaseOff + mi * (16 * TSB) + ks * 32;
                LDSM4(ah[mi], ad);
                if (MODE != 1) LDSM4(al[mi], ad + PL);
            }
            #pragma unroll
            for (int np = 0; np < 2; np++) {
                uint32_t bd = base + bBaseOff + np * (16 * TSB) + ks * 32;
                LDSM4(bh[np], bd);
                LDSM4(bl[np], bd + PL);
            }
            #pragma unroll
            for (int mi = 0; mi < 4; mi++)
                #pragma unroll
                for (int nj = 0; nj < 4; nj++) {
                    int np = nj >> 1, s = nj & 1;
                    mma16816(acc[mi][nj], ah[mi], bh[np][s], bh[np][s + 2]);
                }
            #pragma unroll
            for (int mi = 0; mi < 4; mi++)
                #pragma unroll
                for (int nj = 0; nj < 4; nj++) {
                    int np = nj >> 1, s = nj & 1;
                    mma16816(acc[mi][nj], ah[mi], bl[np][s], bl[np][s + 2]);
                }
            if (MODE != 1) {
                #pragma unroll
                for (int mi = 0; mi < 4; mi++)
                    #pragma unroll
                    for (int nj = 0; nj < 4; nj++) {
                        int np = nj >> 1, s = nj & 1;
                        mma16816(acc[mi][nj], al[mi], bh[np][s], bh[np][s + 2]);
                    }
            }
        }
    }

    // ---- epilogue (regs only; bias smem ordered by first loop sync)
    int g  = lane >> 2;
    int tg = lane & 3;
    const float* sbias = (const float*)(smem + SM_BIAS);
    float qs = 1.f;
    if (MODE == 3) qs = (nBase < DIM) ? 0.125f : 1.f;   // pre-scale Q by 1/sqrt(HD)

    #pragma unroll
    for (int mi = 0; mi < 4; mi++) {
        #pragma unroll
        for (int hrow = 0; hrow < 2; hrow++) {
            int rm = wm * 64 + mi * 16 + g + hrow * 8;  // row in tile
            int m  = mBase + rm;
            if ((MODE == 1 || MODE == 2) && m >= count) continue;
            long cRow; float scl = 1.f;
            if (MODE == 0 || MODE == 3) cRow = m;
            else if (MODE == 1)         cRow = (long)off + m;
            else { int slot = lst[m]; cRow = slot; scl = g_tprob[slot]; }
            #pragma unroll
            for (int nj = 0; nj < 4; nj++) {
                int col = wn * 32 + nj * 8 + tg * 2;
                float vx = acc[mi][nj][hrow * 2]     + sbias[col];
                float vy = acc[mi][nj][hrow * 2 + 1] + sbias[col + 1];
                if (MODE == 1) { vx = gelu_f(vx); vy = gelu_f(vy); }
                if (MODE == 3) { vx *= qs; vy *= qs; }
                if (MODE == 1 || MODE == 3) {
                    __nv_bfloat16 hx = __float2bfloat16_rn(vx);
                    __nv_bfloat16 hy = __float2bfloat16_rn(vy);
                    __nv_bfloat162 H; H.x = hx; H.y = hy;
                    __nv_bfloat162 L;
                    L.x = __float2bfloat16_rn(vx - __bfloat162float(hx));
                    L.y = __float2bfloat16_rn(vy - __bfloat162float(hy));
                    long idx = cRow * (long)N + nBase + col;
                    *(__nv_bfloat162*)(ChH + idx) = H;
                    *(__nv_bfloat162*)(ChL + idx) = L;
                } else {
                    float2 v; v.x = vx * scl; v.y = vy * scl;
                    *(float2*)(Cf + cRow * (long)N + nBase + col) = v;
                }
            }
        }
    }
}

// =====================================================================
// FA2-style mma attention: 128 q-rows/CTA, 8 warps x m16, K-tile 64.
// Single __syncthreads per K-tile (wait -> sync -> prefetch -> compute).
// =====================================================================
#define AT_STRIDE 144                    // 64 bf16 cols + 16B pad
#define AT_KVB    18432                  // Kh(9216) + Vh(9216) per buffer
#define AT_KH(b)  ((b) * AT_KVB)
#define AT_VH(b)  ((b) * AT_KVB + 9216)
#define AT_QH     36864
#define AT_QL     55296
#define AT_SMEM   73728

__global__ void __launch_bounds__(256) attn_mma(
    const __nv_bfloat16* __restrict__ qkvH,
    const __nv_bfloat16* __restrict__ qkvL,
    __nv_bfloat16* __restrict__ outH, __nv_bfloat16* __restrict__ outL)
{
    extern __shared__ char smem[];
    const uint32_t sb = smem_u32(smem);
    int tid = threadIdx.x, wid = tid >> 5, lane = tid & 31;
    int bh = blockIdx.y;
    int b  = bh >> 4, h = bh & 15;
    int q0 = blockIdx.x * 128;

    const char* Hb = (const char*)qkvH;
    const char* Lb = (const char*)qkvL;
    const long ROWB = (long)QKVD * 2;            // bytes per token row
    const long tokB = (long)b * SS;

    auto stage_kv = [&](int tile) {
        #pragma unroll
        for (int u = 0; u < 2; u++) {
            int id = tid + u * 256;
            int row = id >> 3, ch = id & 7;
            long ko = (tokB + tile * 64 + row) * ROWB + (long)(DIM     + h * 64) * 2 + ch * 16;
            long vo = (tokB + tile * 64 + row) * ROWB + (long)(2 * DIM + h * 64) * 2 + ch * 16;
            CP16(sb + AT_KH(tile & 1) + row * AT_STRIDE + ch * 16, Hb + ko);
            CP16(sb + AT_VH(tile & 1) + row * AT_STRIDE + ch * 16, Hb + vo);
        }
        CPCOMMIT();
    };

    // ---- stage Q (both planes) + K/V tile 0
    #pragma unroll
    for (int u = 0; u < 4; u++) {
        int id = tid + u * 256;                  // 0..1023
        int row = id >> 3, ch = id & 7;
        long so = (tokB + q0 + row) * ROWB + (long)(h * 64) * 2 + ch * 16;
        CP16(sb + AT_QH + row * AT_STRIDE + ch * 16, Hb + so);
        CP16(sb + AT_QL + row * AT_STRIDE + ch * 16, Lb + so);
    }
    stage_kv(0);
    CPWAIT0();
    __syncthreads();

    // ---- load Q fragments once (warp owns rows wid*16 .. +15)
    uint32_t qh[4][4], ql[4][4];
    {
        uint32_t rb = (uint32_t)((wid * 16 + (lane & 15)) * AT_STRIDE + (lane >> 4) * 16);
        #pragma unroll
        for (int ks = 0; ks < 4; ks++) {
            LDSM4(qh[ks], sb + AT_QH + rb + ks * 32);
            LDSM4(ql[ks], sb + AT_QL + rb + ks * 32);
        }
    }

    float m0 = -1e30f, m1 = -1e30f, l0 = 0.f, l1 = 0.f;
    float O[8][4];
    #pragma unroll
    for (int j = 0; j < 8; j++)
        #pragma unroll
        for (int q = 0; q < 4; q++) O[j][q] = 0.f;

    const int NT = SS / 64;   // 16 K-tiles
    for (int c = 0; c < NT; c++) {
        if (c) { CPWAIT0(); __syncthreads(); }
        if (c + 1 < NT) stage_kv(c + 1);

        // ---- scores S[m16][kk64] = Q . K^T
        float s[8][4];
        #pragma unroll
        for (int j = 0; j < 8; j++)
            #pragma unroll
            for (int q = 0; q < 4; q++) s[j][q] = 0.f;

        uint32_t kb = sb + AT_KH(c & 1) + (uint32_t)((lane & 15) * AT_STRIDE + (lane >> 4) * 16);
        #pragma unroll
        for (int ks = 0; ks < 4; ks++) {        // d chunks of 16
            uint32_t kf[4][4];
            #pragma unroll
            for (int np = 0; np < 4; np++)
                LDSM4(kf[np], kb + np * (16 * AT_STRIDE) + ks * 32);
            #pragma unroll
            for (int np = 0; np < 4; np++) {
                mma16816(s[2 * np],     qh[ks], kf[np][0], kf[np][2]);
                mma16816(s[2 * np + 1], qh[ks], kf[np][1], kf[np][3]);
            }
            #pragma unroll
            for (int np = 0; np < 4; np++) {
                mma16816(s[2 * np],     ql[ks], kf[np][0], kf[np][2]);
                mma16816(s[2 * np + 1], ql[ks], kf[np][1], kf[np][3]);
            }
        }

        // ---- online softmax (2 rows/thread; quad = lanes sharing a row)
        float rm0 = -1e30f, rm1 = -1e30f;
        #pragma unroll
        for (int j = 0; j < 8; j++) {
            rm0 = fmaxf(rm0, fmaxf(s[j][0], s[j][1]));
            rm1 = fmaxf(rm1, fmaxf(s[j][2], s[j][3]));
        }
        rm0 = fmaxf(rm0, __shfl_xor_sync(0xffffffffu, rm0, 1));
        rm0 = fmaxf(rm0, __shfl_xor_sync(0xffffffffu, rm0, 2));
        rm1 = fmaxf(rm1, __shfl_xor_sync(0xffffffffu, rm1, 1));
        rm1 = fmaxf(rm1, __shfl_xor_sync(0xffffffffu, rm1, 2));
        float mn0 = fmaxf(m0, rm0), mn1 = fmaxf(m1, rm1);
        float a0 = __expf(m0 - mn0), a1 = __expf(m1 - mn1);
        m0 = mn0; m1 = mn1;
        float rs0 = 0.f, rs1 = 0.f;
        #pragma unroll
        for (int j = 0; j < 8; j++) {
            s[j][0] = __expf(s[j][0] - mn0);
            s[j][1] = __expf(s[j][1] - mn0);
            s[j][2] = __expf(s[j][2] - mn1);
            s[j][3] = __expf(s[j][3] - mn1);
            rs0 += s[j][0] + s[j][1];
            rs1 += s[j][2] + s[j][3];
        }
        rs0 += __shfl_xor_sync(0xffffffffu, rs0, 1);
        rs0 += __shfl_xor_sync(0xffffffffu, rs0, 2);
        rs1 += __shfl_xor_sync(0xffffffffu, rs1, 1);
        rs1 += __shfl_xor_sync(0xffffffffu, rs1, 2);
        l0 = l0 * a0 + rs0;
        l1 = l1 * a1 + rs1;
        #pragma unroll
        for (int j = 0; j < 8; j++) {
            O[j][0] *= a0; O[j][1] *= a0;
            O[j][2] *= a1; O[j][3] *= a1;
        }

        // ---- pack P hi/lo as A-fragments directly from score frags
        uint32_t ph[4][4], pl[4][4];
        #pragma unroll
        for (int ks = 0; ks < 4; ks++) {
            int j0 = 2 * ks, j1 = 2 * ks + 1;
            #pragma unroll
            for (int half = 0; half < 2; half++) {
                int jj = half ? j1 : j0;
                float x = s[jj][0], y = s[jj][1], z = s[jj][2], w = s[jj][3];
                __nv_bfloat16 hx = __float2bfloat16_rn(x);
                __nv_bfloat16 hy = __float2bfloat16_rn(y);
                __nv_bfloat16 hz = __float2bfloat16_rn(z);
                __nv_bfloat16 hw = __float2bfloat16_rn(w);
                __nv_bfloat162 P0; P0.x = hx; P0.y = hy;
                __nv_bfloat162 P1; P1.x = hz; P1.y = hw;
                ph[ks][2 * half]     = *(uint32_t*)&P0;
                ph[ks][2 * half + 1] = *(uint32_t*)&P1;
                pl[ks][2 * half]     = packbf(x - __bfloat162float(hx),
                                              y - __bfloat162float(hy));
                pl[ks][2 * half + 1] = packbf(z - __bfloat162float(hz),
                                              w - __bfloat162float(hw));
            }
        }

        // ---- O += P . V  (V via ldmatrix.trans)
        uint32_t vb = sb + AT_VH(c & 1) + (uint32_t)((lane & 15) * AT_STRIDE + (lane >> 4) * 16);
        #pragma unroll
        for (int ks = 0; ks < 4; ks++) {        // kk chunks of 16
            uint32_t vf[4][4];
            #pragma unroll
            for (int np = 0; np < 4; np++)
                LDSM4T(vf[np], vb + ks * (16 * AT_STRIDE) + np * 32);
            #pragma unroll
            for (int np = 0; np < 4; np++) {
                mma16816(O[2 * np],     ph[ks], vf[np][0], vf[np][1]);
                mma16816(O[2 * np + 1], ph[ks], vf[np][2], vf[np][3]);
            }
            #pragma unroll
            for (int np = 0; np < 4; np++) {
                mma16816(O[2 * np],     pl[ks], vf[np][0], vf[np][1]);
                mma16816(O[2 * np + 1], pl[ks], vf[np][2], vf[np][3]);
            }
        }
    }

    // ---- epilogue: O/l -> hi/lo planes at [tok][h*64 + d]
    float inv0 = 1.f / l0, inv1 = 1.f / l1;
    int g  = lane >> 2;
    int t2 = (lane & 3) * 2;
    long tok0 = (long)b * SS + q0 + wid * 16 + g;
    long tok1 = tok0 + 8;
    #pragma unroll
    for (int nj = 0; nj < 8; nj++) {
        int col = h * 64 + nj * 8 + t2;
        float v0 = O[nj][0] * inv0, v1 = O[nj][1] * inv0;
        float v2 = O[nj][2] * inv1, v3 = O[nj][3] * inv1;
        __nv_bfloat16 h0 = __float2bfloat16_rn(v0);
        __nv_bfloat16 h1 = __float2bfloat16_rn(v1);
        __nv_bfloat16 h2 = __float2bfloat16_rn(v2);
        __nv_bfloat16 h3 = __float2bfloat16_rn(v3);
        __nv_bfloat162 H0; H0.x = h0; H0.y = h1;
        __nv_bfloat162 H1; H1.x = h2; H1.y = h3;
        *(__nv_bfloat162*)(outH + tok0 * DIM + col) = H0;
        *(__nv_bfloat162*)(outH + tok1 * DIM + col) = H1;
        __nv_bfloat162 L0, L1;
        L0.x = __float2bfloat16_rn(v0 - __bfloat162float(h0));
        L0.y = __float2bfloat16_rn(v1 - __bfloat162float(h1));
        L1.x = __float2bfloat16_rn(v2 - __bfloat162float(h2));
        L1.y = __float2bfloat16_rn(v3 - __bfloat162float(h3));
        *(__nv_bfloat162*)(outL + tok0 * DIM + col) = L0;
        *(__nv_bfloat162*)(outL + tok1 * DIM + col) = L1;
    }
}

// ---------------- residual + LayerNorm; also emits x1 hi/lo planes ----------
__global__ void __launch_bounds__(256) ln_res_kernel(
    const float* __restrict__ a, const float* __restrict__ b,
    const float* __restrict__ g, const float* __restrict__ bt,
    float* __restrict__ out,
    __nv_bfloat16* __restrict__ outH, __nv_bfloat16* __restrict__ outL)
{
    long t  = blockIdx.x;
    int tid = threadIdx.x;
    float4 va = ((const float4*)(a + t * DIM))[tid];
    float4 vb = ((const float4*)(b + t * DIM))[tid];
    float v[4] = { va.x + vb.x, va.y + vb.y, va.z + vb.z, va.w + vb.w };
    float s1 = v[0] + v[1] + v[2] + v[3];
    float s2 = v[0]*v[0] + v[1]*v[1] + v[2]*v[2] + v[3]*v[3];
    #pragma unroll
    for (int o2 = 16; o2 >= 1; o2 >>= 1) {
        s1 += __shfl_xor_sync(0xffffffffu, s1, o2);
        s2 += __shfl_xor_sync(0xffffffffu, s2, o2);
    }
    __shared__ float r1[8], r2[8], mv[2];
    if ((tid & 31) == 0) { r1[tid >> 5] = s1; r2[tid >> 5] = s2; }
    __syncthreads();
    if (tid == 0) {
        float A = 0.f, Bq = 0.f;
        #pragma unroll
        for (int w = 0; w < 8; w++) { A += r1[w]; Bq += r2[w]; }
        float mean = A * (1.f / DIM);
        float var  = Bq * (1.f / DIM) - mean * mean;
        mv[0] = mean; mv[1] = rsqrtf(var + 1e-5f);
    }
    __syncthreads();
    float mean = mv[0], rstd = mv[1];
    float4 gg  = ((const float4*)g)[tid];
    float4 bbv = ((const float4*)bt)[tid];
    float4 ov;
    ov.x = (v[0] - mean) * rstd * gg.x + bbv.x;
    ov.y = (v[1] - mean) * rstd * gg.y + bbv.y;
    ov.z = (v[2] - mean) * rstd * gg.z + bbv.z;
    ov.w = (v[3] - mean) * rstd * gg.w + bbv.w;
    ((float4*)(out + t * DIM))[tid] = ov;

    __nv_bfloat16 h0 = __float2bfloat16_rn(ov.x), h1 = __float2bfloat16_rn(ov.y);
    __nv_bfloat16 h2 = __float2bfloat16_rn(ov.z), h3 = __float2bfloat16_rn(ov.w);
    __nv_bfloat162 H0; H0.x = h0; H0.y = h1;
    __nv_bfloat162 H1; H1.x = h2; H1.y = h3;
    __nv_bfloat162 L0, L1;
    L0.x = __float2bfloat16_rn(ov.x - __bfloat162float(h0));
    L0.y = __float2bfloat16_rn(ov.y - __bfloat162float(h1));
    L1.x = __float2bfloat16_rn(ov.z - __bfloat162float(h2));
    L1.y = __float2bfloat16_rn(ov.w - __bfloat162float(h3));
    ((__nv_bfloat162*)(outH + t * DIM))[2 * tid]     = H0;
    ((__nv_bfloat162*)(outH + t * DIM))[2 * tid + 1] = H1;
    ((__nv_bfloat162*)(outL + t * DIM))[2 * tid]     = L0;
    ((__nv_bfloat162*)(outL + t * DIM))[2 * tid + 1] = L1;
}

// ---------------- combine MoE slots + residual + LN2 -> d_out ----------------
__global__ void __launch_bounds__(256) ln2_kernel(
    const float* __restrict__ x1, const float* __restrict__ moe2,
    const float* __restrict__ g, const float* __restrict__ bt,
    float* __restrict__ out)
{
    long t  = blockIdx.x;
    int tid = threadIdx.x;
    float4 va = ((const float4*)(x1   + t * DIM))[tid];
    float4 vb = ((const float4*)(moe2 + (2 * t)     * DIM))[tid];
    float4 vc = ((const float4*)(moe2 + (2 * t + 1) * DIM))[tid];
    float v[4] = { va.x + vb.x + vc.x, va.y + vb.y + vc.y,
                   va.z + vb.z + vc.z, va.w + vb.w + vc.w };
    float s1 = v[0] + v[1] + v[2] + v[3];
    float s2 = v[0]*v[0] + v[1]*v[1] + v[2]*v[2] + v[3]*v[3];
    #pragma unroll
    for (int o2 = 16; o2 >= 1; o2 >>= 1) {
        s1 += __shfl_xor_sync(0xffffffffu, s1, o2);
        s2 += __shfl_xor_sync(0xffffffffu, s2, o2);
    }
    __shared__ float r1[8], r2[8], mv[2];
    if ((tid & 31) == 0) { r1[tid >> 5] = s1; r2[tid >> 5] = s2; }
    __syncthreads();
    if (tid == 0) {
        float A = 0.f, Bq = 0.f;
        #pragma unroll
        for (int w = 0; w < 8; w++) { A += r1[w]; Bq += r2[w]; }
        float mean = A * (1.f / DIM);
        float var  = Bq * (1.f / DIM) - mean * mean;
        mv[0] = mean; mv[1] = rsqrtf(var + 1e-5f);
    }
    __syncthreads();
    float mean = mv[0], rstd = mv[1];
    float4 gg  = ((const float4*)g)[tid];
    float4 bbv = ((const float4*)bt)[tid];
    float4 ov;
    ov.x = (v[0] - mean) * rstd * gg.x + bbv.x;
    ov.y = (v[1] - mean) * rstd * gg.y + bbv.y;
    ov.z = (v[2] - mean) * rstd * gg.z + bbv.z;
    ov.w = (v[3] - mean) * rstd * gg.w + bbv.w;
    ((float4*)(out + t * DIM))[tid] = ov;
}

// ---------------- gate: logits, softmax usage, top-2 -------------------------
__global__ void __launch_bounds__(256) gate_kernel(
    const float* __restrict__ x, const float* __restrict__ gw,
    const float* __restrict__ gb)
{
    int t = blockIdx.x;
    int w = threadIdx.x >> 5, lane = threadIdx.x & 31;
    const float* xr = x + (long)t * DIM;
    const float* wr = gw + w * DIM;
    float s = 0.f;
    for (int d = lane; d < DIM; d += 32) s += xr[d] * wr[d];
    #pragma unroll
    for (int o2 = 16; o2 >= 1; o2 >>= 1) s += __shfl_xor_sync(0xffffffffu, s, o2);
    __shared__ float lg[NEXP];
    if (lane == 0) lg[w] = s + gb[w];
    __syncthreads();
    if (threadIdx.x == 0) {
        float mx = lg[0];
        #pragma unroll
        for (int e = 1; e < NEXP; e++) mx = fmaxf(mx, lg[e]);
        float ex[NEXP], sum = 0.f;
        #pragma unroll
        for (int e = 0; e < NEXP; e++) { ex[e] = expf(lg[e] - mx); sum += ex[e]; }
        float inv = 1.f / sum;
        #pragma unroll
        for (int e = 0; e < NEXP; e++) atomicAdd(&g_usage[e], ex[e] * inv);
        int e0 = 0;
        #pragma unroll
        for (int e = 1; e < NEXP; e++) if (lg[e] > lg[e0]) e0 = e;
        int e1 = -1;
        #pragma unroll
        for (int e = 0; e < NEXP; e++)
            if (e != e0 && (e1 < 0 || lg[e] > lg[e1])) e1 = e;
        float z  = expf(lg[e1] - lg[e0]);
        float p0 = 1.f / (1.f + z);
        g_tidx[2 * t]     = e0;  g_tidx[2 * t + 1]  = e1;
        g_tprob[2 * t]    = p0;  g_tprob[2 * t + 1] = z * p0;
        atomicAdd(&g_count[e0], 1);
        atomicAdd(&g_count[e1], 1);
    }
}

__global__ void k_offsets() {
    if (threadIdx.x == 0) {
        int a = 0;
        for (int e = 0; e < NEXP; e++) { g_off[e] = a; a += g_count[e]; }
    }
}

__global__ void k_fill() {
    int t = blockIdx.x * blockDim.x + threadIdx.x;
    if (t < TOK) {
        #pragma unroll
        for (int k = 0; k < 2; k++) {
            int e   = g_tidx[2 * t + k];
            int pos = atomicAdd(&g_fill[e], 1);
            g_list[g_off[e] + pos] = 2 * t + k;
        }
    }
}

__global__ void k_aux(float* out) {
    float s = 0.f;
    #pragma unroll
    for (int e = 0; e < NEXP; e++) {
        float u = g_usage[e] * (1.f / TOK);
        s += u * u;
    }
    out[(size_t)TOK * DIM] = (float)NEXP * s;
}

// ---------------- launch ----------------
extern "C" void kernel_launch(void* const* d_in, const int* in_sizes, int n_in,
                              void* d_out, int out_size)
{
    (void)in_sizes; (void)n_in;
    const float* src  = (const float*)d_in[0];
    const float* ipw  = (const float*)d_in[1];
    const float* ipb  = (const float*)d_in[2];
    const float* outw = (const float*)d_in[3];
    const float* outb = (const float*)d_in[4];
    const float* gw   = (const float*)d_in[5];
    const float* gb   = (const float*)d_in[6];
    const float* w1   = (const float*)d_in[7];
    const float* b1   = (const float*)d_in[8];
    const float* w2   = (const float*)d_in[9];
    const float* b2   = (const float*)d_in[10];
    const float* ln1g = (const float*)d_in[11];
    const float* ln1b = (const float*)d_in[12];
    const float* ln2g = (const float*)d_in[13];
    const float* ln2b = (const float*)d_in[14];
    float* out = (float*)d_out;

    float *p_proj, *p_x1, *p_moe2;
    cudaGetSymbolAddress((void**)&p_proj, g_proj);
    cudaGetSymbolAddress((void**)&p_x1,   g_x1);
    cudaGetSymbolAddress((void**)&p_moe2, g_moe2);
    __nv_bfloat16 *qkvH, *qkvL, *srcH, *srcL, *attnH, *attnL, *x1H, *x1L, *hH, *hL;
    __nv_bfloat16 *ipwH, *ipwL, *outwH, *outwL, *w1H, *w1L, *w2H, *w2L;
    cudaGetSymbolAddress((void**)&qkvH,  g_qkvH);
    cudaGetSymbolAddress((void**)&qkvL,  g_qkvL);
    cudaGetSymbolAddress((void**)&srcH,  g_srcH);
    cudaGetSymbolAddress((void**)&srcL,  g_srcL);
    cudaGetSymbolAddress((void**)&attnH, g_attnH);
    cudaGetSymbolAddress((void**)&attnL, g_attnL);
    cudaGetSymbolAddress((void**)&x1H,   g_x1H);
    cudaGetSymbolAddress((void**)&x1L,   g_x1L);
    cudaGetSymbolAddress((void**)&hH,    g_hH);
    cudaGetSymbolAddress((void**)&hL,    g_hL);
    cudaGetSymbolAddress((void**)&ipwH,  g_ipwH);
    cudaGetSymbolAddress((void**)&ipwL,  g_ipwL);
    cudaGetSymbolAddress((void**)&outwH, g_outwH);
    cudaGetSymbolAddress((void**)&outwL, g_outwL);
    cudaGetSymbolAddress((void**)&w1H,   g_w1H);
    cudaGetSymbolAddress((void**)&w1L,   g_w1L);
    cudaGetSymbolAddress((void**)&w2H,   g_w2H);
    cudaGetSymbolAddress((void**)&w2L,   g_w2L);

    cudaFuncSetAttribute(attn_mma,
                         cudaFuncAttributeMaxDynamicSharedMemorySize, AT_SMEM);
    cudaFuncSetAttribute(mma_gemm<0>,
                         cudaFuncAttributeMaxDynamicSharedMemorySize, SM_TOTAL);
    cudaFuncSetAttribute(mma_gemm<1>,
                         cudaFuncAttributeMaxDynamicSharedMemorySize, SM_TOTAL);
    cudaFuncSetAttribute(mma_gemm<2>,
                         cudaFuncAttributeMaxDynamicSharedMemorySize, SM_TOTAL);
    cudaFuncSetAttribute(mma_gemm<3>,
                         cudaFuncAttributeMaxDynamicSharedMemorySize, SM_TOTAL);

    // 1) per-replay init
    k_init<<<1, 32>>>();
    // 2-4) conversions needed before QKV + expert GEMM1
    {
        long n;
        n = (long)TOK * DIM / 4;
        k_conv<<<(int)((n + 255) / 256), 256>>>(src, srcH, srcL, n);
        n = (long)QKVD * DIM / 4;
        k_conv<<<(int)((n + 255) / 256), 256>>>(ipw, ipwH, ipwL, n);
        n = (long)NEXP * FDIM * DIM / 4;
        k_conv<<<(int)((n + 255) / 256), 256>>>(w1, w1H, w1L, n);
    }

    // 5) QKV projection -> hi/lo planes, Q columns pre-scaled by 1/8
    mma_gemm<3><<<dim3(QKVD / 128, TOK / 128, 1), 256, SM_TOTAL>>>(
        srcH, srcL, ipwH, ipwL, ipb, 0, qkvH, qkvL, TOK, QKVD, DIM, 0, 0);

    // 6) tensor-core flash attention -> attn hi/lo planes
    attn_mma<<<dim3(SS / 128, BB * NHEAD), 256, AT_SMEM>>>(qkvH, qkvL, attnH, attnL);

    // 7-8) remaining weight conversions (first consumers are steps 10/14)
    {
        long n = (long)DIM * DIM / 4;
        k_conv<<<(int)((n + 255) / 256), 256>>>(outw, outwH, outwL, n);
        n = (long)NEXP * DIM * FDIM / 4;
        k_conv<<<(int)((n + 255) / 256), 256>>>(w2, w2H, w2L, n);
    }

    // 9) output projection (fp32 out for LN)
    mma_gemm<0><<<dim3(DIM / 128, TOK / 128, 1), 256, SM_TOTAL>>>(
        attnH, attnL, outwH, outwL, outb, p_proj, 0, 0, TOK, DIM, DIM, 0, 0);

    // 10) x1 = LN(src + attn_out); also emit x1 planes
    ln_res_kernel<<<TOK, 256>>>(p_proj, src, ln1g, ln1b, p_x1, x1H, x1L);

    // 11) gating
    gate_kernel<<<TOK, 256>>>(p_x1, gw, gb);
    k_offsets<<<1, 32>>>();
    k_fill<<<TOK / 256, 256>>>();

    // 12) expert GEMM1 (split-2): h = gelu(x1 @ w1[e]^T + b1[e]) -> planes
    mma_gemm<1><<<dim3(FDIM / 128, TOK / 128, NEXP), 256, SM_TOTAL>>>(
        x1H, x1L, w1H, w1L, b1, 0, hH, hL,
        TOK, FDIM, DIM, (long)FDIM * DIM, FDIM);

    // 13) expert GEMM2: eo = (h @ w2[e]^T + b2[e]) * prob -> fp32 scatter
    mma_gemm<2><<<dim3(DIM / 128, TOK / 128, NEXP), 256, SM_TOTAL>>>(
        hH, hL, w2H, w2L, b2, p_moe2, 0, 0,
        TOK, DIM, FDIM, (long)DIM * FDIM, DIM);

    // 14) out = LN(x1 + moe_out)
    ln2_kernel<<<TOK, 256>>>(p_x1, p_moe2, ln2g, ln2b, out);

    // 15) aux loss
    if (out_size > TOK * DIM) k_aux<<<1, 1>>>(out);
}

// round 16
// speedup vs baseline: 1.2594x; 1.0787x over previous
#include <cuda_runtime.h>
#include <cuda_bf16.h>
#include <math.h>
#include <stdint.h>

// ---------------- problem constants ----------------
#define BB    2
#define SS    1024
#define TOK   2048          // B*S
#define DIM   1024
#define QKVD  3072
#define NHEAD 16
#define HDIM  64
#define NEXP  8
#define FDIM  4096
#define NSLOT 4096          // TOK * top_k

// ---------------- device scratch (no allocs allowed) ----------------
__device__ __align__(128) float g_proj[(size_t)TOK * DIM];
__device__ __align__(128) float g_x1  [(size_t)TOK * DIM];
__device__ __align__(128) float g_moe2[(size_t)NSLOT * DIM];

// hi/lo bf16 operand planes
__device__ __align__(128) __nv_bfloat16 g_qkvH [(size_t)TOK * QKVD];
__device__ __align__(128) __nv_bfloat16 g_srcH [(size_t)TOK * DIM];
__device__ __align__(128) __nv_bfloat16 g_srcL [(size_t)TOK * DIM];
__device__ __align__(128) __nv_bfloat16 g_attnH[(size_t)TOK * DIM];
__device__ __align__(128) __nv_bfloat16 g_attnL[(size_t)TOK * DIM];
__device__ __align__(128) __nv_bfloat16 g_x1H  [(size_t)TOK * DIM];
__device__ __align__(128) __nv_bfloat16 g_x1L  [(size_t)TOK * DIM];
__device__ __align__(128) __nv_bfloat16 g_hH   [(size_t)NSLOT * FDIM];
__device__ __align__(128) __nv_bfloat16 g_hL   [(size_t)NSLOT * FDIM];
__device__ __align__(128) __nv_bfloat16 g_ipwH [(size_t)QKVD * DIM];
__device__ __align__(128) __nv_bfloat16 g_ipwL [(size_t)QKVD * DIM];
__device__ __align__(128) __nv_bfloat16 g_outwH[(size_t)DIM * DIM];
__device__ __align__(128) __nv_bfloat16 g_outwL[(size_t)DIM * DIM];
__device__ __align__(128) __nv_bfloat16 g_w1H  [(size_t)NEXP * FDIM * DIM];
__device__ __align__(128) __nv_bfloat16 g_w1L  [(size_t)NEXP * FDIM * DIM];
__device__ __align__(128) __nv_bfloat16 g_w2H  [(size_t)NEXP * DIM * FDIM];
__device__ __align__(128) __nv_bfloat16 g_w2L  [(size_t)NEXP * DIM * FDIM];

__device__ int   g_tidx[NSLOT];
__device__ float g_tprob[NSLOT];
__device__ float g_usage[NEXP];
__device__ int   g_count[NEXP];
__device__ int   g_off[NEXP];
__device__ int   g_fill[NEXP];
__device__ int   g_list[NSLOT];

__device__ __forceinline__ float gelu_f(float x) {
    return 0.5f * x * (1.0f + erff(x * 0.70710678118654752f));
}

// ---------------- PTX helpers (all compute_103-legal) ----------------
__device__ __forceinline__ uint32_t smem_u32(const void* p) {
    uint32_t a;
    asm("{ .reg .u64 t; cvta.to.shared.u64 t, %1; cvt.u32.u64 %0, t; }"
        : "=r"(a) : "l"(p));
    return a;
}

#define CP16(dst, src) \
    asm volatile("cp.async.cg.shared.global [%0], [%1], 16;" \
                 :: "r"(dst), "l"(src) : "memory")
#define CPCOMMIT()  asm volatile("cp.async.commit_group;" ::: "memory")
#define CPWAIT0()   asm volatile("cp.async.wait_group 0;" ::: "memory")

#define LDSM4(R, addr) \
    asm volatile("ldmatrix.sync.aligned.m8n8.x4.shared.b16 {%0,%1,%2,%3}, [%4];" \
        : "=r"((R)[0]), "=r"((R)[1]), "=r"((R)[2]), "=r"((R)[3]) : "r"(addr))
#define LDSM4T(R, addr) \
    asm volatile("ldmatrix.sync.aligned.m8n8.x4.trans.shared.b16 {%0,%1,%2,%3}, [%4];" \
        : "=r"((R)[0]), "=r"((R)[1]), "=r"((R)[2]), "=r"((R)[3]) : "r"(addr))

__device__ __forceinline__ void mma16816(float* c, const uint32_t* a,
                                         uint32_t b0, uint32_t b1) {
    asm volatile(
        "mma.sync.aligned.m16n8k16.row.col.f32.bf16.bf16.f32 "
        "{%0,%1,%2,%3}, {%4,%5,%6,%7}, {%8,%9}, {%0,%1,%2,%3};"
        : "+f"(c[0]), "+f"(c[1]), "+f"(c[2]), "+f"(c[3])
        : "r"(a[0]), "r"(a[1]), "r"(a[2]), "r"(a[3]), "r"(b0), "r"(b1));
}

__device__ __forceinline__ uint32_t packbf(float a, float b) {
    __nv_bfloat162 t;
    t.x = __float2bfloat16_rn(a);
    t.y = __float2bfloat16_rn(b);
    return *(uint32_t*)&t;
}

// ---------------- init (re-zero per replay) ----------------
__global__ void k_init() {
    int i = threadIdx.x;
    if (i < NEXP) { g_usage[i] = 0.f; g_count[i] = 0; g_fill[i] = 0; }
}

// ---------------- fp32 -> (hi, lo) bf16 planes ----------------
__global__ void __launch_bounds__(256) k_conv(
    const float* __restrict__ x, __nv_bfloat16* __restrict__ hi,
    __nv_bfloat16* __restrict__ lo, long n4)
{
    long i = (long)blockIdx.x * blockDim.x + threadIdx.x;
    if (i >= n4) return;
    float4 v = ((const float4*)x)[i];
    __nv_bfloat16 h0 = __float2bfloat16_rn(v.x);
    __nv_bfloat16 h1 = __float2bfloat16_rn(v.y);
    __nv_bfloat16 h2 = __float2bfloat16_rn(v.z);
    __nv_bfloat16 h3 = __float2bfloat16_rn(v.w);
    __nv_bfloat162 H0; H0.x = h0; H0.y = h1;
    __nv_bfloat162 H1; H1.x = h2; H1.y = h3;
    __nv_bfloat162 L0, L1;
    L0.x = __float2bfloat16_rn(v.x - __bfloat162float(h0));
    L0.y = __float2bfloat16_rn(v.y - __bfloat162float(h1));
    L1.x = __float2bfloat16_rn(v.z - __bfloat162float(h2));
    L1.y = __float2bfloat16_rn(v.w - __bfloat162float(h3));
    ((__nv_bfloat162*)hi)[2 * i]     = H0;
    ((__nv_bfloat162*)hi)[2 * i + 1] = H1;
    ((__nv_bfloat162*)lo)[2 * i]     = L0;
    ((__nv_bfloat162*)lo)[2 * i + 1] = L1;
}

// =====================================================================
// bf16-split NT GEMM via mma.sync (R9 champion pipeline):
//   tile 128x128x32, 8 warps (2m x 4n), hi/lo planes,
//   2-stage cp.async double buffer, ONE __syncthreads per K-chunk.
// Numerics per mode (error budget anchored on R7/R14 measurements):
//   MODE 2 (GEMM2): split-3 (hh + hl + lh)  — h-lo error would cost ~5e-4
//   MODE 0/1/3:     split-2 (hh + hl)       — A-lo errors attenuate to
//     ~3e-5 (MODE 0/3: attention-path shield, attn/src ~ 0.014) or were
//     already measured acceptable (MODE 1 at 5.8e-4 total in R14).
// MODE 0: out-proj, C fp32 = acc + bias
// MODE 1: A rows gathered via g_list; gelu(acc+bias) -> hi/lo planes
// MODE 2: A rows = g_off[e]+m; (acc+bias)*prob -> fp32 scatter
// MODE 3: QKV; (acc+bias) [cols<DIM scaled 1/8] -> H plane ONLY
// =====================================================================
#define TSB   80            // smem row stride bytes (64 data + 16 pad)
#define PL    10240         // one plane: 128 rows * 80B
#define BUFB  40960         // 4 planes (Ahi, Alo, Bhi, Blo)
#define SM_BIAS  81920      // after 2 buffers (82KB keeps 2 CTAs/SM)
#define SM_TOTAL (SM_BIAS + 512)

template<int MODE>
__global__ void __launch_bounds__(256)
mma_gemm(const __nv_bfloat16* __restrict__ Ah, const __nv_bfloat16* __restrict__ Al,
         const __nv_bfloat16* __restrict__ Bh, const __nv_bfloat16* __restrict__ Bl,
         const float* __restrict__ bias,
         float* __restrict__ Cf,
         __nv_bfloat16* __restrict__ ChH, __nv_bfloat16* __restrict__ ChL,
         int M, int N, int K, long strideBe, int strideBiasE)
{
    constexpr bool SPLIT3 = (MODE == 2);
    extern __shared__ char smem[];
    const uint32_t sb = smem_u32(smem);

    int tid  = threadIdx.x;
    int wid  = tid >> 5, lane = tid & 31;
    int mBase = blockIdx.y * 128;
    int nBase = blockIdx.x * 128;

    int count = M, off = 0;
    const int* lst = 0;
    if (MODE == 1 || MODE == 2) {
        int e = blockIdx.z;
        count = g_count[e];
        if (mBase >= count) return;
        off  = g_off[e];
        Bh  += (long)e * strideBe;
        Bl  += (long)e * strideBe;
        bias += (long)e * strideBiasE;
        lst  = g_list + off;
    }

    if (tid < 128) *(float*)(smem + SM_BIAS + tid * 4) = bias[nBase + tid];

    // ---- cp.async source setup: thread -> (row r, 32B half hf)
    int r  = tid >> 1;
    int hf = tid & 1;
    long aRow;
    {
        int mIdxL = mBase + r;
        if (MODE == 0 || MODE == 3) aRow = mIdxL;
        else if (MODE == 1) aRow = (long)(lst[min(mIdxL, count - 1)] >> 1);
        else                aRow = (long)off + min(mIdxL, count - 1);
    }
    const char* aH = (const char*)(Ah + aRow * (long)K) + hf * 32;
    const char* aL = (const char*)(Al + aRow * (long)K) + hf * 32;
    const char* bH = (const char*)(Bh + (long)(nBase + r) * K) + hf * 32;
    const char* bL = (const char*)(Bl + (long)(nBase + r) * K) + hf * 32;
    uint32_t d0 = sb + (uint32_t)(r * TSB + hf * 32);

    const int NC = K >> 5;   // 32-K chunks

    auto stage_chunk = [&](int cc) {
        long ob = (long)cc * 64;     // 32 bf16 = 64 bytes
        uint32_t db = d0 + (uint32_t)((cc & 1) * BUFB);
        CP16(db,              aH + ob);  CP16(db + 16,              aH + ob + 16);
        if (SPLIT3) {
            CP16(db + PL,     aL + ob);  CP16(db + PL + 16,         aL + ob + 16);
        }
        CP16(db + 2 * PL,     bH + ob);  CP16(db + 2 * PL + 16,     bH + ob + 16);
        CP16(db + 3 * PL,     bL + ob);  CP16(db + 3 * PL + 16,     bL + ob + 16);
        CPCOMMIT();
    };

    // prologue: stage chunk 0
    stage_chunk(0);

    // warp compute setup
    int wm = wid >> 2;           // 0..1  (m half)
    int wn = wid & 3;            // 0..3  (n quarter)
    uint32_t laneoff = (uint32_t)((lane & 15) * TSB + (lane >> 4) * 16);
    uint32_t aBaseOff = (uint32_t)(wm * 64 * TSB) + laneoff;
    uint32_t bBaseOff = (uint32_t)(2 * PL + wn * 32 * TSB) + laneoff;

    float acc[4][4][4];
    #pragma unroll
    for (int i = 0; i < 4; i++)
        #pragma unroll
        for (int j = 0; j < 4; j++)
            #pragma unroll
            for (int q = 0; q < 4; q++) acc[i][j][q] = 0.f;

    // mainloop: wait(chunk c) -> sync -> prefetch(c+1) -> compute(c)
    for (int c = 0; c < NC; c++) {
        CPWAIT0();
        __syncthreads();
        if (c + 1 < NC) stage_chunk(c + 1);

        uint32_t base = sb + (uint32_t)((c & 1) * BUFB);
        #pragma unroll
        for (int ks = 0; ks < 2; ks++) {
            uint32_t ah[4][4], al[4][4], bh[2][4], bl[2][4];
            #pragma unroll
            for (int mi = 0; mi < 4; mi++) {
                uint32_t ad = base + aBaseOff + mi * (16 * TSB) + ks * 32;
                LDSM4(ah[mi], ad);
                if (SPLIT3) LDSM4(al[mi], ad + PL);
            }
            #pragma unroll
            for (int np = 0; np < 2; np++) {
                uint32_t bd = base + bBaseOff + np * (16 * TSB) + ks * 32;
                LDSM4(bh[np], bd);
                LDSM4(bl[np], bd + PL);
            }
            #pragma unroll
            for (int mi = 0; mi < 4; mi++)
                #pragma unroll
                for (int nj = 0; nj < 4; nj++) {
                    int np = nj >> 1, s = nj & 1;
                    mma16816(acc[mi][nj], ah[mi], bh[np][s], bh[np][s + 2]);
                }
            #pragma unroll
            for (int mi = 0; mi < 4; mi++)
                #pragma unroll
                for (int nj = 0; nj < 4; nj++) {
                    int np = nj >> 1, s = nj & 1;
                    mma16816(acc[mi][nj], ah[mi], bl[np][s], bl[np][s + 2]);
                }
            if (SPLIT3) {
                #pragma unroll
                for (int mi = 0; mi < 4; mi++)
                    #pragma unroll
                    for (int nj = 0; nj < 4; nj++) {
                        int np = nj >> 1, s = nj & 1;
                        mma16816(acc[mi][nj], al[mi], bh[np][s], bh[np][s + 2]);
                    }
            }
        }
    }

    // ---- epilogue (regs only; bias smem ordered by first loop sync)
    int g  = lane >> 2;
    int tg = lane & 3;
    const float* sbias = (const float*)(smem + SM_BIAS);
    float qs = 1.f;
    if (MODE == 3) qs = (nBase < DIM) ? 0.125f : 1.f;   // pre-scale Q by 1/sqrt(HD)

    #pragma unroll
    for (int mi = 0; mi < 4; mi++) {
        #pragma unroll
        for (int hrow = 0; hrow < 2; hrow++) {
            int rm = wm * 64 + mi * 16 + g + hrow * 8;  // row in tile
            int m  = mBase + rm;
            if ((MODE == 1 || MODE == 2) && m >= count) continue;
            long cRow; float scl = 1.f;
            if (MODE == 0 || MODE == 3) cRow = m;
            else if (MODE == 1)         cRow = (long)off + m;
            else { int slot = lst[m]; cRow = slot; scl = g_tprob[slot]; }
            #pragma unroll
            for (int nj = 0; nj < 4; nj++) {
                int col = wn * 32 + nj * 8 + tg * 2;
                float vx = acc[mi][nj][hrow * 2]     + sbias[col];
                float vy = acc[mi][nj][hrow * 2 + 1] + sbias[col + 1];
                if (MODE == 1) { vx = gelu_f(vx); vy = gelu_f(vy); }
                if (MODE == 3) { vx *= qs; vy *= qs; }
                long idx = cRow * (long)N + nBase + col;
                if (MODE == 1) {
                    __nv_bfloat16 hx = __float2bfloat16_rn(vx);
                    __nv_bfloat16 hy = __float2bfloat16_rn(vy);
                    __nv_bfloat162 H; H.x = hx; H.y = hy;
                    __nv_bfloat162 L;
                    L.x = __float2bfloat16_rn(vx - __bfloat162float(hx));
                    L.y = __float2bfloat16_rn(vy - __bfloat162float(hy));
                    *(__nv_bfloat162*)(ChH + idx) = H;
                    *(__nv_bfloat162*)(ChL + idx) = L;
                } else if (MODE == 3) {
                    __nv_bfloat162 H;
                    H.x = __float2bfloat16_rn(vx);
                    H.y = __float2bfloat16_rn(vy);
                    *(__nv_bfloat162*)(ChH + idx) = H;   // H plane only
                } else {
                    float2 v; v.x = vx * scl; v.y = vy * scl;
                    *(float2*)(Cf + cRow * (long)N + nBase + col) = v;
                }
            }
        }
    }
}

// =====================================================================
// FA2-style mma attention: 128 q-rows/CTA, 8 warps x m16, K-tile 64.
// Q/K/V all single-bf16 (H plane); per R7 measurement each such operand
// contributes ~2.5e-5 end-to-end (attn/src magnitude shield).
// P still split hi/lo (softmax values, direct path).
// =====================================================================
#define AT_STRIDE 144                    // 64 bf16 cols + 16B pad
#define AT_KVB    18432                  // Kh(9216) + Vh(9216) per buffer
#define AT_KH(b)  ((b) * AT_KVB)
#define AT_VH(b)  ((b) * AT_KVB + 9216)
#define AT_QH     36864
#define AT_SMEM   55296

__global__ void __launch_bounds__(256) attn_mma(
    const __nv_bfloat16* __restrict__ qkvH,
    __nv_bfloat16* __restrict__ outH, __nv_bfloat16* __restrict__ outL)
{
    extern __shared__ char smem[];
    const uint32_t sb = smem_u32(smem);
    int tid = threadIdx.x, wid = tid >> 5, lane = tid & 31;
    int bh = blockIdx.y;
    int b  = bh >> 4, h = bh & 15;
    int q0 = blockIdx.x * 128;

    const char* Hb = (const char*)qkvH;
    const long ROWB = (long)QKVD * 2;            // bytes per token row
    const long tokB = (long)b * SS;

    auto stage_kv = [&](int tile) {
        #pragma unroll
        for (int u = 0; u < 2; u++) {
            int id = tid + u * 256;
            int row = id >> 3, ch = id & 7;
            long ko = (tokB + tile * 64 + row) * ROWB + (long)(DIM     + h * 64) * 2 + ch * 16;
            long vo = (tokB + tile * 64 + row) * ROWB + (long)(2 * DIM + h * 64) * 2 + ch * 16;
            CP16(sb + AT_KH(tile & 1) + row * AT_STRIDE + ch * 16, Hb + ko);
            CP16(sb + AT_VH(tile & 1) + row * AT_STRIDE + ch * 16, Hb + vo);
        }
        CPCOMMIT();
    };

    // ---- stage Q (H plane) + K/V tile 0
    #pragma unroll
    for (int u = 0; u < 4; u++) {
        int id = tid + u * 256;                  // 0..1023
        int row = id >> 3, ch = id & 7;
        long so = (tokB + q0 + row) * ROWB + (long)(h * 64) * 2 + ch * 16;
        CP16(sb + AT_QH + row * AT_STRIDE + ch * 16, Hb + so);
    }
    stage_kv(0);
    CPWAIT0();
    __syncthreads();

    // ---- load Q fragments once (warp owns rows wid*16 .. +15)
    uint32_t qh[4][4];
    {
        uint32_t rb = (uint32_t)((wid * 16 + (lane & 15)) * AT_STRIDE + (lane >> 4) * 16);
        #pragma unroll
        for (int ks = 0; ks < 4; ks++)
            LDSM4(qh[ks], sb + AT_QH + rb + ks * 32);
    }

    float m0 = -1e30f, m1 = -1e30f, l0 = 0.f, l1 = 0.f;
    float O[8][4];
    #pragma unroll
    for (int j = 0; j < 8; j++)
        #pragma unroll
        for (int q = 0; q < 4; q++) O[j][q] = 0.f;

    const int NT = SS / 64;   // 16 K-tiles
    for (int c = 0; c < NT; c++) {
        if (c) { CPWAIT0(); __syncthreads(); }
        if (c + 1 < NT) stage_kv(c + 1);

        // ---- scores S[m16][kk64] = Q . K^T
        float s[8][4];
        #pragma unroll
        for (int j = 0; j < 8; j++)
            #pragma unroll
            for (int q = 0; q < 4; q++) s[j][q] = 0.f;

        uint32_t kb = sb + AT_KH(c & 1) + (uint32_t)((lane & 15) * AT_STRIDE + (lane >> 4) * 16);
        #pragma unroll
        for (int ks = 0; ks < 4; ks++) {        // d chunks of 16
            uint32_t kf[4][4];
            #pragma unroll
            for (int np = 0; np < 4; np++)
                LDSM4(kf[np], kb + np * (16 * AT_STRIDE) + ks * 32);
            #pragma unroll
            for (int np = 0; np < 4; np++) {
                mma16816(s[2 * np],     qh[ks], kf[np][0], kf[np][2]);
                mma16816(s[2 * np + 1], qh[ks], kf[np][1], kf[np][3]);
            }
        }

        // ---- online softmax (2 rows/thread; quad = lanes sharing a row)
        float rm0 = -1e30f, rm1 = -1e30f;
        #pragma unroll
        for (int j = 0; j < 8; j++) {
            rm0 = fmaxf(rm0, fmaxf(s[j][0], s[j][1]));
            rm1 = fmaxf(rm1, fmaxf(s[j][2], s[j][3]));
        }
        rm0 = fmaxf(rm0, __shfl_xor_sync(0xffffffffu, rm0, 1));
        rm0 = fmaxf(rm0, __shfl_xor_sync(0xffffffffu, rm0, 2));
        rm1 = fmaxf(rm1, __shfl_xor_sync(0xffffffffu, rm1, 1));
        rm1 = fmaxf(rm1, __shfl_xor_sync(0xffffffffu, rm1, 2));
        float mn0 = fmaxf(m0, rm0), mn1 = fmaxf(m1, rm1);
        float a0 = __expf(m0 - mn0), a1 = __expf(m1 - mn1);
        m0 = mn0; m1 = mn1;
        float rs0 = 0.f, rs1 = 0.f;
        #pragma unroll
        for (int j = 0; j < 8; j++) {
            s[j][0] = __expf(s[j][0] - mn0);
            s[j][1] = __expf(s[j][1] - mn0);
            s[j][2] = __expf(s[j][2] - mn1);
            s[j][3] = __expf(s[j][3] - mn1);
            rs0 += s[j][0] + s[j][1];
            rs1 += s[j][2] + s[j][3];
        }
        rs0 += __shfl_xor_sync(0xffffffffu, rs0, 1);
        rs0 += __shfl_xor_sync(0xffffffffu, rs0, 2);
        rs1 += __shfl_xor_sync(0xffffffffu, rs1, 1);
        rs1 += __shfl_xor_sync(0xffffffffu, rs1, 2);
        l0 = l0 * a0 + rs0;
        l1 = l1 * a1 + rs1;
        #pragma unroll
        for (int j = 0; j < 8; j++) {
            O[j][0] *= a0; O[j][1] *= a0;
            O[j][2] *= a1; O[j][3] *= a1;
        }

        // ---- pack P hi/lo as A-fragments directly from score frags
        uint32_t ph[4][4], pl[4][4];
        #pragma unroll
        for (int ks = 0; ks < 4; ks++) {
            int j0 = 2 * ks, j1 = 2 * ks + 1;
            #pragma unroll
            for (int half = 0; half < 2; half++) {
                int jj = half ? j1 : j0;
                float x = s[jj][0], y = s[jj][1], z = s[jj][2], w = s[jj][3];
                __nv_bfloat16 hx = __float2bfloat16_rn(x);
                __nv_bfloat16 hy = __float2bfloat16_rn(y);
                __nv_bfloat16 hz = __float2bfloat16_rn(z);
                __nv_bfloat16 hw = __float2bfloat16_rn(w);
                __nv_bfloat162 P0; P0.x = hx; P0.y = hy;
                __nv_bfloat162 P1; P1.x = hz; P1.y = hw;
                ph[ks][2 * half]     = *(uint32_t*)&P0;
                ph[ks][2 * half + 1] = *(uint32_t*)&P1;
                pl[ks][2 * half]     = packbf(x - __bfloat162float(hx),
                                              y - __bfloat162float(hy));
                pl[ks][2 * half + 1] = packbf(z - __bfloat162float(hz),
                                              w - __bfloat162float(hw));
            }
        }

        // ---- O += P . V  (V via ldmatrix.trans)
        uint32_t vb = sb + AT_VH(c & 1) + (uint32_t)((lane & 15) * AT_STRIDE + (lane >> 4) * 16);
        #pragma unroll
        for (int ks = 0; ks < 4; ks++) {        // kk chunks of 16
            uint32_t vf[4][4];
            #pragma unroll
            for (int np = 0; np < 4; np++)
                LDSM4T(vf[np], vb + ks * (16 * AT_STRIDE) + np * 32);
            #pragma unroll
            for (int np = 0; np < 4; np++) {
                mma16816(O[2 * np],     ph[ks], vf[np][0], vf[np][1]);
                mma16816(O[2 * np + 1], ph[ks], vf[np][2], vf[np][3]);
            }
            #pragma unroll
            for (int np = 0; np < 4; np++) {
                mma16816(O[2 * np],     pl[ks], vf[np][0], vf[np][1]);
                mma16816(O[2 * np + 1], pl[ks], vf[np][2], vf[np][3]);
            }
        }
    }

    // ---- epilogue: O/l -> hi/lo planes at [tok][h*64 + d]
    float inv0 = 1.f / l0, inv1 = 1.f / l1;
    int g  = lane >> 2;
    int t2 = (lane & 3) * 2;
    long tok0 = (long)b * SS + q0 + wid * 16 + g;
    long tok1 = tok0 + 8;
    #pragma unroll
    for (int nj = 0; nj < 8; nj++) {
        int col = h * 64 + nj * 8 + t2;
        float v0 = O[nj][0] * inv0, v1 = O[nj][1] * inv0;
        float v2 = O[nj][2] * inv1, v3 = O[nj][3] * inv1;
        __nv_bfloat16 h0 = __float2bfloat16_rn(v0);
        __nv_bfloat16 h1 = __float2bfloat16_rn(v1);
        __nv_bfloat16 h2 = __float2bfloat16_rn(v2);
        __nv_bfloat16 h3 = __float2bfloat16_rn(v3);
        __nv_bfloat162 H0; H0.x = h0; H0.y = h1;
        __nv_bfloat162 H1; H1.x = h2; H1.y = h3;
        *(__nv_bfloat162*)(outH + tok0 * DIM + col) = H0;
        *(__nv_bfloat162*)(outH + tok1 * DIM + col) = H1;
        __nv_bfloat162 L0, L1;
        L0.x = __float2bfloat16_rn(v0 - __bfloat162float(h0));
        L0.y = __float2bfloat16_rn(v1 - __bfloat162float(h1));
        L1.x = __float2bfloat16_rn(v2 - __bfloat162float(h2));
        L1.y = __float2bfloat16_rn(v3 - __bfloat162float(h3));
        *(__nv_bfloat162*)(outL + tok0 * DIM + col) = L0;
        *(__nv_bfloat162*)(outL + tok1 * DIM + col) = L1;
    }
}

// ---------------- residual + LayerNorm; also emits x1 hi/lo planes ----------
__global__ void __launch_bounds__(256) ln_res_kernel(
    const float* __restrict__ a, const float* __restrict__ b,
    const float* __restrict__ g, const float* __restrict__ bt,
    float* __restrict__ out,
    __nv_bfloat16* __restrict__ outH, __nv_bfloat16* __restrict__ outL)
{
    long t  = blockIdx.x;
    int tid = threadIdx.x;
    float4 va = ((const float4*)(a + t * DIM))[tid];
    float4 vb = ((const float4*)(b + t * DIM))[tid];
    float v[4] = { va.x + vb.x, va.y + vb.y, va.z + vb.z, va.w + vb.w };
    float s1 = v[0] + v[1] + v[2] + v[3];
    float s2 = v[0]*v[0] + v[1]*v[1] + v[2]*v[2] + v[3]*v[3];
    #pragma unroll
    for (int o2 = 16; o2 >= 1; o2 >>= 1) {
        s1 += __shfl_xor_sync(0xffffffffu, s1, o2);
        s2 += __shfl_xor_sync(0xffffffffu, s2, o2);
    }
    __shared__ float r1[8], r2[8], mv[2];
    if ((tid & 31) == 0) { r1[tid >> 5] = s1; r2[tid >> 5] = s2; }
    __syncthreads();
    if (tid == 0) {
        float A = 0.f, Bq = 0.f;
        #pragma unroll
        for (int w = 0; w < 8; w++) { A += r1[w]; Bq += r2[w]; }
        float mean = A * (1.f / DIM);
        float var  = Bq * (1.f / DIM) - mean * mean;
        mv[0] = mean; mv[1] = rsqrtf(var + 1e-5f);
    }
    __syncthreads();
    float mean = mv[0], rstd = mv[1];
    float4 gg  = ((const float4*)g)[tid];
    float4 bbv = ((const float4*)bt)[tid];
    float4 ov;
    ov.x = (v[0] - mean) * rstd * gg.x + bbv.x;
    ov.y = (v[1] - mean) * rstd * gg.y + bbv.y;
    ov.z = (v[2] - mean) * rstd * gg.z + bbv.z;
    ov.w = (v[3] - mean) * rstd * gg.w + bbv.w;
    ((float4*)(out + t * DIM))[tid] = ov;

    __nv_bfloat16 h0 = __float2bfloat16_rn(ov.x), h1 = __float2bfloat16_rn(ov.y);
    __nv_bfloat16 h2 = __float2bfloat16_rn(ov.z), h3 = __float2bfloat16_rn(ov.w);
    __nv_bfloat162 H0; H0.x = h0; H0.y = h1;
    __nv_bfloat162 H1; H1.x = h2; H1.y = h3;
    __nv_bfloat162 L0, L1;
    L0.x = __float2bfloat16_rn(ov.x - __bfloat162float(h0));
    L0.y = __float2bfloat16_rn(ov.y - __bfloat162float(h1));
    L1.x = __float2bfloat16_rn(ov.z - __bfloat162float(h2));
    L1.y = __float2bfloat16_rn(ov.w - __bfloat162float(h3));
    ((__nv_bfloat162*)(outH + t * DIM))[2 * tid]     = H0;
    ((__nv_bfloat162*)(outH + t * DIM))[2 * tid + 1] = H1;
    ((__nv_bfloat162*)(outL + t * DIM))[2 * tid]     = L0;
    ((__nv_bfloat162*)(outL + t * DIM))[2 * tid + 1] = L1;
}

// ---------------- combine MoE slots + residual + LN2 -> d_out ----------------
__global__ void __launch_bounds__(256) ln2_kernel(
    const float* __restrict__ x1, const float* __restrict__ moe2,
    const float* __restrict__ g, const float* __restrict__ bt,
    float* __restrict__ out)
{
    long t  = blockIdx.x;
    int tid = threadIdx.x;
    float4 va = ((const float4*)(x1   + t * DIM))[tid];
    float4 vb = ((const float4*)(moe2 + (2 * t)     * DIM))[tid];
    float4 vc = ((const float4*)(moe2 + (2 * t + 1) * DIM))[tid];
    float v[4] = { va.x + vb.x + vc.x, va.y + vb.y + vc.y,
                   va.z + vb.z + vc.z, va.w + vb.w + vc.w };
    float s1 = v[0] + v[1] + v[2] + v[3];
    float s2 = v[0]*v[0] + v[1]*v[1] + v[2]*v[2] + v[3]*v[3];
    #pragma unroll
    for (int o2 = 16; o2 >= 1; o2 >>= 1) {
        s1 += __shfl_xor_sync(0xffffffffu, s1, o2);
        s2 += __shfl_xor_sync(0xffffffffu, s2, o2);
    }
    __shared__ float r1[8], r2[8], mv[2];
    if ((tid & 31) == 0) { r1[tid >> 5] = s1; r2[tid >> 5] = s2; }
    __syncthreads();
    if (tid == 0) {
        float A = 0.f, Bq = 0.f;
        #pragma unroll
        for (int w = 0; w < 8; w++) { A += r1[w]; Bq += r2[w]; }
        float mean = A * (1.f / DIM);
        float var  = Bq * (1.f / DIM) - mean * mean;
        mv[0] = mean; mv[1] = rsqrtf(var + 1e-5f);
    }
    __syncthreads();
    float mean = mv[0], rstd = mv[1];
    float4 gg  = ((const float4*)g)[tid];
    float4 bbv = ((const float4*)bt)[tid];
    float4 ov;
    ov.x = (v[0] - mean) * rstd * gg.x + bbv.x;
    ov.y = (v[1] - mean) * rstd * gg.y + bbv.y;
    ov.z = (v[2] - mean) * rstd * gg.z + bbv.z;
    ov.w = (v[3] - mean) * rstd * gg.w + bbv.w;
    ((float4*)(out + t * DIM))[tid] = ov;
}

// ---------------- gate: logits, softmax usage, top-2 -------------------------
__global__ void __launch_bounds__(256) gate_kernel(
    const float* __restrict__ x, const float* __restrict__ gw,
    const float* __restrict__ gb)
{
    int t = blockIdx.x;
    int w = threadIdx.x >> 5, lane = threadIdx.x & 31;
    const float* xr = x + (long)t * DIM;
    const float* wr = gw + w * DIM;
    float s = 0.f;
    for (int d = lane; d < DIM; d += 32) s += xr[d] * wr[d];
    #pragma unroll
    for (int o2 = 16; o2 >= 1; o2 >>= 1) s += __shfl_xor_sync(0xffffffffu, s, o2);
    __shared__ float lg[NEXP];
    if (lane == 0) lg[w] = s + gb[w];
    __syncthreads();
    if (threadIdx.x == 0) {
        float mx = lg[0];
        #pragma unroll
        for (int e = 1; e < NEXP; e++) mx = fmaxf(mx, lg[e]);
        float ex[NEXP], sum = 0.f;
        #pragma unroll
        for (int e = 0; e < NEXP; e++) { ex[e] = expf(lg[e] - mx); sum += ex[e]; }
        float inv = 1.f / sum;
        #pragma unroll
        for (int e = 0; e < NEXP; e++) atomicAdd(&g_usage[e], ex[e] * inv);
        int e0 = 0;
        #pragma unroll
        for (int e = 1; e < NEXP; e++) if (lg[e] > lg[e0]) e0 = e;
        int e1 = -1;
        #pragma unroll
        for (int e = 0; e < NEXP; e++)
            if (e != e0 && (e1 < 0 || lg[e] > lg[e1])) e1 = e;
        float z  = expf(lg[e1] - lg[e0]);
        float p0 = 1.f / (1.f + z);
        g_tidx[2 * t]     = e0;  g_tidx[2 * t + 1]  = e1;
        g_tprob[2 * t]    = p0;  g_tprob[2 * t + 1] = z * p0;
        atomicAdd(&g_count[e0], 1);
        atomicAdd(&g_count[e1], 1);
    }
}

__global__ void k_offsets() {
    if (threadIdx.x == 0) {
        int a = 0;
        for (int e = 0; e < NEXP; e++) { g_off[e] = a; a += g_count[e]; }
    }
}

__global__ void k_fill() {
    int t = blockIdx.x * blockDim.x + threadIdx.x;
    if (t < TOK) {
        #pragma unroll
        for (int k = 0; k < 2; k++) {
            int e   = g_tidx[2 * t + k];
            int pos = atomicAdd(&g_fill[e], 1);
            g_list[g_off[e] + pos] = 2 * t + k;
        }
    }
}

__global__ void k_aux(float* out) {
    float s = 0.f;
    #pragma unroll
    for (int e = 0; e < NEXP; e++) {
        float u = g_usage[e] * (1.f / TOK);
        s += u * u;
    }
    out[(size_t)TOK * DIM] = (float)NEXP * s;
}

// ---------------- launch ----------------
extern "C" void kernel_launch(void* const* d_in, const int* in_sizes, int n_in,
                              void* d_out, int out_size)
{
    (void)in_sizes; (void)n_in;
    const float* src  = (const float*)d_in[0];
    const float* ipw  = (const float*)d_in[1];
    const float* ipb  = (const float*)d_in[2];
    const float* outw = (const float*)d_in[3];
    const float* outb = (const float*)d_in[4];
    const float* gw   = (const float*)d_in[5];
    const float* gb   = (const float*)d_in[6];
    const float* w1   = (const float*)d_in[7];
    const float* b1   = (const float*)d_in[8];
    const float* w2   = (const float*)d_in[9];
    const float* b2   = (const float*)d_in[10];
    const float* ln1g = (const float*)d_in[11];
    const float* ln1b = (const float*)d_in[12];
    const float* ln2g = (const float*)d_in[13];
    const float* ln2b = (const float*)d_in[14];
    float* out = (float*)d_out;

    float *p_proj, *p_x1, *p_moe2;
    cudaGetSymbolAddress((void**)&p_proj, g_proj);
    cudaGetSymbolAddress((void**)&p_x1,   g_x1);
    cudaGetSymbolAddress((void**)&p_moe2, g_moe2);
    __nv_bfloat16 *qkvH, *srcH, *srcL, *attnH, *attnL, *x1H, *x1L, *hH, *hL;
    __nv_bfloat16 *ipwH, *ipwL, *outwH, *outwL, *w1H, *w1L, *w2H, *w2L;
    cudaGetSymbolAddress((void**)&qkvH,  g_qkvH);
    cudaGetSymbolAddress((void**)&srcH,  g_srcH);
    cudaGetSymbolAddress((void**)&srcL,  g_srcL);
    cudaGetSymbolAddress((void**)&attnH, g_attnH);
    cudaGetSymbolAddress((void**)&attnL, g_attnL);
    cudaGetSymbolAddress((void**)&x1H,   g_x1H);
    cudaGetSymbolAddress((void**)&x1L,   g_x1L);
    cudaGetSymbolAddress((void**)&hH,    g_hH);
    cudaGetSymbolAddress((void**)&hL,    g_hL);
    cudaGetSymbolAddress((void**)&ipwH,  g_ipwH);
    cudaGetSymbolAddress((void**)&ipwL,  g_ipwL);
    cudaGetSymbolAddress((void**)&outwH, g_outwH);
    cudaGetSymbolAddress((void**)&outwL, g_outwL);
    cudaGetSymbolAddress((void**)&w1H,   g_w1H);
    cudaGetSymbolAddress((void**)&w1L,   g_w1L);
    cudaGetSymbolAddress((void**)&w2H,   g_w2H);
    cudaGetSymbolAddress((void**)&w2L,   g_w2L);

    cudaFuncSetAttribute(attn_mma,
                         cudaFuncAttributeMaxDynamicSharedMemorySize, AT_SMEM);
    cudaFuncSetAttribute(mma_gemm<0>,
                         cudaFuncAttributeMaxDynamicSharedMemorySize, SM_TOTAL);
    cudaFuncSetAttribute(mma_gemm<1>,
                         cudaFuncAttributeMaxDynamicSharedMemorySize, SM_TOTAL);
    cudaFuncSetAttribute(mma_gemm<2>,
                         cudaFuncAttributeMaxDynamicSharedMemorySize, SM_TOTAL);
    cudaFuncSetAttribute(mma_gemm<3>,
                         cudaFuncAttributeMaxDynamicSharedMemorySize, SM_TOTAL);

    // 1) per-replay init
    k_init<<<1, 32>>>();
    // 2-4) conversions needed before QKV + expert GEMM1
    {
        long n;
        n = (long)TOK * DIM / 4;
        k_conv<<<(int)((n + 255) / 256), 256>>>(src, srcH, srcL, n);
        n = (long)QKVD * DIM / 4;
        k_conv<<<(int)((n + 255) / 256), 256>>>(ipw, ipwH, ipwL, n);
        n = (long)NEXP * FDIM * DIM / 4;
        k_conv<<<(int)((n + 255) / 256), 256>>>(w1, w1H, w1L, n);
    }

    // 5) QKV projection (split-2) -> H plane, Q cols pre-scaled 1/8
    mma_gemm<3><<<dim3(QKVD / 128, TOK / 128, 1), 256, SM_TOTAL>>>(
        srcH, srcL, ipwH, ipwL, ipb, 0, qkvH, 0, TOK, QKVD, DIM, 0, 0);

    // 6) tensor-core flash attention (Q/K/V single-bf16) -> attn planes
    attn_mma<<<dim3(SS / 128, BB * NHEAD), 256, AT_SMEM>>>(qkvH, attnH, attnL);

    // 7-8) remaining weight conversions (first consumers are steps 9/13)
    {
        long n = (long)DIM * DIM / 4;
        k_conv<<<(int)((n + 255) / 256), 256>>>(outw, outwH, outwL, n);
        n = (long)NEXP * DIM * FDIM / 4;
        k_conv<<<(int)((n + 255) / 256), 256>>>(w2, w2H, w2L, n);
    }

    // 9) output projection (split-2; fp32 out for LN)
    mma_gemm<0><<<dim3(DIM / 128, TOK / 128, 1), 256, SM_TOTAL>>>(
        attnH, attnL, outwH, outwL, outb, p_proj, 0, 0, TOK, DIM, DIM, 0, 0);

    // 10) x1 = LN(src + attn_out); also emit x1 planes
    ln_res_kernel<<<TOK, 256>>>(p_proj, src, ln1g, ln1b, p_x1, x1H, x1L);

    // 11) gating
    gate_kernel<<<TOK, 256>>>(p_x1, gw, gb);
    k_offsets<<<1, 32>>>();
    k_fill<<<TOK / 256, 256>>>();

    // 12) expert GEMM1 (split-2): h = gelu(x1 @ w1[e]^T + b1[e]) -> planes
    mma_gemm<1><<<dim3(FDIM / 128, TOK / 128, NEXP), 256, SM_TOTAL>>>(
        x1H, x1L, w1H, w1L, b1, 0, hH, hL,
        TOK, FDIM, DIM, (long)FDIM * DIM, FDIM);

    // 13) expert GEMM2 (split-3): eo = (h @ w2[e]^T + b2[e]) * prob -> fp32
    mma_gemm<2><<<dim3(DIM / 128, TOK / 128, NEXP), 256, SM_TOTAL>>>(
        hH, hL, w2H, w2L, b2, p_moe2, 0, 0,
        TOK, DIM, FDIM, (long)DIM * FDIM, DIM);

    // 14) out = LN(x1 + moe_out)
    ln2_kernel<<<TOK, 256>>>(p_x1, p_moe2, ln2g, ln2b, out);

    // 15) aux loss
    if (out_size > TOK * DIM) k_aux<<<1, 1>>>(out);
}

// round 17
// speedup vs baseline: 1.2651x; 1.0045x over previous
#include <cuda_runtime.h>
#include <cuda_bf16.h>
#include <math.h>
#include <stdint.h>

// ---------------- problem constants ----------------
#define BB    2
#define SS    1024
#define TOK   2048          // B*S
#define DIM   1024
#define QKVD  3072
#define NHEAD 16
#define HDIM  64
#define NEXP  8
#define FDIM  4096
#define NSLOT 4096          // TOK * top_k

// ---------------- device scratch (no allocs allowed) ----------------
__device__ __align__(128) float g_proj[(size_t)TOK * DIM];
__device__ __align__(128) float g_x1  [(size_t)TOK * DIM];
__device__ __align__(128) float g_moe2[(size_t)NSLOT * DIM];

// bf16 operand planes (lo planes kept only where actually consumed)
__device__ __align__(128) __nv_bfloat16 g_qkvH [(size_t)TOK * QKVD];
__device__ __align__(128) __nv_bfloat16 g_srcH [(size_t)TOK * DIM];
__device__ __align__(128) __nv_bfloat16 g_attnH[(size_t)TOK * DIM];
__device__ __align__(128) __nv_bfloat16 g_x1H  [(size_t)TOK * DIM];
__device__ __align__(128) __nv_bfloat16 g_hH   [(size_t)NSLOT * FDIM];
__device__ __align__(128) __nv_bfloat16 g_hL   [(size_t)NSLOT * FDIM];
__device__ __align__(128) __nv_bfloat16 g_ipwH [(size_t)QKVD * DIM];
__device__ __align__(128) __nv_bfloat16 g_ipwL [(size_t)QKVD * DIM];
__device__ __align__(128) __nv_bfloat16 g_outwH[(size_t)DIM * DIM];
__device__ __align__(128) __nv_bfloat16 g_outwL[(size_t)DIM * DIM];
__device__ __align__(128) __nv_bfloat16 g_w1H  [(size_t)NEXP * FDIM * DIM];
__device__ __align__(128) __nv_bfloat16 g_w1L  [(size_t)NEXP * FDIM * DIM];
__device__ __align__(128) __nv_bfloat16 g_w2H  [(size_t)NEXP * DIM * FDIM];
__device__ __align__(128) __nv_bfloat16 g_w2L  [(size_t)NEXP * DIM * FDIM];

__device__ int   g_tidx[NSLOT];
__device__ float g_tprob[NSLOT];
__device__ float g_usage[NEXP];
__device__ int   g_count[NEXP];
__device__ int   g_off[NEXP];
__device__ int   g_fill[NEXP];
__device__ int   g_list[NSLOT];

__device__ __forceinline__ float gelu_f(float x) {
    return 0.5f * x * (1.0f + erff(x * 0.70710678118654752f));
}

// ---------------- PTX helpers (all compute_103-legal) ----------------
__device__ __forceinline__ uint32_t smem_u32(const void* p) {
    uint32_t a;
    asm("{ .reg .u64 t; cvta.to.shared.u64 t, %1; cvt.u32.u64 %0, t; }"
        : "=r"(a) : "l"(p));
    return a;
}

#define CP16(dst, src) \
    asm volatile("cp.async.cg.shared.global [%0], [%1], 16;" \
                 :: "r"(dst), "l"(src) : "memory")
#define CPCOMMIT()  asm volatile("cp.async.commit_group;" ::: "memory")
#define CPWAIT0()   asm volatile("cp.async.wait_group 0;" ::: "memory")

#define LDSM4(R, addr) \
    asm volatile("ldmatrix.sync.aligned.m8n8.x4.shared.b16 {%0,%1,%2,%3}, [%4];" \
        : "=r"((R)[0]), "=r"((R)[1]), "=r"((R)[2]), "=r"((R)[3]) : "r"(addr))
#define LDSM4T(R, addr) \
    asm volatile("ldmatrix.sync.aligned.m8n8.x4.trans.shared.b16 {%0,%1,%2,%3}, [%4];" \
        : "=r"((R)[0]), "=r"((R)[1]), "=r"((R)[2]), "=r"((R)[3]) : "r"(addr))

__device__ __forceinline__ void mma16816(float* c, const uint32_t* a,
                                         uint32_t b0, uint32_t b1) {
    asm volatile(
        "mma.sync.aligned.m16n8k16.row.col.f32.bf16.bf16.f32 "
        "{%0,%1,%2,%3}, {%4,%5,%6,%7}, {%8,%9}, {%0,%1,%2,%3};"
        : "+f"(c[0]), "+f"(c[1]), "+f"(c[2]), "+f"(c[3])
        : "r"(a[0]), "r"(a[1]), "r"(a[2]), "r"(a[3]), "r"(b0), "r"(b1));
}

__device__ __forceinline__ uint32_t packbf(float a, float b) {
    __nv_bfloat162 t;
    t.x = __float2bfloat16_rn(a);
    t.y = __float2bfloat16_rn(b);
    return *(uint32_t*)&t;
}

// ---------------- init (re-zero per replay) ----------------
__global__ void k_init() {
    int i = threadIdx.x;
    if (i < NEXP) { g_usage[i] = 0.f; g_count[i] = 0; g_fill[i] = 0; }
}

// ---------------- fp32 -> (hi, lo) bf16 planes ----------------
__global__ void __launch_bounds__(256) k_conv(
    const float* __restrict__ x, __nv_bfloat16* __restrict__ hi,
    __nv_bfloat16* __restrict__ lo, long n4)
{
    long i = (long)blockIdx.x * blockDim.x + threadIdx.x;
    if (i >= n4) return;
    float4 v = ((const float4*)x)[i];
    __nv_bfloat16 h0 = __float2bfloat16_rn(v.x);
    __nv_bfloat16 h1 = __float2bfloat16_rn(v.y);
    __nv_bfloat16 h2 = __float2bfloat16_rn(v.z);
    __nv_bfloat16 h3 = __float2bfloat16_rn(v.w);
    __nv_bfloat162 H0; H0.x = h0; H0.y = h1;
    __nv_bfloat162 H1; H1.x = h2; H1.y = h3;
    __nv_bfloat162 L0, L1;
    L0.x = __float2bfloat16_rn(v.x - __bfloat162float(h0));
    L0.y = __float2bfloat16_rn(v.y - __bfloat162float(h1));
    L1.x = __float2bfloat16_rn(v.z - __bfloat162float(h2));
    L1.y = __float2bfloat16_rn(v.w - __bfloat162float(h3));
    ((__nv_bfloat162*)hi)[2 * i]     = H0;
    ((__nv_bfloat162*)hi)[2 * i + 1] = H1;
    ((__nv_bfloat162*)lo)[2 * i]     = L0;
    ((__nv_bfloat162*)lo)[2 * i + 1] = L1;
}

// fp32 -> hi plane only (for operands whose lo plane is never consumed)
__global__ void __launch_bounds__(256) k_convH(
    const float* __restrict__ x, __nv_bfloat16* __restrict__ hi, long n4)
{
    long i = (long)blockIdx.x * blockDim.x + threadIdx.x;
    if (i >= n4) return;
    float4 v = ((const float4*)x)[i];
    __nv_bfloat162 H0, H1;
    H0.x = __float2bfloat16_rn(v.x); H0.y = __float2bfloat16_rn(v.y);
    H1.x = __float2bfloat16_rn(v.z); H1.y = __float2bfloat16_rn(v.w);
    ((__nv_bfloat162*)hi)[2 * i]     = H0;
    ((__nv_bfloat162*)hi)[2 * i + 1] = H1;
}

// =====================================================================
// bf16-split NT GEMM via mma.sync (R9 champion pipeline):
//   tile 128x128x32, 8 warps (2m x 4n), hi/lo planes,
//   2-stage cp.async double buffer, ONE __syncthreads per K-chunk.
// Numerics FROZEN (validated R14/R15):
//   MODE 2 (GEMM2): split-3 (hh + hl + lh)
//   MODE 0/1/3:     split-2 (hh + hl) — A-lo never loaded
// Grid mapping: MODE 1/2 put m on blockIdx.x (fastest) so the ~4 active
// m-tiles sharing a B weight tile are launch-adjacent -> L2 reuse.
// MODE 0/3 keep n on x (B small, already L2-resident).
// MODE 0: out-proj, C fp32 = acc + bias
// MODE 1: A rows gathered via g_list; gelu(acc+bias) -> hi/lo planes
// MODE 2: A rows = g_off[e]+m; (acc+bias)*prob -> fp32 scatter
// MODE 3: QKV; (acc+bias) [cols<DIM scaled 1/8] -> H plane ONLY
// =====================================================================
#define TSB   80            // smem row stride bytes (64 data + 16 pad)
#define PL    10240         // one plane: 128 rows * 80B
#define BUFB  40960         // 4 planes (Ahi, Alo, Bhi, Blo)
#define SM_BIAS  81920      // after 2 buffers (82KB keeps 2 CTAs/SM)
#define SM_TOTAL (SM_BIAS + 512)

template<int MODE>
__global__ void __launch_bounds__(256)
mma_gemm(const __nv_bfloat16* __restrict__ Ah, const __nv_bfloat16* __restrict__ Al,
         const __nv_bfloat16* __restrict__ Bh, const __nv_bfloat16* __restrict__ Bl,
         const float* __restrict__ bias,
         float* __restrict__ Cf,
         __nv_bfloat16* __restrict__ ChH, __nv_bfloat16* __restrict__ ChL,
         int M, int N, int K, long strideBe, int strideBiasE)
{
    constexpr bool SPLIT3 = (MODE == 2);
    constexpr bool MOE    = (MODE == 1 || MODE == 2);
    extern __shared__ char smem[];
    const uint32_t sb = smem_u32(smem);

    int tid  = threadIdx.x;
    int wid  = tid >> 5, lane = tid & 31;
    // MoE GEMMs: m on x (fastest) for B-tile L2 reuse; others: n on x.
    int mBase = (MOE ? blockIdx.x : blockIdx.y) * 128;
    int nBase = (MOE ? blockIdx.y : blockIdx.x) * 128;

    int count = M, off = 0;
    const int* lst = 0;
    if (MOE) {
        int e = blockIdx.z;
        count = g_count[e];
        if (mBase >= count) return;
        off  = g_off[e];
        Bh  += (long)e * strideBe;
        Bl  += (long)e * strideBe;
        bias += (long)e * strideBiasE;
        lst  = g_list + off;
    }

    if (tid < 128) *(float*)(smem + SM_BIAS + tid * 4) = bias[nBase + tid];

    // ---- cp.async source setup: thread -> (row r, 32B half hf)
    int r  = tid >> 1;
    int hf = tid & 1;
    long aRow;
    {
        int mIdxL = mBase + r;
        if (MODE == 0 || MODE == 3) aRow = mIdxL;
        else if (MODE == 1) aRow = (long)(lst[min(mIdxL, count - 1)] >> 1);
        else                aRow = (long)off + min(mIdxL, count - 1);
    }
    const char* aH = (const char*)(Ah + aRow * (long)K) + hf * 32;
    const char* aL = (const char*)(Al + aRow * (long)K) + hf * 32;
    const char* bH = (const char*)(Bh + (long)(nBase + r) * K) + hf * 32;
    const char* bL = (const char*)(Bl + (long)(nBase + r) * K) + hf * 32;
    uint32_t d0 = sb + (uint32_t)(r * TSB + hf * 32);

    const int NC = K >> 5;   // 32-K chunks

    auto stage_chunk = [&](int cc) {
        long ob = (long)cc * 64;     // 32 bf16 = 64 bytes
        uint32_t db = d0 + (uint32_t)((cc & 1) * BUFB);
        CP16(db,              aH + ob);  CP16(db + 16,              aH + ob + 16);
        if (SPLIT3) {
            CP16(db + PL,     aL + ob);  CP16(db + PL + 16,         aL + ob + 16);
        }
        CP16(db + 2 * PL,     bH + ob);  CP16(db + 2 * PL + 16,     bH + ob + 16);
        CP16(db + 3 * PL,     bL + ob);  CP16(db + 3 * PL + 16,     bL + ob + 16);
        CPCOMMIT();
    };

    // prologue: stage chunk 0
    stage_chunk(0);

    // warp compute setup
    int wm = wid >> 2;           // 0..1  (m half)
    int wn = wid & 3;            // 0..3  (n quarter)
    uint32_t laneoff = (uint32_t)((lane & 15) * TSB + (lane >> 4) * 16);
    uint32_t aBaseOff = (uint32_t)(wm * 64 * TSB) + laneoff;
    uint32_t bBaseOff = (uint32_t)(2 * PL + wn * 32 * TSB) + laneoff;

    float acc[4][4][4];
    #pragma unroll
    for (int i = 0; i < 4; i++)
        #pragma unroll
        for (int j = 0; j < 4; j++)
            #pragma unroll
            for (int q = 0; q < 4; q++) acc[i][j][q] = 0.f;

    // mainloop: wait(chunk c) -> sync -> prefetch(c+1) -> compute(c)
    for (int c = 0; c < NC; c++) {
        CPWAIT0();
        __syncthreads();
        if (c + 1 < NC) stage_chunk(c + 1);

        uint32_t base = sb + (uint32_t)((c & 1) * BUFB);
        #pragma unroll
        for (int ks = 0; ks < 2; ks++) {
            uint32_t ah[4][4], al[4][4], bh[2][4], bl[2][4];
            #pragma unroll
            for (int mi = 0; mi < 4; mi++) {
                uint32_t ad = base + aBaseOff + mi * (16 * TSB) + ks * 32;
                LDSM4(ah[mi], ad);
                if (SPLIT3) LDSM4(al[mi], ad + PL);
            }
            #pragma unroll
            for (int np = 0; np < 2; np++) {
                uint32_t bd = base + bBaseOff + np * (16 * TSB) + ks * 32;
                LDSM4(bh[np], bd);
                LDSM4(bl[np], bd + PL);
            }
            #pragma unroll
            for (int mi = 0; mi < 4; mi++)
                #pragma unroll
                for (int nj = 0; nj < 4; nj++) {
                    int np = nj >> 1, s = nj & 1;
                    mma16816(acc[mi][nj], ah[mi], bh[np][s], bh[np][s + 2]);
                }
            #pragma unroll
            for (int mi = 0; mi < 4; mi++)
                #pragma unroll
                for (int nj = 0; nj < 4; nj++) {
                    int np = nj >> 1, s = nj & 1;
                    mma16816(acc[mi][nj], ah[mi], bl[np][s], bl[np][s + 2]);
                }
            if (SPLIT3) {
                #pragma unroll
                for (int mi = 0; mi < 4; mi++)
                    #pragma unroll
                    for (int nj = 0; nj < 4; nj++) {
                        int np = nj >> 1, s = nj & 1;
                        mma16816(acc[mi][nj], al[mi], bh[np][s], bh[np][s + 2]);
                    }
            }
        }
    }

    // ---- epilogue (regs only; bias smem ordered by first loop sync)
    int g  = lane >> 2;
    int tg = lane & 3;
    const float* sbias = (const float*)(smem + SM_BIAS);
    float qs = 1.f;
    if (MODE == 3) qs = (nBase < DIM) ? 0.125f : 1.f;   // pre-scale Q by 1/sqrt(HD)

    #pragma unroll
    for (int mi = 0; mi < 4; mi++) {
        #pragma unroll
        for (int hrow = 0; hrow < 2; hrow++) {
            int rm = wm * 64 + mi * 16 + g + hrow * 8;  // row in tile
            int m  = mBase + rm;
            if (MOE && m >= count) continue;
            long cRow; float scl = 1.f;
            if (MODE == 0 || MODE == 3) cRow = m;
            else if (MODE == 1)         cRow = (long)off + m;
            else { int slot = lst[m]; cRow = slot; scl = g_tprob[slot]; }
            #pragma unroll
            for (int nj = 0; nj < 4; nj++) {
                int col = wn * 32 + nj * 8 + tg * 2;
                float vx = acc[mi][nj][hrow * 2]     + sbias[col];
                float vy = acc[mi][nj][hrow * 2 + 1] + sbias[col + 1];
                if (MODE == 1) { vx = gelu_f(vx); vy = gelu_f(vy); }
                if (MODE == 3) { vx *= qs; vy *= qs; }
                long idx = cRow * (long)N + nBase + col;
                if (MODE == 1) {
                    __nv_bfloat16 hx = __float2bfloat16_rn(vx);
                    __nv_bfloat16 hy = __float2bfloat16_rn(vy);
                    __nv_bfloat162 H; H.x = hx; H.y = hy;
                    __nv_bfloat162 L;
                    L.x = __float2bfloat16_rn(vx - __bfloat162float(hx));
                    L.y = __float2bfloat16_rn(vy - __bfloat162float(hy));
                    *(__nv_bfloat162*)(ChH + idx) = H;
                    *(__nv_bfloat162*)(ChL + idx) = L;
                } else if (MODE == 3) {
                    __nv_bfloat162 H;
                    H.x = __float2bfloat16_rn(vx);
                    H.y = __float2bfloat16_rn(vy);
                    *(__nv_bfloat162*)(ChH + idx) = H;   // H plane only
                } else {
                    float2 v; v.x = vx * scl; v.y = vy * scl;
                    *(float2*)(Cf + cRow * (long)N + nBase + col) = v;
                }
            }
        }
    }
}

// =====================================================================
// FA2-style mma attention: 128 q-rows/CTA, 8 warps x m16, K-tile 64.
// Q/K/V single-bf16; P split hi/lo. Output: H plane only (out-proj is
// split-2 and never reads attn-lo).
// =====================================================================
#define AT_STRIDE 144                    // 64 bf16 cols + 16B pad
#define AT_KVB    18432                  // Kh(9216) + Vh(9216) per buffer
#define AT_KH(b)  ((b) * AT_KVB)
#define AT_VH(b)  ((b) * AT_KVB + 9216)
#define AT_QH     36864
#define AT_SMEM   55296

__global__ void __launch_bounds__(256) attn_mma(
    const __nv_bfloat16* __restrict__ qkvH,
    __nv_bfloat16* __restrict__ outH)
{
    extern __shared__ char smem[];
    const uint32_t sb = smem_u32(smem);
    int tid = threadIdx.x, wid = tid >> 5, lane = tid & 31;
    int bh = blockIdx.y;
    int b  = bh >> 4, h = bh & 15;
    int q0 = blockIdx.x * 128;

    const char* Hb = (const char*)qkvH;
    const long ROWB = (long)QKVD * 2;            // bytes per token row
    const long tokB = (long)b * SS;

    auto stage_kv = [&](int tile) {
        #pragma unroll
        for (int u = 0; u < 2; u++) {
            int id = tid + u * 256;
            int row = id >> 3, ch = id & 7;
            long ko = (tokB + tile * 64 + row) * ROWB + (long)(DIM     + h * 64) * 2 + ch * 16;
            long vo = (tokB + tile * 64 + row) * ROWB + (long)(2 * DIM + h * 64) * 2 + ch * 16;
            CP16(sb + AT_KH(tile & 1) + row * AT_STRIDE + ch * 16, Hb + ko);
            CP16(sb + AT_VH(tile & 1) + row * AT_STRIDE + ch * 16, Hb + vo);
        }
        CPCOMMIT();
    };

    // ---- stage Q (H plane) + K/V tile 0
    #pragma unroll
    for (int u = 0; u < 4; u++) {
        int id = tid + u * 256;                  // 0..1023
        int row = id >> 3, ch = id & 7;
        long so = (tokB + q0 + row) * ROWB + (long)(h * 64) * 2 + ch * 16;
        CP16(sb + AT_QH + row * AT_STRIDE + ch * 16, Hb + so);
    }
    stage_kv(0);
    CPWAIT0();
    __syncthreads();

    // ---- load Q fragments once (warp owns rows wid*16 .. +15)
    uint32_t qh[4][4];
    {
        uint32_t rb = (uint32_t)((wid * 16 + (lane & 15)) * AT_STRIDE + (lane >> 4) * 16);
        #pragma unroll
        for (int ks = 0; ks < 4; ks++)
            LDSM4(qh[ks], sb + AT_QH + rb + ks * 32);
    }

    float m0 = -1e30f, m1 = -1e30f, l0 = 0.f, l1 = 0.f;
    float O[8][4];
    #pragma unroll
    for (int j = 0; j < 8; j++)
        #pragma unroll
        for (int q = 0; q < 4; q++) O[j][q] = 0.f;

    const int NT = SS / 64;   // 16 K-tiles
    for (int c = 0; c < NT; c++) {
        if (c) { CPWAIT0(); __syncthreads(); }
        if (c + 1 < NT) stage_kv(c + 1);

        // ---- scores S[m16][kk64] = Q . K^T
        float s[8][4];
        #pragma unroll
        for (int j = 0; j < 8; j++)
            #pragma unroll
            for (int q = 0; q < 4; q++) s[j][q] = 0.f;

        uint32_t kb = sb + AT_KH(c & 1) + (uint32_t)((lane & 15) * AT_STRIDE + (lane >> 4) * 16);
        #pragma unroll
        for (int ks = 0; ks < 4; ks++) {        // d chunks of 16
            uint32_t kf[4][4];
            #pragma unroll
            for (int np = 0; np < 4; np++)
                LDSM4(kf[np], kb + np * (16 * AT_STRIDE) + ks * 32);
            #pragma unroll
            for (int np = 0; np < 4; np++) {
                mma16816(s[2 * np],     qh[ks], kf[np][0], kf[np][2]);
                mma16816(s[2 * np + 1], qh[ks], kf[np][1], kf[np][3]);
            }
        }

        // ---- online softmax (2 rows/thread; quad = lanes sharing a row)
        float rm0 = -1e30f, rm1 = -1e30f;
        #pragma unroll
        for (int j = 0; j < 8; j++) {
            rm0 = fmaxf(rm0, fmaxf(s[j][0], s[j][1]));
            rm1 = fmaxf(rm1, fmaxf(s[j][2], s[j][3]));
        }
        rm0 = fmaxf(rm0, __shfl_xor_sync(0xffffffffu, rm0, 1));
        rm0 = fmaxf(rm0, __shfl_xor_sync(0xffffffffu, rm0, 2));
        rm1 = fmaxf(rm1, __shfl_xor_sync(0xffffffffu, rm1, 1));
        rm1 = fmaxf(rm1, __shfl_xor_sync(0xffffffffu, rm1, 2));
        float mn0 = fmaxf(m0, rm0), mn1 = fmaxf(m1, rm1);
        float a0 = __expf(m0 - mn0), a1 = __expf(m1 - mn1);
        m0 = mn0; m1 = mn1;
        float rs0 = 0.f, rs1 = 0.f;
        #pragma unroll
        for (int j = 0; j < 8; j++) {
            s[j][0] = __expf(s[j][0] - mn0);
            s[j][1] = __expf(s[j][1] - mn0);
            s[j][2] = __expf(s[j][2] - mn1);
            s[j][3] = __expf(s[j][3] - mn1);
            rs0 += s[j][0] + s[j][1];
            rs1 += s[j][2] + s[j][3];
        }
        rs0 += __shfl_xor_sync(0xffffffffu, rs0, 1);
        rs0 += __shfl_xor_sync(0xffffffffu, rs0, 2);
        rs1 += __shfl_xor_sync(0xffffffffu, rs1, 1);
        rs1 += __shfl_xor_sync(0xffffffffu, rs1, 2);
        l0 = l0 * a0 + rs0;
        l1 = l1 * a1 + rs1;
        #pragma unroll
        for (int j = 0; j < 8; j++) {
            O[j][0] *= a0; O[j][1] *= a0;
            O[j][2] *= a1; O[j][3] *= a1;
        }

        // ---- pack P hi/lo as A-fragments directly from score frags
        uint32_t ph[4][4], pl[4][4];
        #pragma unroll
        for (int ks = 0; ks < 4; ks++) {
            int j0 = 2 * ks, j1 = 2 * ks + 1;
            #pragma unroll
            for (int half = 0; half < 2; half++) {
                int jj = half ? j1 : j0;
                float x = s[jj][0], y = s[jj][1], z = s[jj][2], w = s[jj][3];
                __nv_bfloat16 hx = __float2bfloat16_rn(x);
                __nv_bfloat16 hy = __float2bfloat16_rn(y);
                __nv_bfloat16 hz = __float2bfloat16_rn(z);
                __nv_bfloat16 hw = __float2bfloat16_rn(w);
                __nv_bfloat162 P0; P0.x = hx; P0.y = hy;
                __nv_bfloat162 P1; P1.x = hz; P1.y = hw;
                ph[ks][2 * half]     = *(uint32_t*)&P0;
                ph[ks][2 * half + 1] = *(uint32_t*)&P1;
                pl[ks][2 * half]     = packbf(x - __bfloat162float(hx),
                                              y - __bfloat162float(hy));
                pl[ks][2 * half + 1] = packbf(z - __bfloat162float(hz),
                                              w - __bfloat162float(hw));
            }
        }

        // ---- O += P . V  (V via ldmatrix.trans)
        uint32_t vb = sb + AT_VH(c & 1) + (uint32_t)((lane & 15) * AT_STRIDE + (lane >> 4) * 16);
        #pragma unroll
        for (int ks = 0; ks < 4; ks++) {        // kk chunks of 16
            uint32_t vf[4][4];
            #pragma unroll
            for (int np = 0; np < 4; np++)
                LDSM4T(vf[np], vb + ks * (16 * AT_STRIDE) + np * 32);
            #pragma unroll
            for (int np = 0; np < 4; np++) {
                mma16816(O[2 * np],     ph[ks], vf[np][0], vf[np][1]);
                mma16816(O[2 * np + 1], ph[ks], vf[np][2], vf[np][3]);
            }
            #pragma unroll
            for (int np = 0; np < 4; np++) {
                mma16816(O[2 * np],     pl[ks], vf[np][0], vf[np][1]);
                mma16816(O[2 * np + 1], pl[ks], vf[np][2], vf[np][3]);
            }
        }
    }

    // ---- epilogue: O/l -> H plane at [tok][h*64 + d]
    float inv0 = 1.f / l0, inv1 = 1.f / l1;
    int g  = lane >> 2;
    int t2 = (lane & 3) * 2;
    long tok0 = (long)b * SS + q0 + wid * 16 + g;
    long tok1 = tok0 + 8;
    #pragma unroll
    for (int nj = 0; nj < 8; nj++) {
        int col = h * 64 + nj * 8 + t2;
        float v0 = O[nj][0] * inv0, v1 = O[nj][1] * inv0;
        float v2 = O[nj][2] * inv1, v3 = O[nj][3] * inv1;
        __nv_bfloat162 H0, H1;
        H0.x = __float2bfloat16_rn(v0); H0.y = __float2bfloat16_rn(v1);
        H1.x = __float2bfloat16_rn(v2); H1.y = __float2bfloat16_rn(v3);
        *(__nv_bfloat162*)(outH + tok0 * DIM + col) = H0;
        *(__nv_bfloat162*)(outH + tok1 * DIM + col) = H1;
    }
}

// ---------------- residual + LayerNorm; emits x1 H plane only --------------
__global__ void __launch_bounds__(256) ln_res_kernel(
    const float* __restrict__ a, const float* __restrict__ b,
    const float* __restrict__ g, const float* __restrict__ bt,
    float* __restrict__ out, __nv_bfloat16* __restrict__ outH)
{
    long t  = blockIdx.x;
    int tid = threadIdx.x;
    float4 va = ((const float4*)(a + t * DIM))[tid];
    float4 vb = ((const float4*)(b + t * DIM))[tid];
    float v[4] = { va.x + vb.x, va.y + vb.y, va.z + vb.z, va.w + vb.w };
    float s1 = v[0] + v[1] + v[2] + v[3];
    float s2 = v[0]*v[0] + v[1]*v[1] + v[2]*v[2] + v[3]*v[3];
    #pragma unroll
    for (int o2 = 16; o2 >= 1; o2 >>= 1) {
        s1 += __shfl_xor_sync(0xffffffffu, s1, o2);
        s2 += __shfl_xor_sync(0xffffffffu, s2, o2);
    }
    __shared__ float r1[8], r2[8], mv[2];
    if ((tid & 31) == 0) { r1[tid >> 5] = s1; r2[tid >> 5] = s2; }
    __syncthreads();
    if (tid == 0) {
        float A = 0.f, Bq = 0.f;
        #pragma unroll
        for (int w = 0; w < 8; w++) { A += r1[w]; Bq += r2[w]; }
        float mean = A * (1.f / DIM);
        float var  = Bq * (1.f / DIM) - mean * mean;
        mv[0] = mean; mv[1] = rsqrtf(var + 1e-5f);
    }
    __syncthreads();
    float mean = mv[0], rstd = mv[1];
    float4 gg  = ((const float4*)g)[tid];
    float4 bbv = ((const float4*)bt)[tid];
    float4 ov;
    ov.x = (v[0] - mean) * rstd * gg.x + bbv.x;
    ov.y = (v[1] - mean) * rstd * gg.y + bbv.y;
    ov.z = (v[2] - mean) * rstd * gg.z + bbv.z;
    ov.w = (v[3] - mean) * rstd * gg.w + bbv.w;
    ((float4*)(out + t * DIM))[tid] = ov;

    __nv_bfloat162 H0, H1;
    H0.x = __float2bfloat16_rn(ov.x); H0.y = __float2bfloat16_rn(ov.y);
    H1.x = __float2bfloat16_rn(ov.z); H1.y = __float2bfloat16_rn(ov.w);
    ((__nv_bfloat162*)(outH + t * DIM))[2 * tid]     = H0;
    ((__nv_bfloat162*)(outH + t * DIM))[2 * tid + 1] = H1;
}

// ---------------- combine MoE slots + residual + LN2 -> d_out ----------------
__global__ void __launch_bounds__(256) ln2_kernel(
    const float* __restrict__ x1, const float* __restrict__ moe2,
    const float* __restrict__ g, const float* __restrict__ bt,
    float* __restrict__ out)
{
    long t  = blockIdx.x;
    int tid = threadIdx.x;
    float4 va = ((const float4*)(x1   + t * DIM))[tid];
    float4 vb = ((const float4*)(moe2 + (2 * t)     * DIM))[tid];
    float4 vc = ((const float4*)(moe2 + (2 * t + 1) * DIM))[tid];
    float v[4] = { va.x + vb.x + vc.x, va.y + vb.y + vc.y,
                   va.z + vb.z + vc.z, va.w + vb.w + vc.w };
    float s1 = v[0] + v[1] + v[2] + v[3];
    float s2 = v[0]*v[0] + v[1]*v[1] + v[2]*v[2] + v[3]*v[3];
    #pragma unroll
    for (int o2 = 16; o2 >= 1; o2 >>= 1) {
        s1 += __shfl_xor_sync(0xffffffffu, s1, o2);
        s2 += __shfl_xor_sync(0xffffffffu, s2, o2);
    }
    __shared__ float r1[8], r2[8], mv[2];
    if ((tid & 31) == 0) { r1[tid >> 5] = s1; r2[tid >> 5] = s2; }
    __syncthreads();
    if (tid == 0) {
        float A = 0.f, Bq = 0.f;
        #pragma unroll
        for (int w = 0; w < 8; w++) { A += r1[w]; Bq += r2[w]; }
        float mean = A * (1.f / DIM);
        float var  = Bq * (1.f / DIM) - mean * mean;
        mv[0] = mean; mv[1] = rsqrtf(var + 1e-5f);
    }
    __syncthreads();
    float mean = mv[0], rstd = mv[1];
    float4 gg  = ((const float4*)g)[tid];
    float4 bbv = ((const float4*)bt)[tid];
    float4 ov;
    ov.x = (v[0] - mean) * rstd * gg.x + bbv.x;
    ov.y = (v[1] - mean) * rstd * gg.y + bbv.y;
    ov.z = (v[2] - mean) * rstd * gg.z + bbv.z;
    ov.w = (v[3] - mean) * rstd * gg.w + bbv.w;
    ((float4*)(out + t * DIM))[tid] = ov;
}

// ---------------- gate: logits, softmax usage, top-2 -------------------------
__global__ void __launch_bounds__(256) gate_kernel(
    const float* __restrict__ x, const float* __restrict__ gw,
    const float* __restrict__ gb)
{
    int t = blockIdx.x;
    int w = threadIdx.x >> 5, lane = threadIdx.x & 31;
    const float* xr = x + (long)t * DIM;
    const float* wr = gw + w * DIM;
    float s = 0.f;
    for (int d = lane; d < DIM; d += 32) s += xr[d] * wr[d];
    #pragma unroll
    for (int o2 = 16; o2 >= 1; o2 >>= 1) s += __shfl_xor_sync(0xffffffffu, s, o2);
    __shared__ float lg[NEXP];
    if (lane == 0) lg[w] = s + gb[w];
    __syncthreads();
    if (threadIdx.x == 0) {
        float mx = lg[0];
        #pragma unroll
        for (int e = 1; e < NEXP; e++) mx = fmaxf(mx, lg[e]);
        float ex[NEXP], sum = 0.f;
        #pragma unroll
        for (int e = 0; e < NEXP; e++) { ex[e] = expf(lg[e] - mx); sum += ex[e]; }
        float inv = 1.f / sum;
        #pragma unroll
        for (int e = 0; e < NEXP; e++) atomicAdd(&g_usage[e], ex[e] * inv);
        int e0 = 0;
        #pragma unroll
        for (int e = 1; e < NEXP; e++) if (lg[e] > lg[e0]) e0 = e;
        int e1 = -1;
        #pragma unroll
        for (int e = 0; e < NEXP; e++)
            if (e != e0 && (e1 < 0 || lg[e] > lg[e1])) e1 = e;
        float z  = expf(lg[e1] - lg[e0]);
        float p0 = 1.f / (1.f + z);
        g_tidx[2 * t]     = e0;  g_tidx[2 * t + 1]  = e1;
        g_tprob[2 * t]    = p0;  g_tprob[2 * t + 1] = z * p0;
        atomicAdd(&g_count[e0], 1);
        atomicAdd(&g_count[e1], 1);
    }
}

__global__ void k_offsets() {
    if (threadIdx.x == 0) {
        int a = 0;
        for (int e = 0; e < NEXP; e++) { g_off[e] = a; a += g_count[e]; }
    }
}

__global__ void k_fill() {
    int t = blockIdx.x * blockDim.x + threadIdx.x;
    if (t < TOK) {
        #pragma unroll
        for (int k = 0; k < 2; k++) {
            int e   = g_tidx[2 * t + k];
            int pos = atomicAdd(&g_fill[e], 1);
            g_list[g_off[e] + pos] = 2 * t + k;
        }
    }
}

__global__ void k_aux(float* out) {
    float s = 0.f;
    #pragma unroll
    for (int e = 0; e < NEXP; e++) {
        float u = g_usage[e] * (1.f / TOK);
        s += u * u;
    }
    out[(size_t)TOK * DIM] = (float)NEXP * s;
}

// ---------------- launch ----------------
extern "C" void kernel_launch(void* const* d_in, const int* in_sizes, int n_in,
                              void* d_out, int out_size)
{
    (void)in_sizes; (void)n_in;
    const float* src  = (const float*)d_in[0];
    const float* ipw  = (const float*)d_in[1];
    const float* ipb  = (const float*)d_in[2];
    const float* outw = (const float*)d_in[3];
    const float* outb = (const float*)d_in[4];
    const float* gw   = (const float*)d_in[5];
    const float* gb   = (const float*)d_in[6];
    const float* w1   = (const float*)d_in[7];
    const float* b1   = (const float*)d_in[8];
    const float* w2   = (const float*)d_in[9];
    const float* b2   = (const float*)d_in[10];
    const float* ln1g = (const float*)d_in[11];
    const float* ln1b = (const float*)d_in[12];
    const float* ln2g = (const float*)d_in[13];
    const float* ln2b = (const float*)d_in[14];
    float* out = (float*)d_out;

    float *p_proj, *p_x1, *p_moe2;
    cudaGetSymbolAddress((void**)&p_proj, g_proj);
    cudaGetSymbolAddress((void**)&p_x1,   g_x1);
    cudaGetSymbolAddress((void**)&p_moe2, g_moe2);
    __nv_bfloat16 *qkvH, *srcH, *attnH, *x1H, *hH, *hL;
    __nv_bfloat16 *ipwH, *ipwL, *outwH, *outwL, *w1H, *w1L, *w2H, *w2L;
    cudaGetSymbolAddress((void**)&qkvH,  g_qkvH);
    cudaGetSymbolAddress((void**)&srcH,  g_srcH);
    cudaGetSymbolAddress((void**)&attnH, g_attnH);
    cudaGetSymbolAddress((void**)&x1H,   g_x1H);
    cudaGetSymbolAddress((void**)&hH,    g_hH);
    cudaGetSymbolAddress((void**)&hL,    g_hL);
    cudaGetSymbolAddress((void**)&ipwH,  g_ipwH);
    cudaGetSymbolAddress((void**)&ipwL,  g_ipwL);
    cudaGetSymbolAddress((void**)&outwH, g_outwH);
    cudaGetSymbolAddress((void**)&outwL, g_outwL);
    cudaGetSymbolAddress((void**)&w1H,   g_w1H);
    cudaGetSymbolAddress((void**)&w1L,   g_w1L);
    cudaGetSymbolAddress((void**)&w2H,   g_w2H);
    cudaGetSymbolAddress((void**)&w2L,   g_w2L);

    cudaFuncSetAttribute(attn_mma,
                         cudaFuncAttributeMaxDynamicSharedMemorySize, AT_SMEM);
    cudaFuncSetAttribute(mma_gemm<0>,
                         cudaFuncAttributeMaxDynamicSharedMemorySize, SM_TOTAL);
    cudaFuncSetAttribute(mma_gemm<1>,
                         cudaFuncAttributeMaxDynamicSharedMemorySize, SM_TOTAL);
    cudaFuncSetAttribute(mma_gemm<2>,
                         cudaFuncAttributeMaxDynamicSharedMemorySize, SM_TOTAL);
    cudaFuncSetAttribute(mma_gemm<3>,
                         cudaFuncAttributeMaxDynamicSharedMemorySize, SM_TOTAL);

    // 1) per-replay init
    k_init<<<1, 32>>>();
    // 2-4) conversions needed before QKV + expert GEMM1
    {
        long n;
        n = (long)TOK * DIM / 4;
        k_convH<<<(int)((n + 255) / 256), 256>>>(src, srcH, n);
        n = (long)QKVD * DIM / 4;
        k_conv<<<(int)((n + 255) / 256), 256>>>(ipw, ipwH, ipwL, n);
        n = (long)NEXP * FDIM * DIM / 4;
        k_conv<<<(int)((n + 255) / 256), 256>>>(w1, w1H, w1L, n);
    }

    // 5) QKV projection (split-2) -> H plane, Q cols pre-scaled 1/8
    mma_gemm<3><<<dim3(QKVD / 128, TOK / 128, 1), 256, SM_TOTAL>>>(
        srcH, 0, ipwH, ipwL, ipb, 0, qkvH, 0, TOK, QKVD, DIM, 0, 0);

    // 6) tensor-core flash attention (single-bf16 QKV) -> attn H plane
    attn_mma<<<dim3(SS / 128, BB * NHEAD), 256, AT_SMEM>>>(qkvH, attnH);

    // 7-8) remaining weight conversions (first consumers are steps 9/13)
    {
        long n = (long)DIM * DIM / 4;
        k_conv<<<(int)((n + 255) / 256), 256>>>(outw, outwH, outwL, n);
        n = (long)NEXP * DIM * FDIM / 4;
        k_conv<<<(int)((n + 255) / 256), 256>>>(w2, w2H, w2L, n);
    }

    // 9) output projection (split-2; fp32 out for LN)
    mma_gemm<0><<<dim3(DIM / 128, TOK / 128, 1), 256, SM_TOTAL>>>(
        attnH, 0, outwH, outwL, outb, p_proj, 0, 0, TOK, DIM, DIM, 0, 0);

    // 10) x1 = LN(src + attn_out); emit x1 H plane
    ln_res_kernel<<<TOK, 256>>>(p_proj, src, ln1g, ln1b, p_x1, x1H);

    // 11) gating
    gate_kernel<<<TOK, 256>>>(p_x1, gw, gb);
    k_offsets<<<1, 32>>>();
    k_fill<<<TOK / 256, 256>>>();

    // 12) expert GEMM1 (split-2, m-fastest grid): h = gelu(x1 @ w1^T + b1)
    mma_gemm<1><<<dim3(TOK / 128, FDIM / 128, NEXP), 256, SM_TOTAL>>>(
        x1H, 0, w1H, w1L, b1, 0, hH, hL,
        TOK, FDIM, DIM, (long)FDIM * DIM, FDIM);

    // 13) expert GEMM2 (split-3, m-fastest grid): eo = (h @ w2^T + b2)*prob
    mma_gemm<2><<<dim3(TOK / 128, DIM / 128, NEXP), 256, SM_TOTAL>>>(
        hH, hL, w2H, w2L, b2, p_moe2, 0, 0,
        TOK, DIM, FDIM, (long)DIM * FDIM, DIM);

    // 14) out = LN(x1 + moe_out)
    ln2_kernel<<<TOK, 256>>>(p_x1, p_moe2, ln2g, ln2b, out);

    // 15) aux loss
    if (out_size > TOK * DIM) k_aux<<<1, 1>>>(out);
}